// round 1
// baseline (speedup 1.0000x reference)
#include <cuda_runtime.h>
#include <math.h>

// ---------------- problem constants ----------------
constexpr int B_    = 2;
constexpr int S_    = 2048;
constexpr int H_    = 2048;
constexpr int NH_   = 16;
constexpr int QL_   = 1536;
constexpr int KVL_  = 512;
constexpr int NOPE_ = 128;
constexpr int ROPE_ = 64;
constexpr int VD_   = 128;
constexpr int QKH_  = 192;          // NOPE+ROPE
constexpr int M_    = B_ * S_;      // 4096 tokens
constexpr int QDIM_ = NH_ * QKH_;   // 3072
constexpr int KC_   = KVL_ + ROPE_; // 576 (shared K dim)
constexpr float EPSF = 1e-6f;
constexpr float MINV = -1e15f;

// ---------------- scratch (device globals; no cudaMalloc allowed) ----------------
__device__ float g_qa    [M_ * QL_];                         // 25 MB
__device__ float g_qfull [M_ * QDIM_];                       // 50 MB
__device__ float g_kvfull[M_ * KC_];                         // 9.4 MB
__device__ float g_kcat  [M_ * KC_];                         // 9.4 MB
__device__ float g_qcat  [M_ * NH_ * KC_];                   // 151 MB
__device__ float g_scores[(size_t)B_ * NH_ * S_ * S_];       // 537 MB
__device__ float g_lat2  [M_ * NH_ * KVL_];                  // 134 MB
__device__ float g_oheads[M_ * H_];                          // 33.6 MB
__device__ float g_rope  [S_ * ROPE_];                       // cos|sin tables

// ---------------- generic batched SGEMM ----------------
// C[M,N] = A[M,K] * op(B) (+bias).  TRANSB: B stored [N,K]; else [K,N].
// Batch z: zo=z/inner, zi=z%inner; each operand offset by zo*s?o + zi*s?i.
// CSKIP: skip blocks fully above the causal diagonal (scores GEMM).
// CK:    limit K loop to m0+128 (attn@V GEMM; probs are 0/unwritten past that).
template<bool TRANSB, bool BIAS, bool CSKIP, bool CK>
__global__ __launch_bounds__(256)
void sgemm_kernel(const float* __restrict__ A, int lda, long long sAo, long long sAi,
                  const float* __restrict__ Bm, int ldb, long long sBo, long long sBi,
                  float* __restrict__ C, int ldc, long long sCo, long long sCi,
                  int M, int N, int K, int inner,
                  const float* __restrict__ bias)
{
    const int m0 = blockIdx.y * 128;
    const int n0 = blockIdx.x * 128;
    if (CSKIP && n0 >= m0 + 128) return;

    const int z = blockIdx.z;
    const int zo = z / inner, zi = z - zo * inner;
    A  += zo * sAo + zi * sAi;
    Bm += zo * sBo + zi * sBi;
    C  += zo * sCo + zi * sCi;

    __shared__ __align__(16) float As[8][128];
    __shared__ __align__(16) float Bs[8][128];

    const int tid  = threadIdx.x;
    const int rowb = (tid >> 4) << 3;   // 0..120
    const int colb = (tid & 15) << 3;   // 0..120

    float acc[8][8];
#pragma unroll
    for (int i = 0; i < 8; i++)
#pragma unroll
        for (int j = 0; j < 8; j++) acc[i][j] = 0.f;

    int Kend = K;
    if (CK) { int ke = m0 + 128; Kend = ke < K ? ke : K; }
    const int ktiles = Kend >> 3;   // all K in this problem are multiples of 8

    for (int kt = 0; kt < ktiles; kt++) {
        const int k0 = kt << 3;
        // load A tile (128 rows x 8 k), transposed into As[k][row]
#pragma unroll
        for (int l = 0; l < 4; l++) {
            int li = l * 256 + tid;
            int r = li >> 3, kk = li & 7;
            int gr = m0 + r;
            float v = 0.f;
            if (gr < M) v = A[(long long)gr * lda + (k0 + kk)];
            As[kk][r] = v;
        }
        if (TRANSB) {
#pragma unroll
            for (int l = 0; l < 4; l++) {
                int li = l * 256 + tid;
                int nn = li >> 3, kk = li & 7;
                int gn = n0 + nn;
                float v = 0.f;
                if (gn < N) v = Bm[(long long)gn * ldb + (k0 + kk)];
                Bs[kk][nn] = v;
            }
        } else {
#pragma unroll
            for (int l = 0; l < 4; l++) {
                int li = l * 256 + tid;
                int kk = li >> 7, nn = li & 127;
                int gn = n0 + nn;
                float v = 0.f;
                if (gn < N) v = Bm[(long long)(k0 + kk) * ldb + gn];
                Bs[kk][nn] = v;
            }
        }
        __syncthreads();
#pragma unroll
        for (int kk = 0; kk < 8; kk++) {
            float4 a0 = *(const float4*)&As[kk][rowb];
            float4 a1 = *(const float4*)&As[kk][rowb + 4];
            float4 b0 = *(const float4*)&Bs[kk][colb];
            float4 b1 = *(const float4*)&Bs[kk][colb + 4];
            float av[8] = {a0.x, a0.y, a0.z, a0.w, a1.x, a1.y, a1.z, a1.w};
            float bv[8] = {b0.x, b0.y, b0.z, b0.w, b1.x, b1.y, b1.z, b1.w};
#pragma unroll
            for (int i = 0; i < 8; i++)
#pragma unroll
                for (int j = 0; j < 8; j++)
                    acc[i][j] = fmaf(av[i], bv[j], acc[i][j]);
        }
        __syncthreads();
    }

#pragma unroll
    for (int i = 0; i < 8; i++) {
        int gm = m0 + rowb + i;
        if (gm >= M) continue;
        float* cp = C + (long long)gm * ldc;
#pragma unroll
        for (int j = 0; j < 8; j++) {
            int gn = n0 + colb + j;
            if (gn < N) cp[gn] = acc[i][j] + (BIAS ? bias[gn] : 0.f);
        }
    }
}

// ---------------- RMSNorm (in place, one block per row) ----------------
__global__ __launch_bounds__(256)
void rmsnorm_kernel(float* __restrict__ x, const float* __restrict__ w, int cols)
{
    __shared__ float sh[256];
    float* p = x + (long long)blockIdx.x * cols;
    float s = 0.f;
    for (int c = threadIdx.x; c < cols; c += 256) { float v = p[c]; s += v * v; }
    sh[threadIdx.x] = s; __syncthreads();
    for (int o = 128; o > 0; o >>= 1) {
        if (threadIdx.x < o) sh[threadIdx.x] += sh[threadIdx.x + o];
        __syncthreads();
    }
    float rs = rsqrtf(sh[0] / (float)cols + EPSF);
    for (int c = threadIdx.x; c < cols; c += 256) p[c] = w[c] * p[c] * rs;
}

// ---------------- RoPE cos/sin table (double precision, tiny) ----------------
__global__ void rope_table_kernel(float* __restrict__ rope)
{
    int idx = blockIdx.x * blockDim.x + threadIdx.x;
    if (idx >= S_ * 32) return;
    int pos = idx >> 5, j = idx & 31;
    double f = pow(10000.0, -(double)j / 32.0);
    double ang = (double)pos * f;
    rope[pos * 64 + j]      = (float)cos(ang);
    rope[pos * 64 + 32 + j] = (float)sin(ang);
}

// ---------------- kv branch: rmsnorm(kv) | rope(k_pe) -> k_cat ----------------
__global__ __launch_bounds__(256)
void kvproc_kernel(const float* __restrict__ kvfull, const float* __restrict__ w,
                   const float* __restrict__ rope, float* __restrict__ kcat)
{
    __shared__ float sh[256];
    const int row = blockIdx.x;                  // token index b*S+s
    const float* in = kvfull + (long long)row * KC_;
    float* out      = kcat   + (long long)row * KC_;
    float s = 0.f;
    for (int c = threadIdx.x; c < KVL_; c += 256) { float v = in[c]; s += v * v; }
    sh[threadIdx.x] = s; __syncthreads();
    for (int o = 128; o > 0; o >>= 1) {
        if (threadIdx.x < o) sh[threadIdx.x] += sh[threadIdx.x + o];
        __syncthreads();
    }
    float rs = rsqrtf(sh[0] / (float)KVL_ + EPSF);
    for (int c = threadIdx.x; c < KVL_; c += 256) out[c] = w[c] * in[c] * rs;
    if (threadIdx.x < 32) {
        int j = threadIdx.x;
        int pos = row & (S_ - 1);
        float cs = rope[pos * 64 + j], sn = rope[pos * 64 + 32 + j];
        float x1 = in[KVL_ + j], x2 = in[KVL_ + 32 + j];
        out[KVL_ + j]      = x1 * cs - x2 * sn;
        out[KVL_ + 32 + j] = x2 * cs + x1 * sn;
    }
}

// ---------------- q_pe RoPE -> q_cat[..., 512:576] ----------------
__global__ void qpe_rope_kernel(const float* __restrict__ qfull,
                                const float* __restrict__ rope,
                                float* __restrict__ qcat)
{
    int idx = blockIdx.x * blockDim.x + threadIdx.x;
    if (idx >= M_ * NH_ * 32) return;
    int j   = idx & 31;
    int h   = (idx >> 5) & (NH_ - 1);
    int row = idx >> 9;
    int pos = row & (S_ - 1);
    float cs = rope[pos * 64 + j], sn = rope[pos * 64 + 32 + j];
    const float* q = qfull + (long long)row * QDIM_ + h * QKH_ + NOPE_;
    float x1 = q[j], x2 = q[32 + j];
    float* o = qcat + (long long)row * (NH_ * KC_) + h * KC_ + KVL_;
    o[j]      = x1 * cs - x2 * sn;
    o[32 + j] = x2 * cs + x1 * sn;
}

// ---------------- causal+mask softmax (in place on scores) ----------------
// Only t <= s is read (causal blocks above diagonal were never computed).
// Writes probs[0..s], zero-fills (s, next 128-boundary) so the CK GEMM can
// read whole 128-aligned K tiles.
__global__ __launch_bounds__(256)
void softmax_kernel(float* __restrict__ scores, const int* __restrict__ mask)
{
    __shared__ float sh[256];
    const int s = blockIdx.x;
    const int z = blockIdx.y;            // b*NH + h
    const int b = z >> 4;
    float* row = scores + ((long long)z * S_ + s) * S_;
    const int* mrow = mask + b * S_;
    const int n = s + 1;
    const int tid = threadIdx.x;
    const float scale = 0.07216878364870323f;   // 1/sqrt(192)

    float vals[8];
    float mx = -3.0e38f;
#pragma unroll
    for (int it = 0; it < 8; it++) {
        int t = tid + it * 256;
        float v = -3.0e38f;
        if (t < n) {
            v = row[t] * scale;
            if (mrow[t] == 0) v += MINV;
        }
        vals[it] = v;
        mx = fmaxf(mx, v);
    }
    sh[tid] = mx; __syncthreads();
    for (int o = 128; o > 0; o >>= 1) {
        if (tid < o) sh[tid] = fmaxf(sh[tid], sh[tid + o]);
        __syncthreads();
    }
    mx = sh[0]; __syncthreads();

    float sum = 0.f;
#pragma unroll
    for (int it = 0; it < 8; it++) {
        int t = tid + it * 256;
        if (t < n) { float e = expf(vals[it] - mx); vals[it] = e; sum += e; }
    }
    sh[tid] = sum; __syncthreads();
    for (int o = 128; o > 0; o >>= 1) {
        if (tid < o) sh[tid] += sh[tid + o];
        __syncthreads();
    }
    float inv = 1.f / sh[0];
#pragma unroll
    for (int it = 0; it < 8; it++) {
        int t = tid + it * 256;
        if (t < n) row[t] = vals[it] * inv;
    }
    int pad = ((s >> 7) + 1) << 7;
    for (int t = n + tid; t < pad; t += 256) row[t] = 0.f;
}

// ---------------- launcher ----------------
extern "C" void kernel_launch(void* const* d_in, const int* in_sizes, int n_in,
                              void* d_out, int out_size)
{
    (void)in_sizes; (void)n_in; (void)out_size;
    const float* x        = (const float*)d_in[0];
    const int*   mask     = (const int*)  d_in[1];
    const float* wq_a_w   = (const float*)d_in[2];
    const float* wq_a_b   = (const float*)d_in[3];
    const float* q_norm_w = (const float*)d_in[4];
    const float* wq_b_w   = (const float*)d_in[5];
    const float* wq_b_b   = (const float*)d_in[6];
    const float* wkv_a_w  = (const float*)d_in[7];
    const float* wkv_a_b  = (const float*)d_in[8];
    const float* kv_norm_w= (const float*)d_in[9];
    const float* wkv_b_w  = (const float*)d_in[10];
    const float* wo_w     = (const float*)d_in[11];
    const float* wo_b     = (const float*)d_in[12];
    float* out = (float*)d_out;

    float *qa, *qfull, *kvfull, *kcat, *qcat, *scores, *lat2, *oheads, *rope;
    cudaGetSymbolAddress((void**)&qa,     g_qa);
    cudaGetSymbolAddress((void**)&qfull,  g_qfull);
    cudaGetSymbolAddress((void**)&kvfull, g_kvfull);
    cudaGetSymbolAddress((void**)&kcat,   g_kcat);
    cudaGetSymbolAddress((void**)&qcat,   g_qcat);
    cudaGetSymbolAddress((void**)&scores, g_scores);
    cudaGetSymbolAddress((void**)&lat2,   g_lat2);
    cudaGetSymbolAddress((void**)&oheads, g_oheads);
    cudaGetSymbolAddress((void**)&rope,   g_rope);

    dim3 thr(256);

    // 1) q_a = x @ wq_a^T + b           [4096,1536]
    sgemm_kernel<true,true,false,false><<<dim3(QL_/128, M_/128, 1), thr>>>(
        x, H_, 0, 0, wq_a_w, H_, 0, 0, qa, QL_, 0, 0, M_, QL_, H_, 1, wq_a_b);
    // 2) rmsnorm(q_a)
    rmsnorm_kernel<<<M_, thr>>>(qa, q_norm_w, QL_);
    // 3) q = q_a @ wq_b^T + b           [4096,3072]
    sgemm_kernel<true,true,false,false><<<dim3(QDIM_/128, M_/128, 1), thr>>>(
        qa, QL_, 0, 0, wq_b_w, QL_, 0, 0, qfull, QDIM_, 0, 0, M_, QDIM_, QL_, 1, wq_b_b);
    // 4) kv_full = x @ wkv_a^T + b      [4096,576]
    sgemm_kernel<true,true,false,false><<<dim3((KC_ + 127)/128, M_/128, 1), thr>>>(
        x, H_, 0, 0, wkv_a_w, H_, 0, 0, kvfull, KC_, 0, 0, M_, KC_, H_, 1, wkv_a_b);
    // RoPE tables
    rope_table_kernel<<<(S_*32 + 255)/256, thr>>>(rope);
    // 5) k_cat = [rmsnorm(kv) | rope(k_pe)]
    kvproc_kernel<<<M_, thr>>>(kvfull, kv_norm_w, rope, kcat);
    // 6a) q_cat[:,:512] = q_nope @ wkv_b_k   (batched over heads, NN)
    sgemm_kernel<false,false,false,false><<<dim3(KVL_/128, M_/128, NH_), thr>>>(
        qfull, QDIM_, 0, QKH_,
        wkv_b_w, KVL_, 0, (long long)(NOPE_ + VD_) * KVL_,
        qcat, NH_ * KC_, 0, KC_,
        M_, KVL_, NOPE_, NH_, nullptr);
    // 6b) q_cat[:,512:576] = rope(q_pe)
    qpe_rope_kernel<<<(M_*NH_*32 + 255)/256, thr>>>(qfull, rope, qcat);
    // 7) scores = q_cat @ k_cat^T  (batched over b,h; causal block skip)
    sgemm_kernel<true,false,true,false><<<dim3(S_/128, S_/128, B_*NH_), thr>>>(
        qcat, NH_ * KC_, (long long)S_ * NH_ * KC_, KC_,
        kcat, KC_,        (long long)S_ * KC_,      0,
        scores, S_,       (long long)NH_ * S_ * S_, (long long)S_ * S_,
        S_, S_, KC_, NH_, nullptr);
    // 8) softmax (scale + causal + mask), in place
    softmax_kernel<<<dim3(S_, B_*NH_), thr>>>(scores, mask);
    // 9) lat2 = probs @ kv  (batched, NN, causal K bound)
    sgemm_kernel<false,false,false,true><<<dim3(KVL_/128, S_/128, B_*NH_), thr>>>(
        scores, S_, (long long)NH_ * S_ * S_, (long long)S_ * S_,
        kcat, KC_,  (long long)S_ * KC_,      0,
        lat2, NH_ * KVL_, (long long)S_ * NH_ * KVL_, KVL_,
        S_, KVL_, S_, NH_, nullptr);
    // 10) o_heads = lat2 @ wkv_b_v^T  (batched over heads, NT)
    sgemm_kernel<true,false,false,false><<<dim3(VD_/128, M_/128, NH_), thr>>>(
        lat2, NH_ * KVL_, 0, KVL_,
        wkv_b_w + (long long)NOPE_ * KVL_, KVL_, 0, (long long)(NOPE_ + VD_) * KVL_,
        oheads, H_, 0, VD_,
        M_, VD_, KVL_, NH_, nullptr);
    // 11) out = o_heads @ wo^T + b      [4096,2048]
    sgemm_kernel<true,true,false,false><<<dim3(H_/128, M_/128, 1), thr>>>(
        oheads, H_, 0, 0, wo_w, H_, 0, 0, out, H_, 0, 0, M_, H_, H_, 1, wo_b);
}

// round 8
// speedup vs baseline: 4.9067x; 4.9067x over previous
#include <cuda_runtime.h>
#include <cuda_bf16.h>
#include <math.h>
#include <stdint.h>

// ---------------- problem constants ----------------
constexpr int B_    = 2;
constexpr int S_    = 2048;
constexpr int H_    = 2048;
constexpr int NH_   = 16;
constexpr int QL_   = 1536;
constexpr int KVL_  = 512;
constexpr int NOPE_ = 128;
constexpr int ROPE_ = 64;
constexpr int VD_   = 128;
constexpr int QKH_  = 192;
constexpr int M_    = B_ * S_;      // 4096
constexpr int QDIM_ = NH_ * QKH_;   // 3072
constexpr int KC_   = KVL_ + ROPE_; // 576
constexpr float EPSF = 1e-6f;
constexpr float MINV = -1e15f;

typedef __nv_bfloat16 bf16;

// ---------------- fp32 scratch ----------------
__device__ float g_qa    [M_ * QL_];
__device__ float g_qfull [M_ * QDIM_];
__device__ float g_kvfull[M_ * KC_];
__device__ float g_kcat  [M_ * KC_];
__device__ float g_kcatT [B_ * KVL_ * S_];
__device__ float g_qcat  [M_ * NH_ * KC_];
__device__ float g_scores[(size_t)B_ * NH_ * S_ * S_];
__device__ float g_lat2  [M_ * NH_ * KVL_];
__device__ float g_oheads[M_ * H_];
__device__ float g_wkvbT [NH_ * KVL_ * NOPE_];
__device__ float g_rope  [S_ * ROPE_];

// ---------------- bf16 hi/lo scratch ----------------
__device__ bf16 g_x_h[M_ * H_],            g_x_l[M_ * H_];
__device__ bf16 g_wqa_h[QL_ * H_],         g_wqa_l[QL_ * H_];
__device__ bf16 g_wqb_h[QDIM_ * QL_],      g_wqb_l[QDIM_ * QL_];
__device__ bf16 g_wkva_h[KC_ * H_],        g_wkva_l[KC_ * H_];
__device__ bf16 g_wkvb_h[NH_ * (NOPE_ + VD_) * KVL_], g_wkvb_l[NH_ * (NOPE_ + VD_) * KVL_];
__device__ bf16 g_wkvbT_h[NH_ * KVL_ * NOPE_], g_wkvbT_l[NH_ * KVL_ * NOPE_];
__device__ bf16 g_wo_h[H_ * H_],           g_wo_l[H_ * H_];
__device__ bf16 g_qa_h[M_ * QL_],          g_qa_l[M_ * QL_];
__device__ bf16 g_qfull_h[M_ * QDIM_],     g_qfull_l[M_ * QDIM_];
__device__ bf16 g_kcat_h[M_ * KC_],        g_kcat_l[M_ * KC_];
__device__ bf16 g_kcatT_h[B_ * KVL_ * S_], g_kcatT_l[B_ * KVL_ * S_];
__device__ bf16 g_qcat_h[M_ * NH_ * KC_],  g_qcat_l[M_ * NH_ * KC_];
__device__ bf16 g_probs_h[(size_t)B_ * NH_ * S_ * S_], g_probs_l[(size_t)B_ * NH_ * S_ * S_];
__device__ bf16 g_lat2_h[M_ * NH_ * KVL_], g_lat2_l[M_ * NH_ * KVL_];
__device__ bf16 g_oheads_h[M_ * H_],       g_oheads_l[M_ * H_];

// ---------------- PTX helpers ----------------
__device__ __forceinline__ void mma_bf16(float* d, const uint32_t* a, uint32_t b0, uint32_t b1) {
    asm volatile(
        "mma.sync.aligned.m16n8k16.row.col.f32.bf16.bf16.f32 "
        "{%0,%1,%2,%3}, {%4,%5,%6,%7}, {%8,%9}, {%0,%1,%2,%3};"
        : "+f"(d[0]), "+f"(d[1]), "+f"(d[2]), "+f"(d[3])
        : "r"(a[0]), "r"(a[1]), "r"(a[2]), "r"(a[3]), "r"(b0), "r"(b1));
}
__device__ __forceinline__ void cp16(uint32_t s, const void* g, int sz) {
    asm volatile("cp.async.cg.shared.global [%0], [%1], 16, %2;"
                 :: "r"(s), "l"(g), "r"(sz) : "memory");
}
__device__ __forceinline__ void cpcommit() { asm volatile("cp.async.commit_group;" ::: "memory"); }
__device__ __forceinline__ void cpwait0()  { asm volatile("cp.async.wait_group 0;" ::: "memory"); }
__device__ __forceinline__ void cpwait1()  { asm volatile("cp.async.wait_group 1;" ::: "memory"); }
__device__ __forceinline__ void cpwait2()  { asm volatile("cp.async.wait_group 2;" ::: "memory"); }

// ================= bf16x3 tensor-core GEMM =================
// C[M,N] = A[M,K] @ B[N,K]^T (+bias), A/B given as bf16 hi/lo pairs.
// Tile 128x128x16, 3-stage cp.async, 256 thr (8 warps 2x4), warp tile 64x32.
constexpr int PADW_ = 12;                    // 32-bit words per 16-elem row (8 data + 4 pad)
constexpr int TILE_W_ = 128 * PADW_;         // 1536 words per tile
constexpr int STG_W_ = 4 * TILE_W_;          // Ahi, Alo, Bhi, Blo
constexpr int SMEM_GEMM_ = 3 * STG_W_ * 4;   // 73728 bytes

template<bool CSKIP, bool CK, bool BIAS>
__global__ __launch_bounds__(256, 2)
void gemm_bf3(const bf16* __restrict__ Ah, const bf16* __restrict__ Al,
              int lda, long long sAo, long long sAi,
              const bf16* __restrict__ Bh, const bf16* __restrict__ Bl,
              int ldb, long long sBo, long long sBi,
              float* __restrict__ C, int ldc, long long sCo, long long sCi,
              int M, int N, int K, int inner,
              const float* __restrict__ bias)
{
    const int m0 = blockIdx.y * 128;
    const int n0 = blockIdx.x * 128;
    if (CSKIP && n0 >= m0 + 128) return;

    const int z = blockIdx.z;
    const int zo = z / inner, zi = z - zo * inner;
    const long long aoff = zo * sAo + zi * sAi;
    const long long boff = zo * sBo + zi * sBi;
    Ah += aoff; Al += aoff;
    Bh += boff; Bl += boff;
    C  += zo * sCo + zi * sCi;

    extern __shared__ uint32_t sm[];

    const int tid = threadIdx.x;
    const int wid = tid >> 5, lid = tid & 31;
    const int wm = (wid >> 2) * 64;
    const int wn = (wid & 3) * 32;
    const int gr = lid >> 2;
    const int gc = lid & 3;

    int Kend = K;
    if (CK) { int ke = m0 + 128; Kend = ke < K ? ke : K; }
    const int nkt = Kend >> 4;

    float acc[4][4][4];
#pragma unroll
    for (int i = 0; i < 4; i++)
#pragma unroll
        for (int j = 0; j < 4; j++)
#pragma unroll
            for (int q = 0; q < 4; q++) acc[i][j][q] = 0.f;

    // loads: per tile 128 rows x 32B = 256 x 16B chunks, 1 per thread
    const int lrow = tid >> 1;         // 0..127
    const int lseg = tid & 1;          // 16B segment (k offset 8*lseg)

    auto issue = [&](int kt) {
        const int s = kt % 3;
        uint32_t* st = sm + s * STG_W_;
        const int k0 = kt << 4;
        const uint32_t dw = (uint32_t)__cvta_generic_to_shared(st + lrow * PADW_ + lseg * 4);
        const int ar = m0 + lrow, br = n0 + lrow;
        const int asz = ar < M ? 16 : 0, bsz = br < N ? 16 : 0;
        const long long ai = (long long)ar * lda + k0 + lseg * 8;
        const long long bi = (long long)br * ldb + k0 + lseg * 8;
        cp16(dw,                   Ah + ai, asz);
        cp16(dw + TILE_W_ * 4,     Al + ai, asz);
        cp16(dw + 2 * TILE_W_ * 4, Bh + bi, bsz);
        cp16(dw + 3 * TILE_W_ * 4, Bl + bi, bsz);
        cpcommit();
    };

    const int pre = nkt < 2 ? nkt : 2;
    for (int i = 0; i < pre; i++) issue(i);

    for (int kt = 0; kt < nkt; kt++) {
        if (kt + 2 < nkt) { issue(kt + 2); cpwait2(); }
        else if (kt + 1 < nkt) cpwait1();
        else cpwait0();
        __syncthreads();

        const int s = kt % 3;
        const uint32_t* ah = sm + s * STG_W_;
        const uint32_t* al = ah + TILE_W_;
        const uint32_t* bh = ah + 2 * TILE_W_;
        const uint32_t* bl = ah + 3 * TILE_W_;

        uint32_t afh[4][4], afl[4][4];
#pragma unroll
        for (int i = 0; i < 4; i++) {
            const int rb = (wm + i * 16 + gr) * PADW_ + gc;
            afh[i][0] = ah[rb];                afh[i][1] = ah[rb + 8 * PADW_];
            afh[i][2] = ah[rb + 4];            afh[i][3] = ah[rb + 8 * PADW_ + 4];
            afl[i][0] = al[rb];                afl[i][1] = al[rb + 8 * PADW_];
            afl[i][2] = al[rb + 4];            afl[i][3] = al[rb + 8 * PADW_ + 4];
        }
#pragma unroll
        for (int j = 0; j < 4; j++) {
            const int nb = (wn + j * 8 + gr) * PADW_ + gc;
            const uint32_t bh0 = bh[nb], bh1 = bh[nb + 4];
            const uint32_t bl0 = bl[nb], bl1 = bl[nb + 4];
#pragma unroll
            for (int i = 0; i < 4; i++) {
                mma_bf16(acc[i][j], afh[i], bh0, bh1);
                mma_bf16(acc[i][j], afh[i], bl0, bl1);
                mma_bf16(acc[i][j], afl[i], bh0, bh1);
            }
        }
        __syncthreads();
    }

    // epilogue
#pragma unroll
    for (int i = 0; i < 4; i++) {
        const int r0 = m0 + wm + i * 16 + gr;
        const int r1 = r0 + 8;
        float* crow0 = C + (long long)r0 * ldc;
        float* crow1 = C + (long long)r1 * ldc;
#pragma unroll
        for (int j = 0; j < 4; j++) {
            const int cc = n0 + wn + j * 8 + gc * 2;
            if (cc < N) {
                float b0 = 0.f, b1 = 0.f;
                if (BIAS) { b0 = bias[cc]; b1 = bias[cc + 1]; }
                if (r0 < M) {
                    float2 v = { acc[i][j][0] + b0, acc[i][j][1] + b1 };
                    *(float2*)(crow0 + cc) = v;
                }
                if (r1 < M) {
                    float2 v = { acc[i][j][2] + b0, acc[i][j][3] + b1 };
                    *(float2*)(crow1 + cc) = v;
                }
            }
        }
    }
}

// ---------------- fp32 -> bf16 hi/lo split ----------------
__global__ __launch_bounds__(256)
void cvt_kernel(const float* __restrict__ src, bf16* __restrict__ hi, bf16* __restrict__ lo,
                long long n4)
{
    long long i = (long long)blockIdx.x * blockDim.x + threadIdx.x;
    if (i >= n4) return;
    float4 v = ((const float4*)src)[i];
    union { bf16 b[4]; uint2 u; } ph, pl;
    float f[4] = { v.x, v.y, v.z, v.w };
#pragma unroll
    for (int q = 0; q < 4; q++) {
        bf16 h = __float2bfloat16(f[q]);
        ph.b[q] = h;
        pl.b[q] = __float2bfloat16(f[q] - __bfloat162float(h));
    }
    ((uint2*)hi)[i] = ph.u;
    ((uint2*)lo)[i] = pl.u;
}

// ================= pointwise / softmax / transpose =================
__global__ __launch_bounds__(256)
void rmsnorm_kernel(float* __restrict__ x, const float* __restrict__ w, int cols)
{
    __shared__ float sh[256];
    float* p = x + (long long)blockIdx.x * cols;
    float s = 0.f;
    for (int c = threadIdx.x; c < cols; c += 256) { float v = p[c]; s += v * v; }
    sh[threadIdx.x] = s; __syncthreads();
    for (int o = 128; o > 0; o >>= 1) {
        if (threadIdx.x < o) sh[threadIdx.x] += sh[threadIdx.x + o];
        __syncthreads();
    }
    float rs = rsqrtf(sh[0] / (float)cols + EPSF);
    for (int c = threadIdx.x; c < cols; c += 256) p[c] = w[c] * p[c] * rs;
}

__global__ void rope_table_kernel(float* __restrict__ rope)
{
    int idx = blockIdx.x * blockDim.x + threadIdx.x;
    if (idx >= S_ * 32) return;
    int pos = idx >> 5, j = idx & 31;
    double f = pow(10000.0, -(double)j / 32.0);
    double ang = (double)pos * f;
    rope[pos * 64 + j]      = (float)cos(ang);
    rope[pos * 64 + 32 + j] = (float)sin(ang);
}

__global__ __launch_bounds__(256)
void kvproc_kernel(const float* __restrict__ kvfull, const float* __restrict__ w,
                   const float* __restrict__ rope, float* __restrict__ kcat)
{
    __shared__ float sh[256];
    const int row = blockIdx.x;
    const float* in = kvfull + (long long)row * KC_;
    float* out      = kcat   + (long long)row * KC_;
    float s = 0.f;
    for (int c = threadIdx.x; c < KVL_; c += 256) { float v = in[c]; s += v * v; }
    sh[threadIdx.x] = s; __syncthreads();
    for (int o = 128; o > 0; o >>= 1) {
        if (threadIdx.x < o) sh[threadIdx.x] += sh[threadIdx.x + o];
        __syncthreads();
    }
    float rs = rsqrtf(sh[0] / (float)KVL_ + EPSF);
    for (int c = threadIdx.x; c < KVL_; c += 256) out[c] = w[c] * in[c] * rs;
    if (threadIdx.x < 32) {
        int j = threadIdx.x;
        int pos = row & (S_ - 1);
        float cs = rope[pos * 64 + j], sn = rope[pos * 64 + 32 + j];
        float x1 = in[KVL_ + j], x2 = in[KVL_ + 32 + j];
        out[KVL_ + j]      = x1 * cs - x2 * sn;
        out[KVL_ + 32 + j] = x2 * cs + x1 * sn;
    }
}

__global__ void qpe_rope_kernel(const float* __restrict__ qfull,
                                const float* __restrict__ rope,
                                float* __restrict__ qcat)
{
    int idx = blockIdx.x * blockDim.x + threadIdx.x;
    if (idx >= M_ * NH_ * 32) return;
    int j   = idx & 31;
    int h   = (idx >> 5) & (NH_ - 1);
    int row = idx >> 9;
    int pos = row & (S_ - 1);
    float cs = rope[pos * 64 + j], sn = rope[pos * 64 + 32 + j];
    const float* q = qfull + (long long)row * QDIM_ + h * QKH_ + NOPE_;
    float x1 = q[j], x2 = q[32 + j];
    float* o = qcat + (long long)row * (NH_ * KC_) + h * KC_ + KVL_;
    o[j]      = x1 * cs - x2 * sn;
    o[32 + j] = x2 * cs + x1 * sn;
}

// softmax: reads fp32 scores, writes bf16 hi/lo probs (zero-padded to 128 boundary)
__global__ __launch_bounds__(256)
void softmax_kernel(const float* __restrict__ scores, const int* __restrict__ mask,
                    bf16* __restrict__ ph, bf16* __restrict__ pl)
{
    __shared__ float sh[256];
    const int s = blockIdx.x;
    const int z = blockIdx.y;
    const int b = z >> 4;
    const long long ro = ((long long)z * S_ + s) * S_;
    const float* row = scores + ro;
    bf16* oh = ph + ro;
    bf16* ol = pl + ro;
    const int* mrow = mask + b * S_;
    const int n = s + 1;
    const int tid = threadIdx.x;
    const float scale = 0.07216878364870323f;   // 1/sqrt(192)

    float vals[8];
    float mx = -3.0e38f;
#pragma unroll
    for (int it = 0; it < 8; it++) {
        int t = tid + it * 256;
        float v = -3.0e38f;
        if (t < n) {
            v = row[t] * scale;
            if (mrow[t] == 0) v += MINV;
        }
        vals[it] = v;
        mx = fmaxf(mx, v);
    }
    sh[tid] = mx; __syncthreads();
    for (int o = 128; o > 0; o >>= 1) {
        if (tid < o) sh[tid] = fmaxf(sh[tid], sh[tid + o]);
        __syncthreads();
    }
    mx = sh[0]; __syncthreads();

    float sum = 0.f;
#pragma unroll
    for (int it = 0; it < 8; it++) {
        int t = tid + it * 256;
        if (t < n) { float e = expf(vals[it] - mx); vals[it] = e; sum += e; }
    }
    sh[tid] = sum; __syncthreads();
    for (int o = 128; o > 0; o >>= 1) {
        if (tid < o) sh[tid] += sh[tid + o];
        __syncthreads();
    }
    float inv = 1.f / sh[0];
#pragma unroll
    for (int it = 0; it < 8; it++) {
        int t = tid + it * 256;
        if (t < n) {
            float p = vals[it] * inv;
            bf16 h = __float2bfloat16(p);
            oh[t] = h;
            ol[t] = __float2bfloat16(p - __bfloat162float(h));
        }
    }
    const bf16 zero = __float2bfloat16(0.f);
    int pad = ((s >> 7) + 1) << 7;
    for (int t = n + tid; t < pad; t += 256) { oh[t] = zero; ol[t] = zero; }
}

// dst[z][c][r] = src[z][r][c]
__global__ __launch_bounds__(256)
void transpose_kernel(const float* __restrict__ src, long long sOff, int sld,
                      float* __restrict__ dst, long long dOff, int dld)
{
    __shared__ float t[32][33];
    src += (long long)blockIdx.z * sOff;
    dst += (long long)blockIdx.z * dOff;
    int r0 = blockIdx.y * 32, c0 = blockIdx.x * 32;
    int tx = threadIdx.x & 31, ty = threadIdx.x >> 5;
    for (int rr = ty; rr < 32; rr += 8)
        t[rr][tx] = src[(long long)(r0 + rr) * sld + c0 + tx];
    __syncthreads();
    for (int rr = ty; rr < 32; rr += 8)
        dst[(long long)(c0 + rr) * dld + r0 + tx] = t[tx][rr];
}

// ================= host side =================
static void cvt(const float* src, bf16* hi, bf16* lo, long long n)
{
    long long n4 = n / 4;
    cvt_kernel<<<(unsigned)((n4 + 255) / 256), 256>>>(src, hi, lo, n4);
}

extern "C" void kernel_launch(void* const* d_in, const int* in_sizes, int n_in,
                              void* d_out, int out_size)
{
    (void)in_sizes; (void)n_in; (void)out_size;
    const float* x        = (const float*)d_in[0];
    const int*   mask     = (const int*)  d_in[1];
    const float* wq_a_w   = (const float*)d_in[2];
    const float* wq_a_b   = (const float*)d_in[3];
    const float* q_norm_w = (const float*)d_in[4];
    const float* wq_b_w   = (const float*)d_in[5];
    const float* wq_b_b   = (const float*)d_in[6];
    const float* wkv_a_w  = (const float*)d_in[7];
    const float* wkv_a_b  = (const float*)d_in[8];
    const float* kv_norm_w= (const float*)d_in[9];
    const float* wkv_b_w  = (const float*)d_in[10];
    const float* wo_w     = (const float*)d_in[11];
    const float* wo_b     = (const float*)d_in[12];
    float* out = (float*)d_out;

    float *qa, *qfull, *kvfull, *kcat, *kcatT, *qcat, *scores, *lat2, *oheads, *wkvbT, *rope;
    cudaGetSymbolAddress((void**)&qa,     g_qa);
    cudaGetSymbolAddress((void**)&qfull,  g_qfull);
    cudaGetSymbolAddress((void**)&kvfull, g_kvfull);
    cudaGetSymbolAddress((void**)&kcat,   g_kcat);
    cudaGetSymbolAddress((void**)&kcatT,  g_kcatT);
    cudaGetSymbolAddress((void**)&qcat,   g_qcat);
    cudaGetSymbolAddress((void**)&scores, g_scores);
    cudaGetSymbolAddress((void**)&lat2,   g_lat2);
    cudaGetSymbolAddress((void**)&oheads, g_oheads);
    cudaGetSymbolAddress((void**)&wkvbT,  g_wkvbT);
    cudaGetSymbolAddress((void**)&rope,   g_rope);

    bf16 *x_h,*x_l,*wqa_h,*wqa_l,*wqb_h,*wqb_l,*wkva_h,*wkva_l,*wkvb_h,*wkvb_l;
    bf16 *wkvbT_h,*wkvbT_l,*wo_h,*wo_l,*qa_h,*qa_l,*qfull_h,*qfull_l;
    bf16 *kcat_h,*kcat_l,*kcatT_h,*kcatT_l,*qcat_h,*qcat_l;
    bf16 *probs_h,*probs_l,*lat2_h,*lat2_l,*oheads_h,*oheads_l;
    cudaGetSymbolAddress((void**)&x_h, g_x_h);         cudaGetSymbolAddress((void**)&x_l, g_x_l);
    cudaGetSymbolAddress((void**)&wqa_h, g_wqa_h);     cudaGetSymbolAddress((void**)&wqa_l, g_wqa_l);
    cudaGetSymbolAddress((void**)&wqb_h, g_wqb_h);     cudaGetSymbolAddress((void**)&wqb_l, g_wqb_l);
    cudaGetSymbolAddress((void**)&wkva_h, g_wkva_h);   cudaGetSymbolAddress((void**)&wkva_l, g_wkva_l);
    cudaGetSymbolAddress((void**)&wkvb_h, g_wkvb_h);   cudaGetSymbolAddress((void**)&wkvb_l, g_wkvb_l);
    cudaGetSymbolAddress((void**)&wkvbT_h, g_wkvbT_h); cudaGetSymbolAddress((void**)&wkvbT_l, g_wkvbT_l);
    cudaGetSymbolAddress((void**)&wo_h, g_wo_h);       cudaGetSymbolAddress((void**)&wo_l, g_wo_l);
    cudaGetSymbolAddress((void**)&qa_h, g_qa_h);       cudaGetSymbolAddress((void**)&qa_l, g_qa_l);
    cudaGetSymbolAddress((void**)&qfull_h, g_qfull_h); cudaGetSymbolAddress((void**)&qfull_l, g_qfull_l);
    cudaGetSymbolAddress((void**)&kcat_h, g_kcat_h);   cudaGetSymbolAddress((void**)&kcat_l, g_kcat_l);
    cudaGetSymbolAddress((void**)&kcatT_h, g_kcatT_h); cudaGetSymbolAddress((void**)&kcatT_l, g_kcatT_l);
    cudaGetSymbolAddress((void**)&qcat_h, g_qcat_h);   cudaGetSymbolAddress((void**)&qcat_l, g_qcat_l);
    cudaGetSymbolAddress((void**)&probs_h, g_probs_h); cudaGetSymbolAddress((void**)&probs_l, g_probs_l);
    cudaGetSymbolAddress((void**)&lat2_h, g_lat2_h);   cudaGetSymbolAddress((void**)&lat2_l, g_lat2_l);
    cudaGetSymbolAddress((void**)&oheads_h, g_oheads_h); cudaGetSymbolAddress((void**)&oheads_l, g_oheads_l);

    cudaFuncSetAttribute(gemm_bf3<false,false,true >, cudaFuncAttributeMaxDynamicSharedMemorySize, SMEM_GEMM_);
    cudaFuncSetAttribute(gemm_bf3<false,false,false>, cudaFuncAttributeMaxDynamicSharedMemorySize, SMEM_GEMM_);
    cudaFuncSetAttribute(gemm_bf3<true ,false,false>, cudaFuncAttributeMaxDynamicSharedMemorySize, SMEM_GEMM_);
    cudaFuncSetAttribute(gemm_bf3<false,true ,false>, cudaFuncAttributeMaxDynamicSharedMemorySize, SMEM_GEMM_);

    dim3 thr(256);

    rope_table_kernel<<<(S_ * 32 + 255) / 256, thr>>>(rope);

    // convert inputs/weights
    cvt(x,       x_h,    x_l,    (long long)M_ * H_);
    cvt(wq_a_w,  wqa_h,  wqa_l,  (long long)QL_ * H_);
    cvt(wq_b_w,  wqb_h,  wqb_l,  (long long)QDIM_ * QL_);
    cvt(wkv_a_w, wkva_h, wkva_l, (long long)KC_ * H_);
    cvt(wkv_b_w, wkvb_h, wkvb_l, (long long)NH_ * (NOPE_ + VD_) * KVL_);
    cvt(wo_w,    wo_h,   wo_l,   (long long)H_ * H_);

    // 1) qa = x @ wq_a^T + b    [4096,1536] K=2048
    gemm_bf3<false,false,true><<<dim3(QL_/128, M_/128, 1), thr, SMEM_GEMM_>>>(
        x_h, x_l, H_, 0, 0, wqa_h, wqa_l, H_, 0, 0,
        qa, QL_, 0, 0, M_, QL_, H_, 1, wq_a_b);
    // 2) rmsnorm(qa) then split
    rmsnorm_kernel<<<M_, thr>>>(qa, q_norm_w, QL_);
    cvt(qa, qa_h, qa_l, (long long)M_ * QL_);
    // 3) qfull = qa @ wq_b^T + b  [4096,3072] K=1536
    gemm_bf3<false,false,true><<<dim3(QDIM_/128, M_/128, 1), thr, SMEM_GEMM_>>>(
        qa_h, qa_l, QL_, 0, 0, wqb_h, wqb_l, QL_, 0, 0,
        qfull, QDIM_, 0, 0, M_, QDIM_, QL_, 1, wq_b_b);
    // 4) kvfull = x @ wkv_a^T + b  [4096,576] K=2048
    gemm_bf3<false,false,true><<<dim3((KC_ + 127)/128, M_/128, 1), thr, SMEM_GEMM_>>>(
        x_h, x_l, H_, 0, 0, wkva_h, wkva_l, H_, 0, 0,
        kvfull, KC_, 0, 0, M_, KC_, H_, 1, wkv_a_b);
    // 5) kcat = [rmsnorm(kv) | rope(k_pe)]
    kvproc_kernel<<<M_, thr>>>(kvfull, kv_norm_w, rope, kcat);
    // 6) transposes + splits
    transpose_kernel<<<dim3(KVL_/32, S_/32, B_), thr>>>(
        kcat, (long long)S_ * KC_, KC_, kcatT, (long long)KVL_ * S_, S_);
    transpose_kernel<<<dim3(KVL_/32, NOPE_/32, NH_), thr>>>(
        wkv_b_w, (long long)(NOPE_ + VD_) * KVL_, KVL_, wkvbT, (long long)KVL_ * NOPE_, NOPE_);
    cvt(kcat,  kcat_h,  kcat_l,  (long long)M_ * KC_);
    cvt(kcatT, kcatT_h, kcatT_l, (long long)B_ * KVL_ * S_);
    cvt(wkvbT, wkvbT_h, wkvbT_l, (long long)NH_ * KVL_ * NOPE_);
    cvt(qfull, qfull_h, qfull_l, (long long)M_ * QDIM_);
    // 7) qcat[:,h,:512] = q_nope @ wkvbT[h]^T   batched 16: M=4096 N=512 K=128
    gemm_bf3<false,false,false><<<dim3(KVL_/128, M_/128, NH_), thr, SMEM_GEMM_>>>(
        qfull_h, qfull_l, QDIM_, 0, QKH_,
        wkvbT_h, wkvbT_l, NOPE_, 0, (long long)KVL_ * NOPE_,
        qcat, NH_ * KC_, 0, KC_,
        M_, KVL_, NOPE_, NH_, nullptr);
    // 8) qcat[:,h,512:576] = rope(q_pe)
    qpe_rope_kernel<<<(M_ * NH_ * 32 + 255) / 256, thr>>>(qfull, rope, qcat);
    cvt(qcat, qcat_h, qcat_l, (long long)M_ * NH_ * KC_);
    // 9) scores = qcat @ kcat^T  batched 32 (b,h): M=N=2048 K=576, causal skip
    gemm_bf3<true,false,false><<<dim3(S_/128, S_/128, B_ * NH_), thr, SMEM_GEMM_>>>(
        qcat_h, qcat_l, NH_ * KC_, (long long)S_ * NH_ * KC_, KC_,
        kcat_h, kcat_l, KC_,       (long long)S_ * KC_,       0,
        scores, S_, (long long)NH_ * S_ * S_, (long long)S_ * S_,
        S_, S_, KC_, NH_, nullptr);
    // 10) softmax -> bf16 hi/lo probs
    softmax_kernel<<<dim3(S_, B_ * NH_), thr>>>(scores, mask, probs_h, probs_l);
    // 11) lat2 = probs @ kcatT^T  batched 32: M=2048 N=512 K=causal
    gemm_bf3<false,true,false><<<dim3(KVL_/128, S_/128, B_ * NH_), thr, SMEM_GEMM_>>>(
        probs_h, probs_l, S_, (long long)NH_ * S_ * S_, (long long)S_ * S_,
        kcatT_h, kcatT_l, S_, (long long)KVL_ * S_,     0,
        lat2, NH_ * KVL_, (long long)S_ * NH_ * KVL_, KVL_,
        S_, KVL_, S_, NH_, nullptr);
    cvt(lat2, lat2_h, lat2_l, (long long)M_ * NH_ * KVL_);
    // 12) oheads[:,h*128:] = lat2[:,h] @ wkv_b_v[h]^T  batched 16: M=4096 N=128 K=512
    gemm_bf3<false,false,false><<<dim3(1, M_/128, NH_), thr, SMEM_GEMM_>>>(
        lat2_h, lat2_l, NH_ * KVL_, 0, KVL_,
        wkvb_h + (long long)NOPE_ * KVL_, wkvb_l + (long long)NOPE_ * KVL_,
        KVL_, 0, (long long)(NOPE_ + VD_) * KVL_,
        oheads, H_, 0, VD_,
        M_, VD_, KVL_, NH_, nullptr);
    cvt(oheads, oheads_h, oheads_l, (long long)M_ * H_);
    // 13) out = oheads @ wo^T + b  [4096,2048] K=2048
    gemm_bf3<false,false,true><<<dim3(H_/128, M_/128, 1), thr, SMEM_GEMM_>>>(
        oheads_h, oheads_l, H_, 0, 0, wo_h, wo_l, H_, 0, 0,
        out, H_, 0, 0, M_, H_, H_, 1, wo_b);
}

// round 10
// speedup vs baseline: 5.4385x; 1.1084x over previous
#include <cuda_runtime.h>
#include <cuda_bf16.h>
#include <cuda_fp16.h>
#include <math.h>
#include <stdint.h>

// ---------------- problem constants ----------------
constexpr int B_    = 2;
constexpr int S_    = 2048;
constexpr int H_    = 2048;
constexpr int NH_   = 16;
constexpr int QL_   = 1536;
constexpr int KVL_  = 512;
constexpr int NOPE_ = 128;
constexpr int ROPE_ = 64;
constexpr int VD_   = 128;
constexpr int QKH_  = 192;
constexpr int M_    = B_ * S_;      // 4096
constexpr int QDIM_ = NH_ * QKH_;   // 3072
constexpr int KC_   = KVL_ + ROPE_; // 576
constexpr float EPSF = 1e-6f;
constexpr float MINV = -1e15f;

typedef __nv_bfloat16 bf16;
typedef __half f16;

// ---------------- fp32 scratch ----------------
__device__ float g_qa    [M_ * QL_];
__device__ float g_qfull [M_ * QDIM_];
__device__ float g_kvfull[M_ * KC_];
__device__ float g_kcat  [M_ * KC_];
__device__ float g_scores[(size_t)B_ * NH_ * S_ * S_];
__device__ float g_rope  [S_ * ROPE_];

// ---------------- bf16 hi/lo scratch ----------------
__device__ bf16 g_x_h[M_ * H_],            g_x_l[M_ * H_];
__device__ bf16 g_wqa_h[QL_ * H_],         g_wqa_l[QL_ * H_];
__device__ bf16 g_wqb_h[QDIM_ * QL_],      g_wqb_l[QDIM_ * QL_];
__device__ bf16 g_wkva_h[KC_ * H_],        g_wkva_l[KC_ * H_];
__device__ bf16 g_wkvb_h[NH_ * (NOPE_ + VD_) * KVL_], g_wkvb_l[NH_ * (NOPE_ + VD_) * KVL_];
__device__ bf16 g_wkvbT_h[NH_ * KVL_ * NOPE_], g_wkvbT_l[NH_ * KVL_ * NOPE_];
__device__ bf16 g_wo_h[H_ * H_],           g_wo_l[H_ * H_];
__device__ bf16 g_qa_h[M_ * QL_],          g_qa_l[M_ * QL_];
__device__ bf16 g_qfull_h[M_ * QDIM_],     g_qfull_l[M_ * QDIM_];
__device__ bf16 g_kcat_h[M_ * KC_],        g_kcat_l[M_ * KC_];
__device__ bf16 g_qcat_h[M_ * NH_ * KC_],  g_qcat_l[M_ * NH_ * KC_];
__device__ bf16 g_lat2_h[M_ * NH_ * KVL_], g_lat2_l[M_ * NH_ * KVL_];
__device__ bf16 g_oheads_h[M_ * H_],       g_oheads_l[M_ * H_];
// fp16 scratch
__device__ f16 g_probs[(size_t)B_ * NH_ * S_ * S_];
__device__ f16 g_kcatT_h[B_ * KVL_ * S_],  g_kcatT_l[B_ * KVL_ * S_];

// ---------------- PTX helpers ----------------
__device__ __forceinline__ void mma_bf16(float* d, const uint32_t* a, uint32_t b0, uint32_t b1) {
    asm volatile(
        "mma.sync.aligned.m16n8k16.row.col.f32.bf16.bf16.f32 "
        "{%0,%1,%2,%3}, {%4,%5,%6,%7}, {%8,%9}, {%0,%1,%2,%3};"
        : "+f"(d[0]), "+f"(d[1]), "+f"(d[2]), "+f"(d[3])
        : "r"(a[0]), "r"(a[1]), "r"(a[2]), "r"(a[3]), "r"(b0), "r"(b1));
}
__device__ __forceinline__ void mma_f16(float* d, const uint32_t* a, uint32_t b0, uint32_t b1) {
    asm volatile(
        "mma.sync.aligned.m16n8k16.row.col.f32.f16.f16.f32 "
        "{%0,%1,%2,%3}, {%4,%5,%6,%7}, {%8,%9}, {%0,%1,%2,%3};"
        : "+f"(d[0]), "+f"(d[1]), "+f"(d[2]), "+f"(d[3])
        : "r"(a[0]), "r"(a[1]), "r"(a[2]), "r"(a[3]), "r"(b0), "r"(b1));
}
__device__ __forceinline__ void cp16(uint32_t s, const void* g, int sz) {
    asm volatile("cp.async.cg.shared.global [%0], [%1], 16, %2;"
                 :: "r"(s), "l"(g), "r"(sz) : "memory");
}
__device__ __forceinline__ void cpcommit() { asm volatile("cp.async.commit_group;" ::: "memory"); }
__device__ __forceinline__ void cpwait0()  { asm volatile("cp.async.wait_group 0;" ::: "memory"); }
__device__ __forceinline__ void cpwait1()  { asm volatile("cp.async.wait_group 1;" ::: "memory"); }
__device__ __forceinline__ void cpwait2()  { asm volatile("cp.async.wait_group 2;" ::: "memory"); }

__device__ __forceinline__ uint32_t pack_bf16(float a, float b) {
    union { bf16 v[2]; uint32_t u; } p;
    p.v[0] = __float2bfloat16(a);
    p.v[1] = __float2bfloat16(b);
    return p.u;
}

// ================= bf16x3 tensor-core GEMM =================
// C[M,N] = A[M,K] @ B[N,K]^T (+bias), A/B bf16 hi/lo pairs.
// OUT: 0 = fp32 only, 1 = bf16 hi/lo only, 2 = both.
constexpr int PADW_ = 12;                    // 32-bit words per 16-elem row (8 data + 4 pad)
constexpr int TILE_W_ = 128 * PADW_;
constexpr int STG_W_ = 4 * TILE_W_;
constexpr int SMEM_GEMM_ = 3 * STG_W_ * 4;   // 73728 bytes
constexpr int STGF_W_ = 3 * TILE_W_;
constexpr int SMEM_GEMMF_ = 3 * STGF_W_ * 4; // 55296 bytes

template<bool CSKIP, bool BIAS, int OUT>
__global__ __launch_bounds__(256, 2)
void gemm_bf3(const bf16* __restrict__ Ah, const bf16* __restrict__ Al,
              int lda, long long sAo, long long sAi,
              const bf16* __restrict__ Bh, const bf16* __restrict__ Bl,
              int ldb, long long sBo, long long sBi,
              float* __restrict__ C, bf16* __restrict__ Ch, bf16* __restrict__ Cl,
              int ldc, long long sCo, long long sCi,
              int M, int N, int K, int inner,
              const float* __restrict__ bias)
{
    const int m0 = blockIdx.y * 128;
    const int n0 = blockIdx.x * 128;
    if (CSKIP && n0 >= m0 + 128) return;

    const int z = blockIdx.z;
    const int zo = z / inner, zi = z - zo * inner;
    const long long aoff = zo * sAo + zi * sAi;
    const long long boff = zo * sBo + zi * sBi;
    Ah += aoff; Al += aoff;
    Bh += boff; Bl += boff;
    const long long coff = zo * sCo + zi * sCi;

    extern __shared__ uint32_t sm[];

    const int tid = threadIdx.x;
    const int wid = tid >> 5, lid = tid & 31;
    const int wm = (wid >> 2) * 64;
    const int wn = (wid & 3) * 32;
    const int gr = lid >> 2;
    const int gc = lid & 3;

    const int nkt = K >> 4;

    float acc[4][4][4];
#pragma unroll
    for (int i = 0; i < 4; i++)
#pragma unroll
        for (int j = 0; j < 4; j++)
#pragma unroll
            for (int q = 0; q < 4; q++) acc[i][j][q] = 0.f;

    const int lrow = tid >> 1;
    const int lseg = tid & 1;

    auto issue = [&](int kt) {
        const int s = kt % 3;
        uint32_t* st = sm + s * STG_W_;
        const int k0 = kt << 4;
        const uint32_t dw = (uint32_t)__cvta_generic_to_shared(st + lrow * PADW_ + lseg * 4);
        const int ar = m0 + lrow, br = n0 + lrow;
        const int asz = ar < M ? 16 : 0, bsz = br < N ? 16 : 0;
        const long long ai = (long long)ar * lda + k0 + lseg * 8;
        const long long bi = (long long)br * ldb + k0 + lseg * 8;
        cp16(dw,                   Ah + ai, asz);
        cp16(dw + TILE_W_ * 4,     Al + ai, asz);
        cp16(dw + 2 * TILE_W_ * 4, Bh + bi, bsz);
        cp16(dw + 3 * TILE_W_ * 4, Bl + bi, bsz);
        cpcommit();
    };

    const int pre = nkt < 2 ? nkt : 2;
    for (int i = 0; i < pre; i++) issue(i);

    for (int kt = 0; kt < nkt; kt++) {
        if (kt + 2 < nkt) { issue(kt + 2); cpwait2(); }
        else if (kt + 1 < nkt) cpwait1();
        else cpwait0();
        __syncthreads();

        const int s = kt % 3;
        const uint32_t* ah = sm + s * STG_W_;
        const uint32_t* al = ah + TILE_W_;
        const uint32_t* bh = ah + 2 * TILE_W_;
        const uint32_t* bl = ah + 3 * TILE_W_;

        uint32_t afh[4][4], afl[4][4];
#pragma unroll
        for (int i = 0; i < 4; i++) {
            const int rb = (wm + i * 16 + gr) * PADW_ + gc;
            afh[i][0] = ah[rb];                afh[i][1] = ah[rb + 8 * PADW_];
            afh[i][2] = ah[rb + 4];            afh[i][3] = ah[rb + 8 * PADW_ + 4];
            afl[i][0] = al[rb];                afl[i][1] = al[rb + 8 * PADW_];
            afl[i][2] = al[rb + 4];            afl[i][3] = al[rb + 8 * PADW_ + 4];
        }
#pragma unroll
        for (int j = 0; j < 4; j++) {
            const int nb = (wn + j * 8 + gr) * PADW_ + gc;
            const uint32_t bh0 = bh[nb], bh1 = bh[nb + 4];
            const uint32_t bl0 = bl[nb], bl1 = bl[nb + 4];
#pragma unroll
            for (int i = 0; i < 4; i++) {
                mma_bf16(acc[i][j], afh[i], bh0, bh1);
                mma_bf16(acc[i][j], afh[i], bl0, bl1);
                mma_bf16(acc[i][j], afl[i], bh0, bh1);
            }
        }
        __syncthreads();
    }

    // epilogue
#pragma unroll
    for (int i = 0; i < 4; i++) {
        const int r0 = m0 + wm + i * 16 + gr;
        const int r1 = r0 + 8;
#pragma unroll
        for (int j = 0; j < 4; j++) {
            const int cc = n0 + wn + j * 8 + gc * 2;
            if (cc >= N) continue;
            float b0 = 0.f, b1 = 0.f;
            if (BIAS) { b0 = bias[cc]; b1 = bias[cc + 1]; }
            float v00 = acc[i][j][0] + b0, v01 = acc[i][j][1] + b1;
            float v10 = acc[i][j][2] + b0, v11 = acc[i][j][3] + b1;
            if (r0 < M) {
                const long long o = coff + (long long)r0 * ldc + cc;
                if (OUT != 1) *(float2*)(C + o) = make_float2(v00, v01);
                if (OUT >= 1) {
                    float h0 = __bfloat162float(__float2bfloat16(v00));
                    float h1 = __bfloat162float(__float2bfloat16(v01));
                    *(uint32_t*)(Ch + o) = pack_bf16(v00, v01);
                    *(uint32_t*)(Cl + o) = pack_bf16(v00 - h0, v01 - h1);
                }
            }
            if (r1 < M) {
                const long long o = coff + (long long)r1 * ldc + cc;
                if (OUT != 1) *(float2*)(C + o) = make_float2(v10, v11);
                if (OUT >= 1) {
                    float h0 = __bfloat162float(__float2bfloat16(v10));
                    float h1 = __bfloat162float(__float2bfloat16(v11));
                    *(uint32_t*)(Ch + o) = pack_bf16(v10, v11);
                    *(uint32_t*)(Cl + o) = pack_bf16(v10 - h0, v11 - h1);
                }
            }
        }
    }
}

// ================= fp16 x2 GEMM (probs @ kcatT^T) =================
// A fp16 single, B fp16 hi/lo. CK: Kend = m0+128. Output bf16 hi/lo.
template<bool CK>
__global__ __launch_bounds__(256, 2)
void gemm_f16x2(const f16* __restrict__ A, int lda, long long sAo, long long sAi,
                const f16* __restrict__ Bh, const f16* __restrict__ Bl,
                int ldb, long long sBo, long long sBi,
                bf16* __restrict__ Ch, bf16* __restrict__ Cl,
                int ldc, long long sCo, long long sCi,
                int M, int N, int K, int inner)
{
    const int m0 = blockIdx.y * 128;
    const int n0 = blockIdx.x * 128;

    const int z = blockIdx.z;
    const int zo = z / inner, zi = z - zo * inner;
    A  += zo * sAo + zi * sAi;
    const long long boff = zo * sBo + zi * sBi;
    Bh += boff; Bl += boff;
    const long long coff = zo * sCo + zi * sCi;

    extern __shared__ uint32_t sm[];

    const int tid = threadIdx.x;
    const int wid = tid >> 5, lid = tid & 31;
    const int wm = (wid >> 2) * 64;
    const int wn = (wid & 3) * 32;
    const int gr = lid >> 2;
    const int gc = lid & 3;

    int Kend = K;
    if (CK) { int ke = m0 + 128; Kend = ke < K ? ke : K; }
    const int nkt = Kend >> 4;

    float acc[4][4][4];
#pragma unroll
    for (int i = 0; i < 4; i++)
#pragma unroll
        for (int j = 0; j < 4; j++)
#pragma unroll
            for (int q = 0; q < 4; q++) acc[i][j][q] = 0.f;

    const int lrow = tid >> 1;
    const int lseg = tid & 1;

    auto issue = [&](int kt) {
        const int s = kt % 3;
        uint32_t* st = sm + s * STGF_W_;
        const int k0 = kt << 4;
        const uint32_t dw = (uint32_t)__cvta_generic_to_shared(st + lrow * PADW_ + lseg * 4);
        const int ar = m0 + lrow, br = n0 + lrow;
        const int asz = ar < M ? 16 : 0, bsz = br < N ? 16 : 0;
        const long long ai = (long long)ar * lda + k0 + lseg * 8;
        const long long bi = (long long)br * ldb + k0 + lseg * 8;
        cp16(dw,                   A + ai,  asz);
        cp16(dw + TILE_W_ * 4,     Bh + bi, bsz);
        cp16(dw + 2 * TILE_W_ * 4, Bl + bi, bsz);
        cpcommit();
    };

    const int pre = nkt < 2 ? nkt : 2;
    for (int i = 0; i < pre; i++) issue(i);

    for (int kt = 0; kt < nkt; kt++) {
        if (kt + 2 < nkt) { issue(kt + 2); cpwait2(); }
        else if (kt + 1 < nkt) cpwait1();
        else cpwait0();
        __syncthreads();

        const int s = kt % 3;
        const uint32_t* aa = sm + s * STGF_W_;
        const uint32_t* bh = aa + TILE_W_;
        const uint32_t* bl = aa + 2 * TILE_W_;

        uint32_t af[4][4];
#pragma unroll
        for (int i = 0; i < 4; i++) {
            const int rb = (wm + i * 16 + gr) * PADW_ + gc;
            af[i][0] = aa[rb];      af[i][1] = aa[rb + 8 * PADW_];
            af[i][2] = aa[rb + 4];  af[i][3] = aa[rb + 8 * PADW_ + 4];
        }
#pragma unroll
        for (int j = 0; j < 4; j++) {
            const int nb = (wn + j * 8 + gr) * PADW_ + gc;
            const uint32_t bh0 = bh[nb], bh1 = bh[nb + 4];
            const uint32_t bl0 = bl[nb], bl1 = bl[nb + 4];
#pragma unroll
            for (int i = 0; i < 4; i++) {
                mma_f16(acc[i][j], af[i], bh0, bh1);
                mma_f16(acc[i][j], af[i], bl0, bl1);
            }
        }
        __syncthreads();
    }

#pragma unroll
    for (int i = 0; i < 4; i++) {
        const int r0 = m0 + wm + i * 16 + gr;
        const int r1 = r0 + 8;
#pragma unroll
        for (int j = 0; j < 4; j++) {
            const int cc = n0 + wn + j * 8 + gc * 2;
            if (cc >= N) continue;
            if (r0 < M) {
                const long long o = coff + (long long)r0 * ldc + cc;
                float v0 = acc[i][j][0], v1 = acc[i][j][1];
                float h0 = __bfloat162float(__float2bfloat16(v0));
                float h1 = __bfloat162float(__float2bfloat16(v1));
                *(uint32_t*)(Ch + o) = pack_bf16(v0, v1);
                *(uint32_t*)(Cl + o) = pack_bf16(v0 - h0, v1 - h1);
            }
            if (r1 < M) {
                const long long o = coff + (long long)r1 * ldc + cc;
                float v0 = acc[i][j][2], v1 = acc[i][j][3];
                float h0 = __bfloat162float(__float2bfloat16(v0));
                float h1 = __bfloat162float(__float2bfloat16(v1));
                *(uint32_t*)(Ch + o) = pack_bf16(v0, v1);
                *(uint32_t*)(Cl + o) = pack_bf16(v0 - h0, v1 - h1);
            }
        }
    }
}

// ---------------- fp32 -> bf16 hi/lo split ----------------
__global__ __launch_bounds__(256)
void cvt_kernel(const float* __restrict__ src, bf16* __restrict__ hi, bf16* __restrict__ lo,
                long long n4)
{
    long long i = (long long)blockIdx.x * blockDim.x + threadIdx.x;
    if (i >= n4) return;
    float4 v = ((const float4*)src)[i];
    union { bf16 b[4]; uint2 u; } ph, pl;
    float f[4] = { v.x, v.y, v.z, v.w };
#pragma unroll
    for (int q = 0; q < 4; q++) {
        bf16 h = __float2bfloat16(f[q]);
        ph.b[q] = h;
        pl.b[q] = __float2bfloat16(f[q] - __bfloat162float(h));
    }
    ((uint2*)hi)[i] = ph.u;
    ((uint2*)lo)[i] = pl.u;
}

// ================= pointwise / softmax / transpose =================
// rmsnorm: reads fp32, writes bf16 hi/lo
__global__ __launch_bounds__(256)
void rmsnorm_split_kernel(const float* __restrict__ x, const float* __restrict__ w, int cols,
                          bf16* __restrict__ hi, bf16* __restrict__ lo)
{
    __shared__ float sh[256];
    const float* p = x + (long long)blockIdx.x * cols;
    bf16* oh = hi + (long long)blockIdx.x * cols;
    bf16* ol = lo + (long long)blockIdx.x * cols;
    float s = 0.f;
    for (int c = threadIdx.x; c < cols; c += 256) { float v = p[c]; s += v * v; }
    sh[threadIdx.x] = s; __syncthreads();
    for (int o = 128; o > 0; o >>= 1) {
        if (threadIdx.x < o) sh[threadIdx.x] += sh[threadIdx.x + o];
        __syncthreads();
    }
    float rs = rsqrtf(sh[0] / (float)cols + EPSF);
    for (int c = threadIdx.x; c < cols; c += 256) {
        float v = w[c] * p[c] * rs;
        bf16 h = __float2bfloat16(v);
        oh[c] = h;
        ol[c] = __float2bfloat16(v - __bfloat162float(h));
    }
}

__global__ void rope_table_kernel(float* __restrict__ rope)
{
    int idx = blockIdx.x * blockDim.x + threadIdx.x;
    if (idx >= S_ * 32) return;
    int pos = idx >> 5, j = idx & 31;
    double f = pow(10000.0, -(double)j / 32.0);
    double ang = (double)pos * f;
    rope[pos * 64 + j]      = (float)cos(ang);
    rope[pos * 64 + 32 + j] = (float)sin(ang);
}

// kv branch: kcat fp32 (for transpose) + bf16 hi/lo (for scores B side)
__global__ __launch_bounds__(256)
void kvproc_kernel(const float* __restrict__ kvfull, const float* __restrict__ w,
                   const float* __restrict__ rope, float* __restrict__ kcat,
                   bf16* __restrict__ kh, bf16* __restrict__ kl)
{
    __shared__ float sh[256];
    const int row = blockIdx.x;
    const float* in = kvfull + (long long)row * KC_;
    float* out = kcat + (long long)row * KC_;
    bf16* oh = kh + (long long)row * KC_;
    bf16* ol = kl + (long long)row * KC_;
    float s = 0.f;
    for (int c = threadIdx.x; c < KVL_; c += 256) { float v = in[c]; s += v * v; }
    sh[threadIdx.x] = s; __syncthreads();
    for (int o = 128; o > 0; o >>= 1) {
        if (threadIdx.x < o) sh[threadIdx.x] += sh[threadIdx.x + o];
        __syncthreads();
    }
    float rs = rsqrtf(sh[0] / (float)KVL_ + EPSF);
    for (int c = threadIdx.x; c < KVL_; c += 256) {
        float v = w[c] * in[c] * rs;
        out[c] = v;
        bf16 h = __float2bfloat16(v);
        oh[c] = h;
        ol[c] = __float2bfloat16(v - __bfloat162float(h));
    }
    if (threadIdx.x < 32) {
        int j = threadIdx.x;
        int pos = row & (S_ - 1);
        float cs = rope[pos * 64 + j], sn = rope[pos * 64 + 32 + j];
        float x1 = in[KVL_ + j], x2 = in[KVL_ + 32 + j];
        float v1 = x1 * cs - x2 * sn;
        float v2 = x2 * cs + x1 * sn;
        out[KVL_ + j] = v1;  out[KVL_ + 32 + j] = v2;
        bf16 h1 = __float2bfloat16(v1), h2 = __float2bfloat16(v2);
        oh[KVL_ + j] = h1;       ol[KVL_ + j] = __float2bfloat16(v1 - __bfloat162float(h1));
        oh[KVL_ + 32 + j] = h2;  ol[KVL_ + 32 + j] = __float2bfloat16(v2 - __bfloat162float(h2));
    }
}

// q_pe RoPE -> qcat hi/lo [..., 512:576]
__global__ void qpe_rope_kernel(const float* __restrict__ qfull,
                                const float* __restrict__ rope,
                                bf16* __restrict__ qh, bf16* __restrict__ ql)
{
    int idx = blockIdx.x * blockDim.x + threadIdx.x;
    if (idx >= M_ * NH_ * 32) return;
    int j   = idx & 31;
    int h   = (idx >> 5) & (NH_ - 1);
    int row = idx >> 9;
    int pos = row & (S_ - 1);
    float cs = rope[pos * 64 + j], sn = rope[pos * 64 + 32 + j];
    const float* q = qfull + (long long)row * QDIM_ + h * QKH_ + NOPE_;
    float x1 = q[j], x2 = q[32 + j];
    float v1 = x1 * cs - x2 * sn;
    float v2 = x2 * cs + x1 * sn;
    const long long o = (long long)row * (NH_ * KC_) + h * KC_ + KVL_;
    bf16 h1 = __float2bfloat16(v1), h2 = __float2bfloat16(v2);
    qh[o + j] = h1;       ql[o + j] = __float2bfloat16(v1 - __bfloat162float(h1));
    qh[o + 32 + j] = h2;  ql[o + 32 + j] = __float2bfloat16(v2 - __bfloat162float(h2));
}

// softmax: fp32 scores -> fp16 probs (zero-padded to the 128 boundary)
__global__ __launch_bounds__(256)
void softmax_kernel(const float* __restrict__ scores, const int* __restrict__ mask,
                    f16* __restrict__ probs)
{
    __shared__ float sh[256];
    const int s = blockIdx.x;
    const int z = blockIdx.y;
    const int b = z >> 4;
    const long long ro = ((long long)z * S_ + s) * S_;
    const float* row = scores + ro;
    f16* op = probs + ro;
    const int* mrow = mask + b * S_;
    const int n = s + 1;
    const int tid = threadIdx.x;
    const float scale = 0.07216878364870323f;   // 1/sqrt(192)

    float vals[8];
    float mx = -3.0e38f;
#pragma unroll
    for (int it = 0; it < 8; it++) {
        int t = tid + it * 256;
        float v = -3.0e38f;
        if (t < n) {
            v = row[t] * scale;
            if (mrow[t] == 0) v += MINV;
        }
        vals[it] = v;
        mx = fmaxf(mx, v);
    }
    sh[tid] = mx; __syncthreads();
    for (int o = 128; o > 0; o >>= 1) {
        if (tid < o) sh[tid] = fmaxf(sh[tid], sh[tid + o]);
        __syncthreads();
    }
    mx = sh[0]; __syncthreads();

    float sum = 0.f;
#pragma unroll
    for (int it = 0; it < 8; it++) {
        int t = tid + it * 256;
        if (t < n) { float e = expf(vals[it] - mx); vals[it] = e; sum += e; }
    }
    sh[tid] = sum; __syncthreads();
    for (int o = 128; o > 0; o >>= 1) {
        if (tid < o) sh[tid] += sh[tid + o];
        __syncthreads();
    }
    float inv = 1.f / sh[0];
#pragma unroll
    for (int it = 0; it < 8; it++) {
        int t = tid + it * 256;
        if (t < n) op[t] = __float2half(vals[it] * inv);
    }
    const f16 zero = __float2half(0.f);
    int pad = ((s >> 7) + 1) << 7;
    for (int t = n + tid; t < pad; t += 256) op[t] = zero;
}

// transpose fp32 -> fp16 hi/lo : dst[z][c][r] = src[z][r][c]
__global__ __launch_bounds__(256)
void transpose_f16_kernel(const float* __restrict__ src, long long sOff, int sld,
                          f16* __restrict__ dh, f16* __restrict__ dl,
                          long long dOff, int dld)
{
    __shared__ float t[32][33];
    src += (long long)blockIdx.z * sOff;
    dh  += (long long)blockIdx.z * dOff;
    dl  += (long long)blockIdx.z * dOff;
    int r0 = blockIdx.y * 32, c0 = blockIdx.x * 32;
    int tx = threadIdx.x & 31, ty = threadIdx.x >> 5;
    for (int rr = ty; rr < 32; rr += 8)
        t[rr][tx] = src[(long long)(r0 + rr) * sld + c0 + tx];
    __syncthreads();
    for (int rr = ty; rr < 32; rr += 8) {
        float v = t[tx][rr];
        f16 h = __float2half(v);
        long long o = (long long)(c0 + rr) * dld + r0 + tx;
        dh[o] = h;
        dl[o] = __float2half(v - __half2float(h));
    }
}

// transpose fp32 -> bf16 hi/lo
__global__ __launch_bounds__(256)
void transpose_bf16_kernel(const float* __restrict__ src, long long sOff, int sld,
                           bf16* __restrict__ dh, bf16* __restrict__ dl,
                           long long dOff, int dld)
{
    __shared__ float t[32][33];
    src += (long long)blockIdx.z * sOff;
    dh  += (long long)blockIdx.z * dOff;
    dl  += (long long)blockIdx.z * dOff;
    int r0 = blockIdx.y * 32, c0 = blockIdx.x * 32;
    int tx = threadIdx.x & 31, ty = threadIdx.x >> 5;
    for (int rr = ty; rr < 32; rr += 8)
        t[rr][tx] = src[(long long)(r0 + rr) * sld + c0 + tx];
    __syncthreads();
    for (int rr = ty; rr < 32; rr += 8) {
        float v = t[tx][rr];
        bf16 h = __float2bfloat16(v);
        long long o = (long long)(c0 + rr) * dld + r0 + tx;
        dh[o] = h;
        dl[o] = __float2bfloat16(v - __bfloat162float(h));
    }
}

// ================= host side =================
static void cvt(const float* src, bf16* hi, bf16* lo, long long n)
{
    long long n4 = n / 4;
    cvt_kernel<<<(unsigned)((n4 + 255) / 256), 256>>>(src, hi, lo, n4);
}

extern "C" void kernel_launch(void* const* d_in, const int* in_sizes, int n_in,
                              void* d_out, int out_size)
{
    (void)in_sizes; (void)n_in; (void)out_size;
    const float* x        = (const float*)d_in[0];
    const int*   mask     = (const int*)  d_in[1];
    const float* wq_a_w   = (const float*)d_in[2];
    const float* wq_a_b   = (const float*)d_in[3];
    const float* q_norm_w = (const float*)d_in[4];
    const float* wq_b_w   = (const float*)d_in[5];
    const float* wq_b_b   = (const float*)d_in[6];
    const float* wkv_a_w  = (const float*)d_in[7];
    const float* wkv_a_b  = (const float*)d_in[8];
    const float* kv_norm_w= (const float*)d_in[9];
    const float* wkv_b_w  = (const float*)d_in[10];
    const float* wo_w     = (const float*)d_in[11];
    const float* wo_b     = (const float*)d_in[12];
    float* out = (float*)d_out;

    float *qa, *qfull, *kvfull, *kcat, *scores, *rope;
    cudaGetSymbolAddress((void**)&qa,     g_qa);
    cudaGetSymbolAddress((void**)&qfull,  g_qfull);
    cudaGetSymbolAddress((void**)&kvfull, g_kvfull);
    cudaGetSymbolAddress((void**)&kcat,   g_kcat);
    cudaGetSymbolAddress((void**)&scores, g_scores);
    cudaGetSymbolAddress((void**)&rope,   g_rope);

    bf16 *x_h,*x_l,*wqa_h,*wqa_l,*wqb_h,*wqb_l,*wkva_h,*wkva_l,*wkvb_h,*wkvb_l;
    bf16 *wkvbT_h,*wkvbT_l,*wo_h,*wo_l,*qa_h,*qa_l,*qfull_h,*qfull_l;
    bf16 *kcat_h,*kcat_l,*qcat_h,*qcat_l,*lat2_h,*lat2_l,*oheads_h,*oheads_l;
    f16 *probs,*kcatT_h,*kcatT_l;
    cudaGetSymbolAddress((void**)&x_h, g_x_h);         cudaGetSymbolAddress((void**)&x_l, g_x_l);
    cudaGetSymbolAddress((void**)&wqa_h, g_wqa_h);     cudaGetSymbolAddress((void**)&wqa_l, g_wqa_l);
    cudaGetSymbolAddress((void**)&wqb_h, g_wqb_h);     cudaGetSymbolAddress((void**)&wqb_l, g_wqb_l);
    cudaGetSymbolAddress((void**)&wkva_h, g_wkva_h);   cudaGetSymbolAddress((void**)&wkva_l, g_wkva_l);
    cudaGetSymbolAddress((void**)&wkvb_h, g_wkvb_h);   cudaGetSymbolAddress((void**)&wkvb_l, g_wkvb_l);
    cudaGetSymbolAddress((void**)&wkvbT_h, g_wkvbT_h); cudaGetSymbolAddress((void**)&wkvbT_l, g_wkvbT_l);
    cudaGetSymbolAddress((void**)&wo_h, g_wo_h);       cudaGetSymbolAddress((void**)&wo_l, g_wo_l);
    cudaGetSymbolAddress((void**)&qa_h, g_qa_h);       cudaGetSymbolAddress((void**)&qa_l, g_qa_l);
    cudaGetSymbolAddress((void**)&qfull_h, g_qfull_h); cudaGetSymbolAddress((void**)&qfull_l, g_qfull_l);
    cudaGetSymbolAddress((void**)&kcat_h, g_kcat_h);   cudaGetSymbolAddress((void**)&kcat_l, g_kcat_l);
    cudaGetSymbolAddress((void**)&qcat_h, g_qcat_h);   cudaGetSymbolAddress((void**)&qcat_l, g_qcat_l);
    cudaGetSymbolAddress((void**)&lat2_h, g_lat2_h);   cudaGetSymbolAddress((void**)&lat2_l, g_lat2_l);
    cudaGetSymbolAddress((void**)&oheads_h, g_oheads_h); cudaGetSymbolAddress((void**)&oheads_l, g_oheads_l);
    cudaGetSymbolAddress((void**)&probs, g_probs);
    cudaGetSymbolAddress((void**)&kcatT_h, g_kcatT_h); cudaGetSymbolAddress((void**)&kcatT_l, g_kcatT_l);

    cudaFuncSetAttribute(gemm_bf3<false,true ,0>, cudaFuncAttributeMaxDynamicSharedMemorySize, SMEM_GEMM_);
    cudaFuncSetAttribute(gemm_bf3<false,true ,2>, cudaFuncAttributeMaxDynamicSharedMemorySize, SMEM_GEMM_);
    cudaFuncSetAttribute(gemm_bf3<false,false,1>, cudaFuncAttributeMaxDynamicSharedMemorySize, SMEM_GEMM_);
    cudaFuncSetAttribute(gemm_bf3<true ,false,0>, cudaFuncAttributeMaxDynamicSharedMemorySize, SMEM_GEMM_);
    cudaFuncSetAttribute(gemm_f16x2<true>,        cudaFuncAttributeMaxDynamicSharedMemorySize, SMEM_GEMMF_);

    dim3 thr(256);

    rope_table_kernel<<<(S_ * 32 + 255) / 256, thr>>>(rope);

    // convert inputs/weights once per call
    cvt(x,       x_h,    x_l,    (long long)M_ * H_);
    cvt(wq_a_w,  wqa_h,  wqa_l,  (long long)QL_ * H_);
    cvt(wq_b_w,  wqb_h,  wqb_l,  (long long)QDIM_ * QL_);
    cvt(wkv_a_w, wkva_h, wkva_l, (long long)KC_ * H_);
    cvt(wkv_b_w, wkvb_h, wkvb_l, (long long)NH_ * (NOPE_ + VD_) * KVL_);
    cvt(wo_w,    wo_h,   wo_l,   (long long)H_ * H_);

    // 1) qa = x @ wq_a^T + b  (fp32)
    gemm_bf3<false,true,0><<<dim3(QL_/128, M_/128, 1), thr, SMEM_GEMM_>>>(
        x_h, x_l, H_, 0, 0, wqa_h, wqa_l, H_, 0, 0,
        qa, nullptr, nullptr, QL_, 0, 0, M_, QL_, H_, 1, wq_a_b);
    // 2) rmsnorm -> qa hi/lo
    rmsnorm_split_kernel<<<M_, thr>>>(qa, q_norm_w, QL_, qa_h, qa_l);
    // 3) qfull = qa @ wq_b^T + b  (fp32 for rope + hi/lo for step 7)
    gemm_bf3<false,true,2><<<dim3(QDIM_/128, M_/128, 1), thr, SMEM_GEMM_>>>(
        qa_h, qa_l, QL_, 0, 0, wqb_h, wqb_l, QL_, 0, 0,
        qfull, qfull_h, qfull_l, QDIM_, 0, 0, M_, QDIM_, QL_, 1, wq_b_b);
    // 4) kvfull = x @ wkv_a^T + b  (fp32)
    gemm_bf3<false,true,0><<<dim3((KC_ + 127)/128, M_/128, 1), thr, SMEM_GEMM_>>>(
        x_h, x_l, H_, 0, 0, wkva_h, wkva_l, H_, 0, 0,
        kvfull, nullptr, nullptr, KC_, 0, 0, M_, KC_, H_, 1, wkv_a_b);
    // 5) kcat fp32 + hi/lo
    kvproc_kernel<<<M_, thr>>>(kvfull, kv_norm_w, rope, kcat, kcat_h, kcat_l);
    // 6) kcatT fp16 hi/lo,  wkvbT bf16 hi/lo
    transpose_f16_kernel<<<dim3(KVL_/32, S_/32, B_), thr>>>(
        kcat, (long long)S_ * KC_, KC_, kcatT_h, kcatT_l, (long long)KVL_ * S_, S_);
    transpose_bf16_kernel<<<dim3(KVL_/32, NOPE_/32, NH_), thr>>>(
        wkv_b_w, (long long)(NOPE_ + VD_) * KVL_, KVL_, wkvbT_h, wkvbT_l,
        (long long)KVL_ * NOPE_, NOPE_);
    // 7) qcat[:,h,:512] hi/lo = q_nope @ wkvbT[h]^T   batched 16
    gemm_bf3<false,false,1><<<dim3(KVL_/128, M_/128, NH_), thr, SMEM_GEMM_>>>(
        qfull_h, qfull_l, QDIM_, 0, QKH_,
        wkvbT_h, wkvbT_l, NOPE_, 0, (long long)KVL_ * NOPE_,
        nullptr, qcat_h, qcat_l, NH_ * KC_, 0, KC_,
        M_, KVL_, NOPE_, NH_, nullptr);
    // 8) qcat[:,h,512:576] hi/lo = rope(q_pe)
    qpe_rope_kernel<<<(M_ * NH_ * 32 + 255) / 256, thr>>>(qfull, rope, qcat_h, qcat_l);
    // 9) scores = qcat @ kcat^T  batched 32, causal skip (fp32)
    gemm_bf3<true,false,0><<<dim3(S_/128, S_/128, B_ * NH_), thr, SMEM_GEMM_>>>(
        qcat_h, qcat_l, NH_ * KC_, (long long)S_ * NH_ * KC_, KC_,
        kcat_h, kcat_l, KC_,       (long long)S_ * KC_,       0,
        scores, nullptr, nullptr, S_, (long long)NH_ * S_ * S_, (long long)S_ * S_,
        S_, S_, KC_, NH_, nullptr);
    // 10) softmax -> fp16 probs
    softmax_kernel<<<dim3(S_, B_ * NH_), thr>>>(scores, mask, probs);
    // 11) lat2 hi/lo = probs @ kcatT^T  batched 32, causal K bound (fp16 x2)
    gemm_f16x2<true><<<dim3(KVL_/128, S_/128, B_ * NH_), thr, SMEM_GEMMF_>>>(
        probs, S_, (long long)NH_ * S_ * S_, (long long)S_ * S_,
        kcatT_h, kcatT_l, S_, (long long)KVL_ * S_, 0,
        lat2_h, lat2_l, NH_ * KVL_, (long long)S_ * NH_ * KVL_, KVL_,
        S_, KVL_, S_, NH_);
    // 12) oheads hi/lo = lat2[:,h] @ wkv_b_v[h]^T  batched 16
    gemm_bf3<false,false,1><<<dim3(1, M_/128, NH_), thr, SMEM_GEMM_>>>(
        lat2_h, lat2_l, NH_ * KVL_, 0, KVL_,
        wkvb_h + (long long)NOPE_ * KVL_, wkvb_l + (long long)NOPE_ * KVL_,
        KVL_, 0, (long long)(NOPE_ + VD_) * KVL_,
        nullptr, oheads_h, oheads_l, H_, 0, VD_,
        M_, VD_, KVL_, NH_, nullptr);
    // 13) out = oheads @ wo^T + b  (fp32)
    gemm_bf3<false,true,0><<<dim3(H_/128, M_/128, 1), thr, SMEM_GEMM_>>>(
        oheads_h, oheads_l, H_, 0, 0, wo_h, wo_l, H_, 0, 0,
        out, nullptr, nullptr, H_, 0, 0, M_, H_, H_, 1, wo_b);
}

// round 12
// speedup vs baseline: 5.7063x; 1.0492x over previous
#include <cuda_runtime.h>
#include <cuda_bf16.h>
#include <cuda_fp16.h>
#include <math.h>
#include <stdint.h>

// ---------------- problem constants ----------------
constexpr int B_    = 2;
constexpr int S_    = 2048;
constexpr int H_    = 2048;
constexpr int NH_   = 16;
constexpr int QL_   = 1536;
constexpr int KVL_  = 512;
constexpr int NOPE_ = 128;
constexpr int ROPE_ = 64;
constexpr int VD_   = 128;
constexpr int QKH_  = 192;
constexpr int M_    = B_ * S_;      // 4096
constexpr int QDIM_ = NH_ * QKH_;   // 3072
constexpr int KC_   = KVL_ + ROPE_; // 576
constexpr float EPSF = 1e-6f;
constexpr float MINV = -1e15f;

typedef __nv_bfloat16 bf16;
typedef __half f16;

// ---------------- fp32 scratch ----------------
__device__ float g_qa    [M_ * QL_];
__device__ float g_qfull [M_ * QDIM_];
__device__ float g_kvfull[M_ * KC_];
__device__ float g_kcat  [M_ * KC_];
__device__ float g_scores[(size_t)B_ * NH_ * S_ * S_];
__device__ float g_rope  [S_ * ROPE_];

// ---------------- bf16 hi/lo scratch ----------------
__device__ bf16 g_x_h[M_ * H_],            g_x_l[M_ * H_];
__device__ bf16 g_wqa_h[QL_ * H_],         g_wqa_l[QL_ * H_];
__device__ bf16 g_wqb_h[QDIM_ * QL_],      g_wqb_l[QDIM_ * QL_];
__device__ bf16 g_wkva_h[KC_ * H_],        g_wkva_l[KC_ * H_];
__device__ bf16 g_wkvb_h[NH_ * (NOPE_ + VD_) * KVL_], g_wkvb_l[NH_ * (NOPE_ + VD_) * KVL_];
__device__ bf16 g_wkvbT_h[NH_ * KVL_ * NOPE_], g_wkvbT_l[NH_ * KVL_ * NOPE_];
__device__ bf16 g_wo_h[H_ * H_],           g_wo_l[H_ * H_];
__device__ bf16 g_qa_h[M_ * QL_],          g_qa_l[M_ * QL_];
__device__ bf16 g_qfull_h[M_ * QDIM_],     g_qfull_l[M_ * QDIM_];
__device__ bf16 g_kcat_h[M_ * KC_],        g_kcat_l[M_ * KC_];
__device__ bf16 g_qcat_h[M_ * NH_ * KC_],  g_qcat_l[M_ * NH_ * KC_];
__device__ bf16 g_lat2_h[M_ * NH_ * KVL_], g_lat2_l[M_ * NH_ * KVL_];
__device__ bf16 g_oheads_h[M_ * H_],       g_oheads_l[M_ * H_];
// fp16 scratch
__device__ f16 g_probs[(size_t)B_ * NH_ * S_ * S_];
__device__ f16 g_kcatT_h[B_ * KVL_ * S_],  g_kcatT_l[B_ * KVL_ * S_];

// ---------------- PTX helpers ----------------
__device__ __forceinline__ void mma_bf16(float* d, const uint32_t* a, uint32_t b0, uint32_t b1) {
    asm volatile(
        "mma.sync.aligned.m16n8k16.row.col.f32.bf16.bf16.f32 "
        "{%0,%1,%2,%3}, {%4,%5,%6,%7}, {%8,%9}, {%0,%1,%2,%3};"
        : "+f"(d[0]), "+f"(d[1]), "+f"(d[2]), "+f"(d[3])
        : "r"(a[0]), "r"(a[1]), "r"(a[2]), "r"(a[3]), "r"(b0), "r"(b1));
}
__device__ __forceinline__ void mma_f16(float* d, const uint32_t* a, uint32_t b0, uint32_t b1) {
    asm volatile(
        "mma.sync.aligned.m16n8k16.row.col.f32.f16.f16.f32 "
        "{%0,%1,%2,%3}, {%4,%5,%6,%7}, {%8,%9}, {%0,%1,%2,%3};"
        : "+f"(d[0]), "+f"(d[1]), "+f"(d[2]), "+f"(d[3])
        : "r"(a[0]), "r"(a[1]), "r"(a[2]), "r"(a[3]), "r"(b0), "r"(b1));
}
__device__ __forceinline__ void ldsm4(uint32_t* r, uint32_t addr) {
    asm volatile("ldmatrix.sync.aligned.m8n8.x4.shared.b16 {%0,%1,%2,%3}, [%4];"
                 : "=r"(r[0]), "=r"(r[1]), "=r"(r[2]), "=r"(r[3]) : "r"(addr));
}
__device__ __forceinline__ void cp16(uint32_t s, const void* g, int sz) {
    asm volatile("cp.async.cg.shared.global [%0], [%1], 16, %2;"
                 :: "r"(s), "l"(g), "r"(sz) : "memory");
}
__device__ __forceinline__ void cpcommit() { asm volatile("cp.async.commit_group;" ::: "memory"); }
__device__ __forceinline__ void cpwait0()  { asm volatile("cp.async.wait_group 0;" ::: "memory"); }
__device__ __forceinline__ void cpwait1()  { asm volatile("cp.async.wait_group 1;" ::: "memory"); }
__device__ __forceinline__ void cpwait2()  { asm volatile("cp.async.wait_group 2;" ::: "memory"); }

__device__ __forceinline__ uint32_t pack_bf16(float a, float b) {
    union { bf16 v[2]; uint32_t u; } p;
    p.v[0] = __float2bfloat16(a);
    p.v[1] = __float2bfloat16(b);
    return p.u;
}

// ================= bf16x3 tensor-core GEMM =================
// C[M,N] = A[M,K] @ B[N,K]^T (+bias), A/B bf16 hi/lo pairs.
// OUT: 0 = fp32 only, 1 = bf16 hi/lo only, 2 = both.
constexpr int PADW_ = 12;                    // 32-bit words per 16-elem row (8 data + 4 pad)
constexpr int TILE_W_ = 128 * PADW_;
constexpr int STG_W_ = 4 * TILE_W_;
constexpr int SMEM_GEMM_ = 3 * STG_W_ * 4;   // 73728 bytes
constexpr int STGF_W_ = 3 * TILE_W_;
constexpr int SMEM_GEMMF_ = 3 * STGF_W_ * 4; // 55296 bytes

template<bool CSKIP, bool BIAS, int OUT>
__global__ __launch_bounds__(256, 2)
void gemm_bf3(const bf16* __restrict__ Ah, const bf16* __restrict__ Al,
              int lda, long long sAo, long long sAi,
              const bf16* __restrict__ Bh, const bf16* __restrict__ Bl,
              int ldb, long long sBo, long long sBi,
              float* __restrict__ C, bf16* __restrict__ Ch, bf16* __restrict__ Cl,
              int ldc, long long sCo, long long sCi,
              int M, int N, int K, int inner,
              const float* __restrict__ bias)
{
    const int m0 = blockIdx.y * 128;
    const int n0 = blockIdx.x * 128;
    if (CSKIP && n0 >= m0 + 128) return;

    const int z = blockIdx.z;
    const int zo = z / inner, zi = z - zo * inner;
    const long long aoff = zo * sAo + zi * sAi;
    const long long boff = zo * sBo + zi * sBi;
    Ah += aoff; Al += aoff;
    Bh += boff; Bl += boff;
    const long long coff = zo * sCo + zi * sCi;

    extern __shared__ uint32_t sm[];
    const uint32_t smw = (uint32_t)__cvta_generic_to_shared(sm);

    const int tid = threadIdx.x;
    const int wid = tid >> 5, lid = tid & 31;
    const int wm = (wid >> 2) * 64;
    const int wn = (wid & 3) * 32;
    const int gr = lid >> 2;
    const int gc = lid & 3;

    // ldmatrix per-lane row/koffset (see fragment spec)
    const int lr8 = lid & 7;
    const int mat = lid >> 3;
    const int a_row = (mat & 1) * 8 + lr8;   // + wm + i*16
    const int a_kof = (mat >> 1) * 4;        // words
    const int b_row = (mat >> 1) * 8 + lr8;  // + wn + p*16
    const int b_kof = (mat & 1) * 4;

    const int nkt = K >> 4;

    float acc[4][4][4];
#pragma unroll
    for (int i = 0; i < 4; i++)
#pragma unroll
        for (int j = 0; j < 4; j++)
#pragma unroll
            for (int q = 0; q < 4; q++) acc[i][j][q] = 0.f;

    const int lrow = tid >> 1;
    const int lseg = tid & 1;

    auto issue = [&](int kt) {
        const int s = kt % 3;
        uint32_t* st = sm + s * STG_W_;
        const int k0 = kt << 4;
        const uint32_t dw = (uint32_t)__cvta_generic_to_shared(st + lrow * PADW_ + lseg * 4);
        const int ar = m0 + lrow, br = n0 + lrow;
        const int asz = ar < M ? 16 : 0, bsz = br < N ? 16 : 0;
        const long long ai = (long long)ar * lda + k0 + lseg * 8;
        const long long bi = (long long)br * ldb + k0 + lseg * 8;
        cp16(dw,                   Ah + ai, asz);
        cp16(dw + TILE_W_ * 4,     Al + ai, asz);
        cp16(dw + 2 * TILE_W_ * 4, Bh + bi, bsz);
        cp16(dw + 3 * TILE_W_ * 4, Bl + bi, bsz);
        cpcommit();
    };

    const int pre = nkt < 2 ? nkt : 2;
    for (int i = 0; i < pre; i++) issue(i);

    for (int kt = 0; kt < nkt; kt++) {
        if (kt + 2 < nkt) { issue(kt + 2); cpwait2(); }
        else if (kt + 1 < nkt) cpwait1();
        else cpwait0();
        __syncthreads();

        const int s = kt % 3;
        const uint32_t stb = smw + s * STG_W_ * 4;

        uint32_t afh[4][4], afl[4][4];
#pragma unroll
        for (int i = 0; i < 4; i++) {
            const uint32_t aaddr = stb + (uint32_t)(((wm + i * 16 + a_row) * PADW_ + a_kof) * 4);
            ldsm4(afh[i], aaddr);
            ldsm4(afl[i], aaddr + TILE_W_ * 4);
        }
#pragma unroll
        for (int p = 0; p < 2; p++) {
            const uint32_t baddr = stb + 2 * TILE_W_ * 4 +
                                   (uint32_t)(((wn + p * 16 + b_row) * PADW_ + b_kof) * 4);
            uint32_t bfh[4], bfl[4];
            ldsm4(bfh, baddr);
            ldsm4(bfl, baddr + TILE_W_ * 4);
#pragma unroll
            for (int j2 = 0; j2 < 2; j2++) {
                const int j = p * 2 + j2;
                const uint32_t bh0 = bfh[j2 * 2], bh1 = bfh[j2 * 2 + 1];
                const uint32_t bl0 = bfl[j2 * 2], bl1 = bfl[j2 * 2 + 1];
#pragma unroll
                for (int i = 0; i < 4; i++) {
                    mma_bf16(acc[i][j], afh[i], bh0, bh1);
                    mma_bf16(acc[i][j], afh[i], bl0, bl1);
                    mma_bf16(acc[i][j], afl[i], bh0, bh1);
                }
            }
        }
        __syncthreads();
    }

    // epilogue
#pragma unroll
    for (int i = 0; i < 4; i++) {
        const int r0 = m0 + wm + i * 16 + gr;
        const int r1 = r0 + 8;
#pragma unroll
        for (int j = 0; j < 4; j++) {
            const int cc = n0 + wn + j * 8 + gc * 2;
            if (cc >= N) continue;
            float b0 = 0.f, b1 = 0.f;
            if (BIAS) { b0 = bias[cc]; b1 = bias[cc + 1]; }
            float v00 = acc[i][j][0] + b0, v01 = acc[i][j][1] + b1;
            float v10 = acc[i][j][2] + b0, v11 = acc[i][j][3] + b1;
            if (r0 < M) {
                const long long o = coff + (long long)r0 * ldc + cc;
                if (OUT != 1) *(float2*)(C + o) = make_float2(v00, v01);
                if (OUT >= 1) {
                    float h0 = __bfloat162float(__float2bfloat16(v00));
                    float h1 = __bfloat162float(__float2bfloat16(v01));
                    *(uint32_t*)(Ch + o) = pack_bf16(v00, v01);
                    *(uint32_t*)(Cl + o) = pack_bf16(v00 - h0, v01 - h1);
                }
            }
            if (r1 < M) {
                const long long o = coff + (long long)r1 * ldc + cc;
                if (OUT != 1) *(float2*)(C + o) = make_float2(v10, v11);
                if (OUT >= 1) {
                    float h0 = __bfloat162float(__float2bfloat16(v10));
                    float h1 = __bfloat162float(__float2bfloat16(v11));
                    *(uint32_t*)(Ch + o) = pack_bf16(v10, v11);
                    *(uint32_t*)(Cl + o) = pack_bf16(v10 - h0, v11 - h1);
                }
            }
        }
    }
}

// ================= fp16 x2 GEMM (probs @ kcatT^T) =================
template<bool CK>
__global__ __launch_bounds__(256, 2)
void gemm_f16x2(const f16* __restrict__ A, int lda, long long sAo, long long sAi,
                const f16* __restrict__ Bh, const f16* __restrict__ Bl,
                int ldb, long long sBo, long long sBi,
                bf16* __restrict__ Ch, bf16* __restrict__ Cl,
                int ldc, long long sCo, long long sCi,
                int M, int N, int K, int inner)
{
    const int m0 = blockIdx.y * 128;
    const int n0 = blockIdx.x * 128;

    const int z = blockIdx.z;
    const int zo = z / inner, zi = z - zo * inner;
    A  += zo * sAo + zi * sAi;
    const long long boff = zo * sBo + zi * sBi;
    Bh += boff; Bl += boff;
    const long long coff = zo * sCo + zi * sCi;

    extern __shared__ uint32_t sm[];
    const uint32_t smw = (uint32_t)__cvta_generic_to_shared(sm);

    const int tid = threadIdx.x;
    const int wid = tid >> 5, lid = tid & 31;
    const int wm = (wid >> 2) * 64;
    const int wn = (wid & 3) * 32;
    const int gr = lid >> 2;
    const int gc = lid & 3;

    const int lr8 = lid & 7;
    const int mat = lid >> 3;
    const int a_row = (mat & 1) * 8 + lr8;
    const int a_kof = (mat >> 1) * 4;
    const int b_row = (mat >> 1) * 8 + lr8;
    const int b_kof = (mat & 1) * 4;

    int Kend = K;
    if (CK) { int ke = m0 + 128; Kend = ke < K ? ke : K; }
    const int nkt = Kend >> 4;

    float acc[4][4][4];
#pragma unroll
    for (int i = 0; i < 4; i++)
#pragma unroll
        for (int j = 0; j < 4; j++)
#pragma unroll
            for (int q = 0; q < 4; q++) acc[i][j][q] = 0.f;

    const int lrow = tid >> 1;
    const int lseg = tid & 1;

    auto issue = [&](int kt) {
        const int s = kt % 3;
        uint32_t* st = sm + s * STGF_W_;
        const int k0 = kt << 4;
        const uint32_t dw = (uint32_t)__cvta_generic_to_shared(st + lrow * PADW_ + lseg * 4);
        const int ar = m0 + lrow, br = n0 + lrow;
        const int asz = ar < M ? 16 : 0, bsz = br < N ? 16 : 0;
        const long long ai = (long long)ar * lda + k0 + lseg * 8;
        const long long bi = (long long)br * ldb + k0 + lseg * 8;
        cp16(dw,                   A + ai,  asz);
        cp16(dw + TILE_W_ * 4,     Bh + bi, bsz);
        cp16(dw + 2 * TILE_W_ * 4, Bl + bi, bsz);
        cpcommit();
    };

    const int pre = nkt < 2 ? nkt : 2;
    for (int i = 0; i < pre; i++) issue(i);

    for (int kt = 0; kt < nkt; kt++) {
        if (kt + 2 < nkt) { issue(kt + 2); cpwait2(); }
        else if (kt + 1 < nkt) cpwait1();
        else cpwait0();
        __syncthreads();

        const int s = kt % 3;
        const uint32_t stb = smw + s * STGF_W_ * 4;

        uint32_t af[4][4];
#pragma unroll
        for (int i = 0; i < 4; i++) {
            const uint32_t aaddr = stb + (uint32_t)(((wm + i * 16 + a_row) * PADW_ + a_kof) * 4);
            ldsm4(af[i], aaddr);
        }
#pragma unroll
        for (int p = 0; p < 2; p++) {
            const uint32_t baddr = stb + TILE_W_ * 4 +
                                   (uint32_t)(((wn + p * 16 + b_row) * PADW_ + b_kof) * 4);
            uint32_t bfh[4], bfl[4];
            ldsm4(bfh, baddr);
            ldsm4(bfl, baddr + TILE_W_ * 4);
#pragma unroll
            for (int j2 = 0; j2 < 2; j2++) {
                const int j = p * 2 + j2;
                const uint32_t bh0 = bfh[j2 * 2], bh1 = bfh[j2 * 2 + 1];
                const uint32_t bl0 = bfl[j2 * 2], bl1 = bfl[j2 * 2 + 1];
#pragma unroll
                for (int i = 0; i < 4; i++) {
                    mma_f16(acc[i][j], af[i], bh0, bh1);
                    mma_f16(acc[i][j], af[i], bl0, bl1);
                }
            }
        }
        __syncthreads();
    }

#pragma unroll
    for (int i = 0; i < 4; i++) {
        const int r0 = m0 + wm + i * 16 + gr;
        const int r1 = r0 + 8;
#pragma unroll
        for (int j = 0; j < 4; j++) {
            const int cc = n0 + wn + j * 8 + gc * 2;
            if (cc >= N) continue;
            if (r0 < M) {
                const long long o = coff + (long long)r0 * ldc + cc;
                float v0 = acc[i][j][0], v1 = acc[i][j][1];
                float h0 = __bfloat162float(__float2bfloat16(v0));
                float h1 = __bfloat162float(__float2bfloat16(v1));
                *(uint32_t*)(Ch + o) = pack_bf16(v0, v1);
                *(uint32_t*)(Cl + o) = pack_bf16(v0 - h0, v1 - h1);
            }
            if (r1 < M) {
                const long long o = coff + (long long)r1 * ldc + cc;
                float v0 = acc[i][j][2], v1 = acc[i][j][3];
                float h0 = __bfloat162float(__float2bfloat16(v0));
                float h1 = __bfloat162float(__float2bfloat16(v1));
                *(uint32_t*)(Ch + o) = pack_bf16(v0, v1);
                *(uint32_t*)(Cl + o) = pack_bf16(v0 - h0, v1 - h1);
            }
        }
    }
}

// ---------------- fp32 -> bf16 hi/lo split ----------------
__global__ __launch_bounds__(256)
void cvt_kernel(const float* __restrict__ src, bf16* __restrict__ hi, bf16* __restrict__ lo,
                long long n4)
{
    long long i = (long long)blockIdx.x * blockDim.x + threadIdx.x;
    if (i >= n4) return;
    float4 v = ((const float4*)src)[i];
    union { bf16 b[4]; uint2 u; } ph, pl;
    float f[4] = { v.x, v.y, v.z, v.w };
#pragma unroll
    for (int q = 0; q < 4; q++) {
        bf16 h = __float2bfloat16(f[q]);
        ph.b[q] = h;
        pl.b[q] = __float2bfloat16(f[q] - __bfloat162float(h));
    }
    ((uint2*)hi)[i] = ph.u;
    ((uint2*)lo)[i] = pl.u;
}

// ================= pointwise / softmax / transpose =================
__global__ __launch_bounds__(256)
void rmsnorm_split_kernel(const float* __restrict__ x, const float* __restrict__ w, int cols,
                          bf16* __restrict__ hi, bf16* __restrict__ lo)
{
    __shared__ float sh[256];
    const float* p = x + (long long)blockIdx.x * cols;
    bf16* oh = hi + (long long)blockIdx.x * cols;
    bf16* ol = lo + (long long)blockIdx.x * cols;
    float s = 0.f;
    for (int c = threadIdx.x; c < cols; c += 256) { float v = p[c]; s += v * v; }
    sh[threadIdx.x] = s; __syncthreads();
    for (int o = 128; o > 0; o >>= 1) {
        if (threadIdx.x < o) sh[threadIdx.x] += sh[threadIdx.x + o];
        __syncthreads();
    }
    float rs = rsqrtf(sh[0] / (float)cols + EPSF);
    for (int c = threadIdx.x; c < cols; c += 256) {
        float v = w[c] * p[c] * rs;
        bf16 h = __float2bfloat16(v);
        oh[c] = h;
        ol[c] = __float2bfloat16(v - __bfloat162float(h));
    }
}

__global__ void rope_table_kernel(float* __restrict__ rope)
{
    int idx = blockIdx.x * blockDim.x + threadIdx.x;
    if (idx >= S_ * 32) return;
    int pos = idx >> 5, j = idx & 31;
    double f = pow(10000.0, -(double)j / 32.0);
    double ang = (double)pos * f;
    rope[pos * 64 + j]      = (float)cos(ang);
    rope[pos * 64 + 32 + j] = (float)sin(ang);
}

__global__ __launch_bounds__(256)
void kvproc_kernel(const float* __restrict__ kvfull, const float* __restrict__ w,
                   const float* __restrict__ rope, float* __restrict__ kcat,
                   bf16* __restrict__ kh, bf16* __restrict__ kl)
{
    __shared__ float sh[256];
    const int row = blockIdx.x;
    const float* in = kvfull + (long long)row * KC_;
    float* out = kcat + (long long)row * KC_;
    bf16* oh = kh + (long long)row * KC_;
    bf16* ol = kl + (long long)row * KC_;
    float s = 0.f;
    for (int c = threadIdx.x; c < KVL_; c += 256) { float v = in[c]; s += v * v; }
    sh[threadIdx.x] = s; __syncthreads();
    for (int o = 128; o > 0; o >>= 1) {
        if (threadIdx.x < o) sh[threadIdx.x] += sh[threadIdx.x + o];
        __syncthreads();
    }
    float rs = rsqrtf(sh[0] / (float)KVL_ + EPSF);
    for (int c = threadIdx.x; c < KVL_; c += 256) {
        float v = w[c] * in[c] * rs;
        out[c] = v;
        bf16 h = __float2bfloat16(v);
        oh[c] = h;
        ol[c] = __float2bfloat16(v - __bfloat162float(h));
    }
    if (threadIdx.x < 32) {
        int j = threadIdx.x;
        int pos = row & (S_ - 1);
        float cs = rope[pos * 64 + j], sn = rope[pos * 64 + 32 + j];
        float x1 = in[KVL_ + j], x2 = in[KVL_ + 32 + j];
        float v1 = x1 * cs - x2 * sn;
        float v2 = x2 * cs + x1 * sn;
        out[KVL_ + j] = v1;  out[KVL_ + 32 + j] = v2;
        bf16 h1 = __float2bfloat16(v1), h2 = __float2bfloat16(v2);
        oh[KVL_ + j] = h1;       ol[KVL_ + j] = __float2bfloat16(v1 - __bfloat162float(h1));
        oh[KVL_ + 32 + j] = h2;  ol[KVL_ + 32 + j] = __float2bfloat16(v2 - __bfloat162float(h2));
    }
}

__global__ void qpe_rope_kernel(const float* __restrict__ qfull,
                                const float* __restrict__ rope,
                                bf16* __restrict__ qh, bf16* __restrict__ ql)
{
    int idx = blockIdx.x * blockDim.x + threadIdx.x;
    if (idx >= M_ * NH_ * 32) return;
    int j   = idx & 31;
    int h   = (idx >> 5) & (NH_ - 1);
    int row = idx >> 9;
    int pos = row & (S_ - 1);
    float cs = rope[pos * 64 + j], sn = rope[pos * 64 + 32 + j];
    const float* q = qfull + (long long)row * QDIM_ + h * QKH_ + NOPE_;
    float x1 = q[j], x2 = q[32 + j];
    float v1 = x1 * cs - x2 * sn;
    float v2 = x2 * cs + x1 * sn;
    const long long o = (long long)row * (NH_ * KC_) + h * KC_ + KVL_;
    bf16 h1 = __float2bfloat16(v1), h2 = __float2bfloat16(v2);
    qh[o + j] = h1;       ql[o + j] = __float2bfloat16(v1 - __bfloat162float(h1));
    qh[o + 32 + j] = h2;  ql[o + 32 + j] = __float2bfloat16(v2 - __bfloat162float(h2));
}

__global__ __launch_bounds__(256)
void softmax_kernel(const float* __restrict__ scores, const int* __restrict__ mask,
                    f16* __restrict__ probs)
{
    __shared__ float sh[256];
    const int s = blockIdx.x;
    const int z = blockIdx.y;
    const int b = z >> 4;
    const long long ro = ((long long)z * S_ + s) * S_;
    const float* row = scores + ro;
    f16* op = probs + ro;
    const int* mrow = mask + b * S_;
    const int n = s + 1;
    const int tid = threadIdx.x;
    const float scale = 0.07216878364870323f;   // 1/sqrt(192)

    float vals[8];
    float mx = -3.0e38f;
#pragma unroll
    for (int it = 0; it < 8; it++) {
        int t = tid + it * 256;
        float v = -3.0e38f;
        if (t < n) {
            v = row[t] * scale;
            if (mrow[t] == 0) v += MINV;
        }
        vals[it] = v;
        mx = fmaxf(mx, v);
    }
    sh[tid] = mx; __syncthreads();
    for (int o = 128; o > 0; o >>= 1) {
        if (tid < o) sh[tid] = fmaxf(sh[tid], sh[tid + o]);
        __syncthreads();
    }
    mx = sh[0]; __syncthreads();

    float sum = 0.f;
#pragma unroll
    for (int it = 0; it < 8; it++) {
        int t = tid + it * 256;
        if (t < n) { float e = expf(vals[it] - mx); vals[it] = e; sum += e; }
    }
    sh[tid] = sum; __syncthreads();
    for (int o = 128; o > 0; o >>= 1) {
        if (tid < o) sh[tid] += sh[tid + o];
        __syncthreads();
    }
    float inv = 1.f / sh[0];
#pragma unroll
    for (int it = 0; it < 8; it++) {
        int t = tid + it * 256;
        if (t < n) op[t] = __float2half(vals[it] * inv);
    }
    const f16 zero = __float2half(0.f);
    int pad = ((s >> 7) + 1) << 7;
    for (int t = n + tid; t < pad; t += 256) op[t] = zero;
}

__global__ __launch_bounds__(256)
void transpose_f16_kernel(const float* __restrict__ src, long long sOff, int sld,
                          f16* __restrict__ dh, f16* __restrict__ dl,
                          long long dOff, int dld)
{
    __shared__ float t[32][33];
    src += (long long)blockIdx.z * sOff;
    dh  += (long long)blockIdx.z * dOff;
    dl  += (long long)blockIdx.z * dOff;
    int r0 = blockIdx.y * 32, c0 = blockIdx.x * 32;
    int tx = threadIdx.x & 31, ty = threadIdx.x >> 5;
    for (int rr = ty; rr < 32; rr += 8)
        t[rr][tx] = src[(long long)(r0 + rr) * sld + c0 + tx];
    __syncthreads();
    for (int rr = ty; rr < 32; rr += 8) {
        float v = t[tx][rr];
        f16 h = __float2half(v);
        long long o = (long long)(c0 + rr) * dld + r0 + tx;
        dh[o] = h;
        dl[o] = __float2half(v - __half2float(h));
    }
}

__global__ __launch_bounds__(256)
void transpose_bf16_kernel(const float* __restrict__ src, long long sOff, int sld,
                           bf16* __restrict__ dh, bf16* __restrict__ dl,
                           long long dOff, int dld)
{
    __shared__ float t[32][33];
    src += (long long)blockIdx.z * sOff;
    dh  += (long long)blockIdx.z * dOff;
    dl  += (long long)blockIdx.z * dOff;
    int r0 = blockIdx.y * 32, c0 = blockIdx.x * 32;
    int tx = threadIdx.x & 31, ty = threadIdx.x >> 5;
    for (int rr = ty; rr < 32; rr += 8)
        t[rr][tx] = src[(long long)(r0 + rr) * sld + c0 + tx];
    __syncthreads();
    for (int rr = ty; rr < 32; rr += 8) {
        float v = t[tx][rr];
        bf16 h = __float2bfloat16(v);
        long long o = (long long)(c0 + rr) * dld + r0 + tx;
        dh[o] = h;
        dl[o] = __float2bfloat16(v - __bfloat162float(h));
    }
}

// ================= host side =================
static void cvt(const float* src, bf16* hi, bf16* lo, long long n)
{
    long long n4 = n / 4;
    cvt_kernel<<<(unsigned)((n4 + 255) / 256), 256>>>(src, hi, lo, n4);
}

extern "C" void kernel_launch(void* const* d_in, const int* in_sizes, int n_in,
                              void* d_out, int out_size)
{
    (void)in_sizes; (void)n_in; (void)out_size;
    const float* x        = (const float*)d_in[0];
    const int*   mask     = (const int*)  d_in[1];
    const float* wq_a_w   = (const float*)d_in[2];
    const float* wq_a_b   = (const float*)d_in[3];
    const float* q_norm_w = (const float*)d_in[4];
    const float* wq_b_w   = (const float*)d_in[5];
    const float* wq_b_b   = (const float*)d_in[6];
    const float* wkv_a_w  = (const float*)d_in[7];
    const float* wkv_a_b  = (const float*)d_in[8];
    const float* kv_norm_w= (const float*)d_in[9];
    const float* wkv_b_w  = (const float*)d_in[10];
    const float* wo_w     = (const float*)d_in[11];
    const float* wo_b     = (const float*)d_in[12];
    float* out = (float*)d_out;

    float *qa, *qfull, *kvfull, *kcat, *scores, *rope;
    cudaGetSymbolAddress((void**)&qa,     g_qa);
    cudaGetSymbolAddress((void**)&qfull,  g_qfull);
    cudaGetSymbolAddress((void**)&kvfull, g_kvfull);
    cudaGetSymbolAddress((void**)&kcat,   g_kcat);
    cudaGetSymbolAddress((void**)&scores, g_scores);
    cudaGetSymbolAddress((void**)&rope,   g_rope);

    bf16 *x_h,*x_l,*wqa_h,*wqa_l,*wqb_h,*wqb_l,*wkva_h,*wkva_l,*wkvb_h,*wkvb_l;
    bf16 *wkvbT_h,*wkvbT_l,*wo_h,*wo_l,*qa_h,*qa_l,*qfull_h,*qfull_l;
    bf16 *kcat_h,*kcat_l,*qcat_h,*qcat_l,*lat2_h,*lat2_l,*oheads_h,*oheads_l;
    f16 *probs,*kcatT_h,*kcatT_l;
    cudaGetSymbolAddress((void**)&x_h, g_x_h);         cudaGetSymbolAddress((void**)&x_l, g_x_l);
    cudaGetSymbolAddress((void**)&wqa_h, g_wqa_h);     cudaGetSymbolAddress((void**)&wqa_l, g_wqa_l);
    cudaGetSymbolAddress((void**)&wqb_h, g_wqb_h);     cudaGetSymbolAddress((void**)&wqb_l, g_wqb_l);
    cudaGetSymbolAddress((void**)&wkva_h, g_wkva_h);   cudaGetSymbolAddress((void**)&wkva_l, g_wkva_l);
    cudaGetSymbolAddress((void**)&wkvb_h, g_wkvb_h);   cudaGetSymbolAddress((void**)&wkvb_l, g_wkvb_l);
    cudaGetSymbolAddress((void**)&wkvbT_h, g_wkvbT_h); cudaGetSymbolAddress((void**)&wkvbT_l, g_wkvbT_l);
    cudaGetSymbolAddress((void**)&wo_h, g_wo_h);       cudaGetSymbolAddress((void**)&wo_l, g_wo_l);
    cudaGetSymbolAddress((void**)&qa_h, g_qa_h);       cudaGetSymbolAddress((void**)&qa_l, g_qa_l);
    cudaGetSymbolAddress((void**)&qfull_h, g_qfull_h); cudaGetSymbolAddress((void**)&qfull_l, g_qfull_l);
    cudaGetSymbolAddress((void**)&kcat_h, g_kcat_h);   cudaGetSymbolAddress((void**)&kcat_l, g_kcat_l);
    cudaGetSymbolAddress((void**)&qcat_h, g_qcat_h);   cudaGetSymbolAddress((void**)&qcat_l, g_qcat_l);
    cudaGetSymbolAddress((void**)&lat2_h, g_lat2_h);   cudaGetSymbolAddress((void**)&lat2_l, g_lat2_l);
    cudaGetSymbolAddress((void**)&oheads_h, g_oheads_h); cudaGetSymbolAddress((void**)&oheads_l, g_oheads_l);
    cudaGetSymbolAddress((void**)&probs, g_probs);
    cudaGetSymbolAddress((void**)&kcatT_h, g_kcatT_h); cudaGetSymbolAddress((void**)&kcatT_l, g_kcatT_l);

    cudaFuncSetAttribute(gemm_bf3<false,true ,0>, cudaFuncAttributeMaxDynamicSharedMemorySize, SMEM_GEMM_);
    cudaFuncSetAttribute(gemm_bf3<false,true ,2>, cudaFuncAttributeMaxDynamicSharedMemorySize, SMEM_GEMM_);
    cudaFuncSetAttribute(gemm_bf3<false,false,1>, cudaFuncAttributeMaxDynamicSharedMemorySize, SMEM_GEMM_);
    cudaFuncSetAttribute(gemm_bf3<true ,false,0>, cudaFuncAttributeMaxDynamicSharedMemorySize, SMEM_GEMM_);
    cudaFuncSetAttribute(gemm_f16x2<true>,        cudaFuncAttributeMaxDynamicSharedMemorySize, SMEM_GEMMF_);

    dim3 thr(256);

    // Launch order chosen so launch index 5 (ncu -s 5 -c 1) is the first big GEMM.
    rope_table_kernel<<<(S_ * 32 + 255) / 256, thr>>>(rope);              // 0
    cvt(x,       x_h,    x_l,    (long long)M_ * H_);                     // 1
    cvt(wq_a_w,  wqa_h,  wqa_l,  (long long)QL_ * H_);                    // 2
    cvt(wkv_a_w, wkva_h, wkva_l, (long long)KC_ * H_);                    // 3
    cvt(wkv_b_w, wkvb_h, wkvb_l, (long long)NH_ * (NOPE_ + VD_) * KVL_);  // 4

    // 1) qa = x @ wq_a^T + b  (fp32)                                     // 5 <- profiled
    gemm_bf3<false,true,0><<<dim3(QL_/128, M_/128, 1), thr, SMEM_GEMM_>>>(
        x_h, x_l, H_, 0, 0, wqa_h, wqa_l, H_, 0, 0,
        qa, nullptr, nullptr, QL_, 0, 0, M_, QL_, H_, 1, wq_a_b);

    cvt(wq_b_w,  wqb_h,  wqb_l,  (long long)QDIM_ * QL_);
    cvt(wo_w,    wo_h,   wo_l,   (long long)H_ * H_);

    // 2) rmsnorm -> qa hi/lo
    rmsnorm_split_kernel<<<M_, thr>>>(qa, q_norm_w, QL_, qa_h, qa_l);
    // 3) qfull = qa @ wq_b^T + b
    gemm_bf3<false,true,2><<<dim3(QDIM_/128, M_/128, 1), thr, SMEM_GEMM_>>>(
        qa_h, qa_l, QL_, 0, 0, wqb_h, wqb_l, QL_, 0, 0,
        qfull, qfull_h, qfull_l, QDIM_, 0, 0, M_, QDIM_, QL_, 1, wq_b_b);
    // 4) kvfull = x @ wkv_a^T + b
    gemm_bf3<false,true,0><<<dim3((KC_ + 127)/128, M_/128, 1), thr, SMEM_GEMM_>>>(
        x_h, x_l, H_, 0, 0, wkva_h, wkva_l, H_, 0, 0,
        kvfull, nullptr, nullptr, KC_, 0, 0, M_, KC_, H_, 1, wkv_a_b);
    // 5) kcat fp32 + hi/lo
    kvproc_kernel<<<M_, thr>>>(kvfull, kv_norm_w, rope, kcat, kcat_h, kcat_l);
    // 6) kcatT fp16 hi/lo,  wkvbT bf16 hi/lo
    transpose_f16_kernel<<<dim3(KVL_/32, S_/32, B_), thr>>>(
        kcat, (long long)S_ * KC_, KC_, kcatT_h, kcatT_l, (long long)KVL_ * S_, S_);
    transpose_bf16_kernel<<<dim3(KVL_/32, NOPE_/32, NH_), thr>>>(
        wkv_b_w, (long long)(NOPE_ + VD_) * KVL_, KVL_, wkvbT_h, wkvbT_l,
        (long long)KVL_ * NOPE_, NOPE_);
    // 7) qcat[:,h,:512] hi/lo = q_nope @ wkvbT[h]^T   batched 16
    gemm_bf3<false,false,1><<<dim3(KVL_/128, M_/128, NH_), thr, SMEM_GEMM_>>>(
        qfull_h, qfull_l, QDIM_, 0, QKH_,
        wkvbT_h, wkvbT_l, NOPE_, 0, (long long)KVL_ * NOPE_,
        nullptr, qcat_h, qcat_l, NH_ * KC_, 0, KC_,
        M_, KVL_, NOPE_, NH_, nullptr);
    // 8) qcat[:,h,512:576] hi/lo = rope(q_pe)
    qpe_rope_kernel<<<(M_ * NH_ * 32 + 255) / 256, thr>>>(qfull, rope, qcat_h, qcat_l);
    // 9) scores = qcat @ kcat^T  batched 32, causal skip (fp32)
    gemm_bf3<true,false,0><<<dim3(S_/128, S_/128, B_ * NH_), thr, SMEM_GEMM_>>>(
        qcat_h, qcat_l, NH_ * KC_, (long long)S_ * NH_ * KC_, KC_,
        kcat_h, kcat_l, KC_,       (long long)S_ * KC_,       0,
        scores, nullptr, nullptr, S_, (long long)NH_ * S_ * S_, (long long)S_ * S_,
        S_, S_, KC_, NH_, nullptr);
    // 10) softmax -> fp16 probs
    softmax_kernel<<<dim3(S_, B_ * NH_), thr>>>(scores, mask, probs);
    // 11) lat2 hi/lo = probs @ kcatT^T  batched 32, causal K bound (fp16 x2)
    gemm_f16x2<true><<<dim3(KVL_/128, S_/128, B_ * NH_), thr, SMEM_GEMMF_>>>(
        probs, S_, (long long)NH_ * S_ * S_, (long long)S_ * S_,
        kcatT_h, kcatT_l, S_, (long long)KVL_ * S_, 0,
        lat2_h, lat2_l, NH_ * KVL_, (long long)S_ * NH_ * KVL_, KVL_,
        S_, KVL_, S_, NH_);
    // 12) oheads hi/lo = lat2[:,h] @ wkv_b_v[h]^T  batched 16
    gemm_bf3<false,false,1><<<dim3(1, M_/128, NH_), thr, SMEM_GEMM_>>>(
        lat2_h, lat2_l, NH_ * KVL_, 0, KVL_,
        wkvb_h + (long long)NOPE_ * KVL_, wkvb_l + (long long)NOPE_ * KVL_,
        KVL_, 0, (long long)(NOPE_ + VD_) * KVL_,
        nullptr, oheads_h, oheads_l, H_, 0, VD_,
        M_, VD_, KVL_, NH_, nullptr);
    // 13) out = oheads @ wo^T + b  (fp32)
    gemm_bf3<false,true,0><<<dim3(H_/128, M_/128, 1), thr, SMEM_GEMM_>>>(
        oheads_h, oheads_l, H_, 0, 0, wo_h, wo_l, H_, 0, 0,
        out, nullptr, nullptr, H_, 0, 0, M_, H_, H_, 1, wo_b);
}

// round 13
// speedup vs baseline: 7.9572x; 1.3945x over previous
#include <cuda_runtime.h>
#include <cuda_bf16.h>
#include <cuda_fp16.h>
#include <math.h>
#include <stdint.h>

// ---------------- problem constants ----------------
constexpr int B_    = 2;
constexpr int S_    = 2048;
constexpr int H_    = 2048;
constexpr int NH_   = 16;
constexpr int QL_   = 1536;
constexpr int KVL_  = 512;
constexpr int NOPE_ = 128;
constexpr int ROPE_ = 64;
constexpr int VD_   = 128;
constexpr int QKH_  = 192;
constexpr int M_    = B_ * S_;      // 4096
constexpr int QDIM_ = NH_ * QKH_;   // 3072
constexpr int KC_   = KVL_ + ROPE_; // 576
constexpr float EPSF = 1e-6f;
constexpr float MINV = -1e15f;

typedef __nv_bfloat16 bf16;
typedef __half f16;

// ---------------- fp32 scratch ----------------
__device__ float g_qa    [M_ * QL_];
__device__ float g_qfull [M_ * QDIM_];
__device__ float g_kvfull[M_ * KC_];
__device__ float g_kcat  [M_ * KC_];
__device__ float g_scores[(size_t)B_ * NH_ * S_ * S_];
__device__ float g_rope  [S_ * ROPE_];

// ---------------- bf16 hi/lo scratch ----------------
__device__ bf16 g_x_h[M_ * H_],            g_x_l[M_ * H_];
__device__ bf16 g_wqa_h[QL_ * H_],         g_wqa_l[QL_ * H_];
__device__ bf16 g_wqb_h[QDIM_ * QL_],      g_wqb_l[QDIM_ * QL_];
__device__ bf16 g_wkva_h[KC_ * H_],        g_wkva_l[KC_ * H_];
__device__ bf16 g_wkvb_h[NH_ * (NOPE_ + VD_) * KVL_], g_wkvb_l[NH_ * (NOPE_ + VD_) * KVL_];
__device__ bf16 g_wo_h[H_ * H_],           g_wo_l[H_ * H_];
__device__ bf16 g_qa_h[M_ * QL_],          g_qa_l[M_ * QL_];
__device__ bf16 g_qfull_h[M_ * QDIM_],     g_qfull_l[M_ * QDIM_];
__device__ bf16 g_kcat_h[M_ * KC_],        g_kcat_l[M_ * KC_];
__device__ bf16 g_kcat192_h[M_ * QDIM_],   g_kcat192_l[M_ * QDIM_];   // [r][h*192+d]
__device__ bf16 g_oheads_h[M_ * H_],       g_oheads_l[M_ * H_];
// fp16 scratch
__device__ f16 g_probs[(size_t)B_ * NH_ * S_ * S_];
__device__ f16 g_vT_h[NH_ * VD_ * M_],     g_vT_l[NH_ * VD_ * M_];    // [h][d][b*S+t]

// ---------------- PTX helpers ----------------
__device__ __forceinline__ void mma_bf16(float* d, const uint32_t* a, uint32_t b0, uint32_t b1) {
    asm volatile(
        "mma.sync.aligned.m16n8k16.row.col.f32.bf16.bf16.f32 "
        "{%0,%1,%2,%3}, {%4,%5,%6,%7}, {%8,%9}, {%0,%1,%2,%3};"
        : "+f"(d[0]), "+f"(d[1]), "+f"(d[2]), "+f"(d[3])
        : "r"(a[0]), "r"(a[1]), "r"(a[2]), "r"(a[3]), "r"(b0), "r"(b1));
}
__device__ __forceinline__ void mma_f16(float* d, const uint32_t* a, uint32_t b0, uint32_t b1) {
    asm volatile(
        "mma.sync.aligned.m16n8k16.row.col.f32.f16.f16.f32 "
        "{%0,%1,%2,%3}, {%4,%5,%6,%7}, {%8,%9}, {%0,%1,%2,%3};"
        : "+f"(d[0]), "+f"(d[1]), "+f"(d[2]), "+f"(d[3])
        : "r"(a[0]), "r"(a[1]), "r"(a[2]), "r"(a[3]), "r"(b0), "r"(b1));
}
__device__ __forceinline__ void ldsm4(uint32_t* r, uint32_t addr) {
    asm volatile("ldmatrix.sync.aligned.m8n8.x4.shared.b16 {%0,%1,%2,%3}, [%4];"
                 : "=r"(r[0]), "=r"(r[1]), "=r"(r[2]), "=r"(r[3]) : "r"(addr));
}
__device__ __forceinline__ void cp16(uint32_t s, const void* g, int sz) {
    asm volatile("cp.async.cg.shared.global [%0], [%1], 16, %2;"
                 :: "r"(s), "l"(g), "r"(sz) : "memory");
}
__device__ __forceinline__ void cpcommit() { asm volatile("cp.async.commit_group;" ::: "memory"); }
__device__ __forceinline__ void cpwait0()  { asm volatile("cp.async.wait_group 0;" ::: "memory"); }
__device__ __forceinline__ void cpwait1()  { asm volatile("cp.async.wait_group 1;" ::: "memory"); }
__device__ __forceinline__ void cpwait2()  { asm volatile("cp.async.wait_group 2;" ::: "memory"); }

__device__ __forceinline__ uint32_t pack_bf16(float a, float b) {
    union { bf16 v[2]; uint32_t u; } p;
    p.v[0] = __float2bfloat16(a);
    p.v[1] = __float2bfloat16(b);
    return p.u;
}
__device__ __forceinline__ uint32_t pack_f16(float a, float b) {
    union { f16 v[2]; uint32_t u; } p;
    p.v[0] = __float2half(a);
    p.v[1] = __float2half(b);
    return p.u;
}

// ================= bf16x3 tensor-core GEMM =================
// C[M,N] = A[M,K] @ B[N,K]^T (+bias), A/B bf16 hi/lo pairs.
// OUT: 0 = fp32, 1 = bf16 hi/lo, 2 = fp32 + bf16 hi/lo, 3 = fp16 hi/lo.
constexpr int PADW_ = 12;
constexpr int TILE_W_ = 128 * PADW_;
constexpr int STG_W_ = 4 * TILE_W_;
constexpr int SMEM_GEMM_ = 3 * STG_W_ * 4;   // 73728 bytes
constexpr int STGF_W_ = 3 * TILE_W_;
constexpr int SMEM_GEMMF_ = 3 * STGF_W_ * 4; // 55296 bytes

template<bool CSKIP, bool BIAS, int OUT>
__global__ __launch_bounds__(256, 2)
void gemm_bf3(const bf16* __restrict__ Ah, const bf16* __restrict__ Al,
              int lda, long long sAo, long long sAi,
              const bf16* __restrict__ Bh, const bf16* __restrict__ Bl,
              int ldb, long long sBo, long long sBi,
              float* __restrict__ C, bf16* __restrict__ Ch, bf16* __restrict__ Cl,
              int ldc, long long sCo, long long sCi,
              int M, int N, int K, int inner,
              const float* __restrict__ bias)
{
    const int m0 = blockIdx.y * 128;
    const int n0 = blockIdx.x * 128;
    if (CSKIP && n0 >= m0 + 128) return;

    const int z = blockIdx.z;
    const int zo = z / inner, zi = z - zo * inner;
    const long long aoff = zo * sAo + zi * sAi;
    const long long boff = zo * sBo + zi * sBi;
    Ah += aoff; Al += aoff;
    Bh += boff; Bl += boff;
    const long long coff = zo * sCo + zi * sCi;

    extern __shared__ uint32_t sm[];
    const uint32_t smw = (uint32_t)__cvta_generic_to_shared(sm);

    const int tid = threadIdx.x;
    const int wid = tid >> 5, lid = tid & 31;
    const int wm = (wid >> 2) * 64;
    const int wn = (wid & 3) * 32;
    const int gr = lid >> 2;
    const int gc = lid & 3;

    const int lr8 = lid & 7;
    const int mat = lid >> 3;
    const int a_row = (mat & 1) * 8 + lr8;
    const int a_kof = (mat >> 1) * 4;
    const int b_row = (mat >> 1) * 8 + lr8;
    const int b_kof = (mat & 1) * 4;

    const int nkt = K >> 4;

    float acc[4][4][4];
#pragma unroll
    for (int i = 0; i < 4; i++)
#pragma unroll
        for (int j = 0; j < 4; j++)
#pragma unroll
            for (int q = 0; q < 4; q++) acc[i][j][q] = 0.f;

    const int lrow = tid >> 1;
    const int lseg = tid & 1;

    auto issue = [&](int kt) {
        const int s = kt % 3;
        uint32_t* st = sm + s * STG_W_;
        const int k0 = kt << 4;
        const uint32_t dw = (uint32_t)__cvta_generic_to_shared(st + lrow * PADW_ + lseg * 4);
        const int ar = m0 + lrow, br = n0 + lrow;
        const int asz = ar < M ? 16 : 0, bsz = br < N ? 16 : 0;
        const long long ai = (long long)ar * lda + k0 + lseg * 8;
        const long long bi = (long long)br * ldb + k0 + lseg * 8;
        cp16(dw,                   Ah + ai, asz);
        cp16(dw + TILE_W_ * 4,     Al + ai, asz);
        cp16(dw + 2 * TILE_W_ * 4, Bh + bi, bsz);
        cp16(dw + 3 * TILE_W_ * 4, Bl + bi, bsz);
        cpcommit();
    };

    const int pre = nkt < 2 ? nkt : 2;
    for (int i = 0; i < pre; i++) issue(i);

    for (int kt = 0; kt < nkt; kt++) {
        if (kt + 2 < nkt) { issue(kt + 2); cpwait2(); }
        else if (kt + 1 < nkt) cpwait1();
        else cpwait0();
        __syncthreads();

        const int s = kt % 3;
        const uint32_t stb = smw + s * STG_W_ * 4;

        uint32_t afh[4][4], afl[4][4];
#pragma unroll
        for (int i = 0; i < 4; i++) {
            const uint32_t aaddr = stb + (uint32_t)(((wm + i * 16 + a_row) * PADW_ + a_kof) * 4);
            ldsm4(afh[i], aaddr);
            ldsm4(afl[i], aaddr + TILE_W_ * 4);
        }
#pragma unroll
        for (int p = 0; p < 2; p++) {
            const uint32_t baddr = stb + 2 * TILE_W_ * 4 +
                                   (uint32_t)(((wn + p * 16 + b_row) * PADW_ + b_kof) * 4);
            uint32_t bfh[4], bfl[4];
            ldsm4(bfh, baddr);
            ldsm4(bfl, baddr + TILE_W_ * 4);
#pragma unroll
            for (int j2 = 0; j2 < 2; j2++) {
                const int j = p * 2 + j2;
                const uint32_t bh0 = bfh[j2 * 2], bh1 = bfh[j2 * 2 + 1];
                const uint32_t bl0 = bfl[j2 * 2], bl1 = bfl[j2 * 2 + 1];
#pragma unroll
                for (int i = 0; i < 4; i++) {
                    mma_bf16(acc[i][j], afh[i], bh0, bh1);
                    mma_bf16(acc[i][j], afh[i], bl0, bl1);
                    mma_bf16(acc[i][j], afl[i], bh0, bh1);
                }
            }
        }
        __syncthreads();
    }

    // epilogue
    f16* Fh = (f16*)Ch;
    f16* Fl = (f16*)Cl;
#pragma unroll
    for (int i = 0; i < 4; i++) {
        const int r0 = m0 + wm + i * 16 + gr;
        const int r1 = r0 + 8;
#pragma unroll
        for (int j = 0; j < 4; j++) {
            const int cc = n0 + wn + j * 8 + gc * 2;
            if (cc >= N) continue;
            float b0 = 0.f, b1 = 0.f;
            if (BIAS) { b0 = bias[cc]; b1 = bias[cc + 1]; }
            float v00 = acc[i][j][0] + b0, v01 = acc[i][j][1] + b1;
            float v10 = acc[i][j][2] + b0, v11 = acc[i][j][3] + b1;
            if (r0 < M) {
                const long long o = coff + (long long)r0 * ldc + cc;
                if (OUT == 0 || OUT == 2) *(float2*)(C + o) = make_float2(v00, v01);
                if (OUT == 1 || OUT == 2) {
                    float h0 = __bfloat162float(__float2bfloat16(v00));
                    float h1 = __bfloat162float(__float2bfloat16(v01));
                    *(uint32_t*)(Ch + o) = pack_bf16(v00, v01);
                    *(uint32_t*)(Cl + o) = pack_bf16(v00 - h0, v01 - h1);
                }
                if (OUT == 3) {
                    float h0 = __half2float(__float2half(v00));
                    float h1 = __half2float(__float2half(v01));
                    *(uint32_t*)(Fh + o) = pack_f16(v00, v01);
                    *(uint32_t*)(Fl + o) = pack_f16(v00 - h0, v01 - h1);
                }
            }
            if (r1 < M) {
                const long long o = coff + (long long)r1 * ldc + cc;
                if (OUT == 0 || OUT == 2) *(float2*)(C + o) = make_float2(v10, v11);
                if (OUT == 1 || OUT == 2) {
                    float h0 = __bfloat162float(__float2bfloat16(v10));
                    float h1 = __bfloat162float(__float2bfloat16(v11));
                    *(uint32_t*)(Ch + o) = pack_bf16(v10, v11);
                    *(uint32_t*)(Cl + o) = pack_bf16(v10 - h0, v11 - h1);
                }
                if (OUT == 3) {
                    float h0 = __half2float(__float2half(v10));
                    float h1 = __half2float(__float2half(v11));
                    *(uint32_t*)(Fh + o) = pack_f16(v10, v11);
                    *(uint32_t*)(Fl + o) = pack_f16(v10 - h0, v11 - h1);
                }
            }
        }
    }
}

// ================= fp16 x2 GEMM (probs @ vT^T) =================
// A fp16 single, B fp16 hi/lo. CK: Kend = m0+128. Output bf16 hi/lo.
template<bool CK>
__global__ __launch_bounds__(256, 2)
void gemm_f16x2(const f16* __restrict__ A, int lda, long long sAo, long long sAi,
                const f16* __restrict__ Bh, const f16* __restrict__ Bl,
                int ldb, long long sBo, long long sBi,
                bf16* __restrict__ Ch, bf16* __restrict__ Cl,
                int ldc, long long sCo, long long sCi,
                int M, int N, int K, int inner)
{
    const int m0 = blockIdx.y * 128;
    const int n0 = blockIdx.x * 128;

    const int z = blockIdx.z;
    const int zo = z / inner, zi = z - zo * inner;
    A  += zo * sAo + zi * sAi;
    const long long boff = zo * sBo + zi * sBi;
    Bh += boff; Bl += boff;
    const long long coff = zo * sCo + zi * sCi;

    extern __shared__ uint32_t sm[];
    const uint32_t smw = (uint32_t)__cvta_generic_to_shared(sm);

    const int tid = threadIdx.x;
    const int wid = tid >> 5, lid = tid & 31;
    const int wm = (wid >> 2) * 64;
    const int wn = (wid & 3) * 32;
    const int gr = lid >> 2;
    const int gc = lid & 3;

    const int lr8 = lid & 7;
    const int mat = lid >> 3;
    const int a_row = (mat & 1) * 8 + lr8;
    const int a_kof = (mat >> 1) * 4;
    const int b_row = (mat >> 1) * 8 + lr8;
    const int b_kof = (mat & 1) * 4;

    int Kend = K;
    if (CK) { int ke = m0 + 128; Kend = ke < K ? ke : K; }
    const int nkt = Kend >> 4;

    float acc[4][4][4];
#pragma unroll
    for (int i = 0; i < 4; i++)
#pragma unroll
        for (int j = 0; j < 4; j++)
#pragma unroll
            for (int q = 0; q < 4; q++) acc[i][j][q] = 0.f;

    const int lrow = tid >> 1;
    const int lseg = tid & 1;

    auto issue = [&](int kt) {
        const int s = kt % 3;
        uint32_t* st = sm + s * STGF_W_;
        const int k0 = kt << 4;
        const uint32_t dw = (uint32_t)__cvta_generic_to_shared(st + lrow * PADW_ + lseg * 4);
        const int ar = m0 + lrow, br = n0 + lrow;
        const int asz = ar < M ? 16 : 0, bsz = br < N ? 16 : 0;
        const long long ai = (long long)ar * lda + k0 + lseg * 8;
        const long long bi = (long long)br * ldb + k0 + lseg * 8;
        cp16(dw,                   A + ai,  asz);
        cp16(dw + TILE_W_ * 4,     Bh + bi, bsz);
        cp16(dw + 2 * TILE_W_ * 4, Bl + bi, bsz);
        cpcommit();
    };

    const int pre = nkt < 2 ? nkt : 2;
    for (int i = 0; i < pre; i++) issue(i);

    for (int kt = 0; kt < nkt; kt++) {
        if (kt + 2 < nkt) { issue(kt + 2); cpwait2(); }
        else if (kt + 1 < nkt) cpwait1();
        else cpwait0();
        __syncthreads();

        const int s = kt % 3;
        const uint32_t stb = smw + s * STGF_W_ * 4;

        uint32_t af[4][4];
#pragma unroll
        for (int i = 0; i < 4; i++) {
            const uint32_t aaddr = stb + (uint32_t)(((wm + i * 16 + a_row) * PADW_ + a_kof) * 4);
            ldsm4(af[i], aaddr);
        }
#pragma unroll
        for (int p = 0; p < 2; p++) {
            const uint32_t baddr = stb + TILE_W_ * 4 +
                                   (uint32_t)(((wn + p * 16 + b_row) * PADW_ + b_kof) * 4);
            uint32_t bfh[4], bfl[4];
            ldsm4(bfh, baddr);
            ldsm4(bfl, baddr + TILE_W_ * 4);
#pragma unroll
            for (int j2 = 0; j2 < 2; j2++) {
                const int j = p * 2 + j2;
                const uint32_t bh0 = bfh[j2 * 2], bh1 = bfh[j2 * 2 + 1];
                const uint32_t bl0 = bfl[j2 * 2], bl1 = bfl[j2 * 2 + 1];
#pragma unroll
                for (int i = 0; i < 4; i++) {
                    mma_f16(acc[i][j], af[i], bh0, bh1);
                    mma_f16(acc[i][j], af[i], bl0, bl1);
                }
            }
        }
        __syncthreads();
    }

#pragma unroll
    for (int i = 0; i < 4; i++) {
        const int r0 = m0 + wm + i * 16 + gr;
        const int r1 = r0 + 8;
#pragma unroll
        for (int j = 0; j < 4; j++) {
            const int cc = n0 + wn + j * 8 + gc * 2;
            if (cc >= N) continue;
            if (r0 < M) {
                const long long o = coff + (long long)r0 * ldc + cc;
                float v0 = acc[i][j][0], v1 = acc[i][j][1];
                float h0 = __bfloat162float(__float2bfloat16(v0));
                float h1 = __bfloat162float(__float2bfloat16(v1));
                *(uint32_t*)(Ch + o) = pack_bf16(v0, v1);
                *(uint32_t*)(Cl + o) = pack_bf16(v0 - h0, v1 - h1);
            }
            if (r1 < M) {
                const long long o = coff + (long long)r1 * ldc + cc;
                float v0 = acc[i][j][2], v1 = acc[i][j][3];
                float h0 = __bfloat162float(__float2bfloat16(v0));
                float h1 = __bfloat162float(__float2bfloat16(v1));
                *(uint32_t*)(Ch + o) = pack_bf16(v0, v1);
                *(uint32_t*)(Cl + o) = pack_bf16(v0 - h0, v1 - h1);
            }
        }
    }
}

// ---------------- fp32 -> bf16 hi/lo split ----------------
__global__ __launch_bounds__(256)
void cvt_kernel(const float* __restrict__ src, bf16* __restrict__ hi, bf16* __restrict__ lo,
                long long n4)
{
    long long i = (long long)blockIdx.x * blockDim.x + threadIdx.x;
    if (i >= n4) return;
    float4 v = ((const float4*)src)[i];
    union { bf16 b[4]; uint2 u; } ph, pl;
    float f[4] = { v.x, v.y, v.z, v.w };
#pragma unroll
    for (int q = 0; q < 4; q++) {
        bf16 h = __float2bfloat16(f[q]);
        ph.b[q] = h;
        pl.b[q] = __float2bfloat16(f[q] - __bfloat162float(h));
    }
    ((uint2*)hi)[i] = ph.u;
    ((uint2*)lo)[i] = pl.u;
}

// ================= pointwise / softmax =================
__global__ __launch_bounds__(256)
void rmsnorm_split_kernel(const float* __restrict__ x, const float* __restrict__ w, int cols,
                          bf16* __restrict__ hi, bf16* __restrict__ lo)
{
    __shared__ float sh[256];
    const float* p = x + (long long)blockIdx.x * cols;
    bf16* oh = hi + (long long)blockIdx.x * cols;
    bf16* ol = lo + (long long)blockIdx.x * cols;
    float s = 0.f;
    for (int c = threadIdx.x; c < cols; c += 256) { float v = p[c]; s += v * v; }
    sh[threadIdx.x] = s; __syncthreads();
    for (int o = 128; o > 0; o >>= 1) {
        if (threadIdx.x < o) sh[threadIdx.x] += sh[threadIdx.x + o];
        __syncthreads();
    }
    float rs = rsqrtf(sh[0] / (float)cols + EPSF);
    for (int c = threadIdx.x; c < cols; c += 256) {
        float v = w[c] * p[c] * rs;
        bf16 h = __float2bfloat16(v);
        oh[c] = h;
        ol[c] = __float2bfloat16(v - __bfloat162float(h));
    }
}

__global__ void rope_table_kernel(float* __restrict__ rope)
{
    int idx = blockIdx.x * blockDim.x + threadIdx.x;
    if (idx >= S_ * 32) return;
    int pos = idx >> 5, j = idx & 31;
    double f = pow(10000.0, -(double)j / 32.0);
    double ang = (double)pos * f;
    rope[pos * 64 + j]      = (float)cos(ang);
    rope[pos * 64 + 32 + j] = (float)sin(ang);
}

// kv branch: rmsnorm -> kcat bf16 hi/lo (kv part); roped k_pe replicated into
// kcat192[r][h*192+128..192] for all 16 heads (bf16 hi/lo).
__global__ __launch_bounds__(256)
void kvproc_kernel(const float* __restrict__ kvfull, const float* __restrict__ w,
                   const float* __restrict__ rope,
                   bf16* __restrict__ kh, bf16* __restrict__ kl,
                   bf16* __restrict__ k192h, bf16* __restrict__ k192l)
{
    __shared__ float sh[256];
    const int row = blockIdx.x;
    const float* in = kvfull + (long long)row * KC_;
    bf16* oh = kh + (long long)row * KC_;
    bf16* ol = kl + (long long)row * KC_;
    float s = 0.f;
    for (int c = threadIdx.x; c < KVL_; c += 256) { float v = in[c]; s += v * v; }
    sh[threadIdx.x] = s; __syncthreads();
    for (int o = 128; o > 0; o >>= 1) {
        if (threadIdx.x < o) sh[threadIdx.x] += sh[threadIdx.x + o];
        __syncthreads();
    }
    float rs = rsqrtf(sh[0] / (float)KVL_ + EPSF);
    for (int c = threadIdx.x; c < KVL_; c += 256) {
        float v = w[c] * in[c] * rs;
        bf16 h = __float2bfloat16(v);
        oh[c] = h;
        ol[c] = __float2bfloat16(v - __bfloat162float(h));
    }
    if (threadIdx.x < 32) {
        int j = threadIdx.x;
        int pos = row & (S_ - 1);
        float cs = rope[pos * 64 + j], sn = rope[pos * 64 + 32 + j];
        float x1 = in[KVL_ + j], x2 = in[KVL_ + 32 + j];
        float v1 = x1 * cs - x2 * sn;
        float v2 = x2 * cs + x1 * sn;
        bf16 h1 = __float2bfloat16(v1), h2 = __float2bfloat16(v2);
        bf16 l1 = __float2bfloat16(v1 - __bfloat162float(h1));
        bf16 l2 = __float2bfloat16(v2 - __bfloat162float(h2));
        const long long rb = (long long)row * QDIM_;
#pragma unroll
        for (int h = 0; h < NH_; h++) {
            const long long o = rb + h * QKH_ + NOPE_;
            k192h[o + j] = h1;       k192l[o + j] = l1;
            k192h[o + 32 + j] = h2;  k192l[o + 32 + j] = l2;
        }
    }
}

// q_pe RoPE: overwrite pe columns of qfull hi/lo split in place
__global__ void qpe_rope_kernel(const float* __restrict__ qfull,
                                const float* __restrict__ rope,
                                bf16* __restrict__ qh, bf16* __restrict__ ql)
{
    int idx = blockIdx.x * blockDim.x + threadIdx.x;
    if (idx >= M_ * NH_ * 32) return;
    int j   = idx & 31;
    int h   = (idx >> 5) & (NH_ - 1);
    int row = idx >> 9;
    int pos = row & (S_ - 1);
    float cs = rope[pos * 64 + j], sn = rope[pos * 64 + 32 + j];
    const long long o = (long long)row * QDIM_ + h * QKH_ + NOPE_;
    const float* q = qfull + o;
    float x1 = q[j], x2 = q[32 + j];
    float v1 = x1 * cs - x2 * sn;
    float v2 = x2 * cs + x1 * sn;
    bf16 h1 = __float2bfloat16(v1), h2 = __float2bfloat16(v2);
    qh[o + j] = h1;       ql[o + j] = __float2bfloat16(v1 - __bfloat162float(h1));
    qh[o + 32 + j] = h2;  ql[o + 32 + j] = __float2bfloat16(v2 - __bfloat162float(h2));
}

__global__ __launch_bounds__(256)
void softmax_kernel(const float* __restrict__ scores, const int* __restrict__ mask,
                    f16* __restrict__ probs)
{
    __shared__ float sh[256];
    const int s = blockIdx.x;
    const int z = blockIdx.y;
    const int b = z >> 4;
    const long long ro = ((long long)z * S_ + s) * S_;
    const float* row = scores + ro;
    f16* op = probs + ro;
    const int* mrow = mask + b * S_;
    const int n = s + 1;
    const int tid = threadIdx.x;
    const float scale = 0.07216878364870323f;   // 1/sqrt(192)

    float vals[8];
    float mx = -3.0e38f;
#pragma unroll
    for (int it = 0; it < 8; it++) {
        int t = tid + it * 256;
        float v = -3.0e38f;
        if (t < n) {
            v = row[t] * scale;
            if (mrow[t] == 0) v += MINV;
        }
        vals[it] = v;
        mx = fmaxf(mx, v);
    }
    sh[tid] = mx; __syncthreads();
    for (int o = 128; o > 0; o >>= 1) {
        if (tid < o) sh[tid] = fmaxf(sh[tid], sh[tid + o]);
        __syncthreads();
    }
    mx = sh[0]; __syncthreads();

    float sum = 0.f;
#pragma unroll
    for (int it = 0; it < 8; it++) {
        int t = tid + it * 256;
        if (t < n) { float e = expf(vals[it] - mx); vals[it] = e; sum += e; }
    }
    sh[tid] = sum; __syncthreads();
    for (int o = 128; o > 0; o >>= 1) {
        if (tid < o) sh[tid] += sh[tid + o];
        __syncthreads();
    }
    float inv = 1.f / sh[0];
#pragma unroll
    for (int it = 0; it < 8; it++) {
        int t = tid + it * 256;
        if (t < n) op[t] = __float2half(vals[it] * inv);
    }
    const f16 zero = __float2half(0.f);
    int pad = ((s >> 7) + 1) << 7;
    for (int t = n + tid; t < pad; t += 256) op[t] = zero;
}

// ================= host side =================
static void cvt(const float* src, bf16* hi, bf16* lo, long long n)
{
    long long n4 = n / 4;
    cvt_kernel<<<(unsigned)((n4 + 255) / 256), 256>>>(src, hi, lo, n4);
}

extern "C" void kernel_launch(void* const* d_in, const int* in_sizes, int n_in,
                              void* d_out, int out_size)
{
    (void)in_sizes; (void)n_in; (void)out_size;
    const float* x        = (const float*)d_in[0];
    const int*   mask     = (const int*)  d_in[1];
    const float* wq_a_w   = (const float*)d_in[2];
    const float* wq_a_b   = (const float*)d_in[3];
    const float* q_norm_w = (const float*)d_in[4];
    const float* wq_b_w   = (const float*)d_in[5];
    const float* wq_b_b   = (const float*)d_in[6];
    const float* wkv_a_w  = (const float*)d_in[7];
    const float* wkv_a_b  = (const float*)d_in[8];
    const float* kv_norm_w= (const float*)d_in[9];
    const float* wkv_b_w  = (const float*)d_in[10];
    const float* wo_w     = (const float*)d_in[11];
    const float* wo_b     = (const float*)d_in[12];
    float* out = (float*)d_out;

    float *qa, *qfull, *kvfull, *scores, *rope;
    cudaGetSymbolAddress((void**)&qa,     g_qa);
    cudaGetSymbolAddress((void**)&qfull,  g_qfull);
    cudaGetSymbolAddress((void**)&kvfull, g_kvfull);
    cudaGetSymbolAddress((void**)&scores, g_scores);
    cudaGetSymbolAddress((void**)&rope,   g_rope);

    bf16 *x_h,*x_l,*wqa_h,*wqa_l,*wqb_h,*wqb_l,*wkva_h,*wkva_l,*wkvb_h,*wkvb_l;
    bf16 *wo_h,*wo_l,*qa_h,*qa_l,*qfull_h,*qfull_l;
    bf16 *kcat_h,*kcat_l,*k192_h,*k192_l,*oheads_h,*oheads_l;
    f16 *probs,*vT_h,*vT_l;
    cudaGetSymbolAddress((void**)&x_h, g_x_h);         cudaGetSymbolAddress((void**)&x_l, g_x_l);
    cudaGetSymbolAddress((void**)&wqa_h, g_wqa_h);     cudaGetSymbolAddress((void**)&wqa_l, g_wqa_l);
    cudaGetSymbolAddress((void**)&wqb_h, g_wqb_h);     cudaGetSymbolAddress((void**)&wqb_l, g_wqb_l);
    cudaGetSymbolAddress((void**)&wkva_h, g_wkva_h);   cudaGetSymbolAddress((void**)&wkva_l, g_wkva_l);
    cudaGetSymbolAddress((void**)&wkvb_h, g_wkvb_h);   cudaGetSymbolAddress((void**)&wkvb_l, g_wkvb_l);
    cudaGetSymbolAddress((void**)&wo_h, g_wo_h);       cudaGetSymbolAddress((void**)&wo_l, g_wo_l);
    cudaGetSymbolAddress((void**)&qa_h, g_qa_h);       cudaGetSymbolAddress((void**)&qa_l, g_qa_l);
    cudaGetSymbolAddress((void**)&qfull_h, g_qfull_h); cudaGetSymbolAddress((void**)&qfull_l, g_qfull_l);
    cudaGetSymbolAddress((void**)&kcat_h, g_kcat_h);   cudaGetSymbolAddress((void**)&kcat_l, g_kcat_l);
    cudaGetSymbolAddress((void**)&k192_h, g_kcat192_h); cudaGetSymbolAddress((void**)&k192_l, g_kcat192_l);
    cudaGetSymbolAddress((void**)&oheads_h, g_oheads_h); cudaGetSymbolAddress((void**)&oheads_l, g_oheads_l);
    cudaGetSymbolAddress((void**)&probs, g_probs);
    cudaGetSymbolAddress((void**)&vT_h, g_vT_h);       cudaGetSymbolAddress((void**)&vT_l, g_vT_l);

    cudaFuncSetAttribute(gemm_bf3<false,true ,0>, cudaFuncAttributeMaxDynamicSharedMemorySize, SMEM_GEMM_);
    cudaFuncSetAttribute(gemm_bf3<false,true ,2>, cudaFuncAttributeMaxDynamicSharedMemorySize, SMEM_GEMM_);
    cudaFuncSetAttribute(gemm_bf3<false,false,1>, cudaFuncAttributeMaxDynamicSharedMemorySize, SMEM_GEMM_);
    cudaFuncSetAttribute(gemm_bf3<false,false,3>, cudaFuncAttributeMaxDynamicSharedMemorySize, SMEM_GEMM_);
    cudaFuncSetAttribute(gemm_bf3<true ,false,0>, cudaFuncAttributeMaxDynamicSharedMemorySize, SMEM_GEMM_);
    cudaFuncSetAttribute(gemm_f16x2<true>,        cudaFuncAttributeMaxDynamicSharedMemorySize, SMEM_GEMMF_);

    dim3 thr(256);

    rope_table_kernel<<<(S_ * 32 + 255) / 256, thr>>>(rope);
    cvt(x,       x_h,    x_l,    (long long)M_ * H_);
    cvt(wq_a_w,  wqa_h,  wqa_l,  (long long)QL_ * H_);
    cvt(wkv_a_w, wkva_h, wkva_l, (long long)KC_ * H_);
    cvt(wkv_b_w, wkvb_h, wkvb_l, (long long)NH_ * (NOPE_ + VD_) * KVL_);

    // 1) qa = x @ wq_a^T + b  (fp32)
    gemm_bf3<false,true,0><<<dim3(QL_/128, M_/128, 1), thr, SMEM_GEMM_>>>(
        x_h, x_l, H_, 0, 0, wqa_h, wqa_l, H_, 0, 0,
        qa, nullptr, nullptr, QL_, 0, 0, M_, QL_, H_, 1, wq_a_b);

    cvt(wq_b_w,  wqb_h,  wqb_l,  (long long)QDIM_ * QL_);
    cvt(wo_w,    wo_h,   wo_l,   (long long)H_ * H_);

    // 2) rmsnorm -> qa hi/lo
    rmsnorm_split_kernel<<<M_, thr>>>(qa, q_norm_w, QL_, qa_h, qa_l);
    // 3) qfull = qa @ wq_b^T + b  (fp32 for rope + bf16 hi/lo)
    gemm_bf3<false,true,2><<<dim3(QDIM_/128, M_/128, 1), thr, SMEM_GEMM_>>>(
        qa_h, qa_l, QL_, 0, 0, wqb_h, wqb_l, QL_, 0, 0,
        qfull, qfull_h, qfull_l, QDIM_, 0, 0, M_, QDIM_, QL_, 1, wq_b_b);
    // 4) kvfull = x @ wkv_a^T + b  (fp32)
    gemm_bf3<false,true,0><<<dim3((KC_ + 127)/128, M_/128, 1), thr, SMEM_GEMM_>>>(
        x_h, x_l, H_, 0, 0, wkva_h, wkva_l, H_, 0, 0,
        kvfull, nullptr, nullptr, KC_, 0, 0, M_, KC_, H_, 1, wkv_a_b);
    // 5) kcat hi/lo (kv part) + roped k_pe replicated into kcat192
    kvproc_kernel<<<M_, thr>>>(kvfull, kv_norm_w, rope, kcat_h, kcat_l, k192_h, k192_l);
    // 6) k_proj: kcat192[:, h*192:+128] = kv_norm @ wkvb_k[h]^T  batched 16
    //    M=4096 N=128 K=512
    gemm_bf3<false,false,1><<<dim3(1, M_/128, NH_), thr, SMEM_GEMM_>>>(
        kcat_h, kcat_l, KC_, 0, 0,
        wkvb_h, wkvb_l, KVL_, 0, (long long)(NOPE_ + VD_) * KVL_,
        nullptr, k192_h, k192_l, QDIM_, 0, QKH_,
        M_, NOPE_, KVL_, NH_, nullptr);
    // 7) q_pe rope overwrite in qfull hi/lo
    qpe_rope_kernel<<<(M_ * NH_ * 32 + 255) / 256, thr>>>(qfull, rope, qfull_h, qfull_l);
    // 8) scores = q192 @ k192^T  batched (b,h), K=192, causal skip (fp32)
    gemm_bf3<true,false,0><<<dim3(S_/128, S_/128, B_ * NH_), thr, SMEM_GEMM_>>>(
        qfull_h, qfull_l, QDIM_, (long long)S_ * QDIM_, QKH_,
        k192_h,  k192_l,  QDIM_, (long long)S_ * QDIM_, QKH_,
        scores, nullptr, nullptr, S_, (long long)NH_ * S_ * S_, (long long)S_ * S_,
        S_, S_, QKH_, NH_, nullptr);
    // 9) v_proj (transposed): vT[h][d][r] = wkvb_v[h] @ kv_norm^T  batched 16
    //    M=128 N=4096 K=512, output fp16 hi/lo
    gemm_bf3<false,false,3><<<dim3(M_/128, 1, NH_), thr, SMEM_GEMM_>>>(
        wkvb_h + (long long)NOPE_ * KVL_, wkvb_l + (long long)NOPE_ * KVL_,
        KVL_, 0, (long long)(NOPE_ + VD_) * KVL_,
        kcat_h, kcat_l, KC_, 0, 0,
        nullptr, (bf16*)vT_h, (bf16*)vT_l, M_, 0, (long long)VD_ * M_,
        VD_, M_, KVL_, NH_, nullptr);
    // 10) softmax -> fp16 probs
    softmax_kernel<<<dim3(S_, B_ * NH_), thr>>>(scores, mask, probs);
    // 11) oheads = probs @ vT^T  batched (b,h), causal K bound (fp16 x2)
    //     M=2048 N=128 K=2048
    gemm_f16x2<true><<<dim3(1, S_/128, B_ * NH_), thr, SMEM_GEMMF_>>>(
        probs, S_, (long long)NH_ * S_ * S_, (long long)S_ * S_,
        vT_h, vT_l, M_, 2048, (long long)VD_ * M_,
        oheads_h, oheads_l, H_, (long long)S_ * H_, VD_,
        S_, VD_, S_, NH_);
    // 12) out = oheads @ wo^T + b  (fp32)
    gemm_bf3<false,true,0><<<dim3(H_/128, M_/128, 1), thr, SMEM_GEMM_>>>(
        oheads_h, oheads_l, H_, 0, 0, wo_h, wo_l, H_, 0, 0,
        out, nullptr, nullptr, H_, 0, 0, M_, H_, H_, 1, wo_b);
}

// round 14
// speedup vs baseline: 8.7207x; 1.0960x over previous
#include <cuda_runtime.h>
#include <cuda_bf16.h>
#include <cuda_fp16.h>
#include <math.h>
#include <stdint.h>

// ---------------- problem constants ----------------
constexpr int B_    = 2;
constexpr int S_    = 2048;
constexpr int H_    = 2048;
constexpr int NH_   = 16;
constexpr int QL_   = 1536;
constexpr int KVL_  = 512;
constexpr int NOPE_ = 128;
constexpr int ROPE_ = 64;
constexpr int VD_   = 128;
constexpr int QKH_  = 192;
constexpr int M_    = B_ * S_;      // 4096
constexpr int QDIM_ = NH_ * QKH_;   // 3072
constexpr int KC_   = KVL_ + ROPE_; // 576
constexpr float EPSF = 1e-6f;
constexpr float MINV = -1e15f;

typedef __nv_bfloat16 bf16;
typedef __half f16;

// ---------------- fp32 scratch ----------------
__device__ float g_qa    [M_ * QL_];
__device__ float g_qfull [M_ * QDIM_];
__device__ float g_kvfull[M_ * KC_];
__device__ float g_scores[(size_t)B_ * NH_ * S_ * S_];
__device__ float g_rope  [S_ * ROPE_];

// ---------------- bf16 hi/lo scratch ----------------
__device__ bf16 g_x_h[M_ * H_],            g_x_l[M_ * H_];
__device__ bf16 g_wqa_h[QL_ * H_],         g_wqa_l[QL_ * H_];
__device__ bf16 g_wkva_h[KC_ * H_],        g_wkva_l[KC_ * H_];
__device__ bf16 g_wkvb_h[NH_ * (NOPE_ + VD_) * KVL_], g_wkvb_l[NH_ * (NOPE_ + VD_) * KVL_];
__device__ bf16 g_qfull_h[M_ * QDIM_],     g_qfull_l[M_ * QDIM_];
__device__ bf16 g_kcat_h[M_ * KC_],        g_kcat_l[M_ * KC_];
__device__ bf16 g_kcat192_h[M_ * QDIM_],   g_kcat192_l[M_ * QDIM_];   // [r][h*192+d]
// fp16 scratch
__device__ f16 g_qa_f[M_ * QL_];                                      // rmsnorm out (single)
__device__ f16 g_wqb_fh[QDIM_ * QL_],      g_wqb_fl[QDIM_ * QL_];
__device__ f16 g_wo_fh[H_ * H_],           g_wo_fl[H_ * H_];
__device__ f16 g_oheads_f[M_ * H_];                                   // attn out (single)
__device__ f16 g_probs[(size_t)B_ * NH_ * S_ * S_];
__device__ f16 g_vT_h[NH_ * VD_ * M_],     g_vT_l[NH_ * VD_ * M_];    // [h][d][b*S+t]

// ---------------- PTX helpers ----------------
__device__ __forceinline__ void mma_bf16(float* d, const uint32_t* a, uint32_t b0, uint32_t b1) {
    asm volatile(
        "mma.sync.aligned.m16n8k16.row.col.f32.bf16.bf16.f32 "
        "{%0,%1,%2,%3}, {%4,%5,%6,%7}, {%8,%9}, {%0,%1,%2,%3};"
        : "+f"(d[0]), "+f"(d[1]), "+f"(d[2]), "+f"(d[3])
        : "r"(a[0]), "r"(a[1]), "r"(a[2]), "r"(a[3]), "r"(b0), "r"(b1));
}
__device__ __forceinline__ void mma_f16(float* d, const uint32_t* a, uint32_t b0, uint32_t b1) {
    asm volatile(
        "mma.sync.aligned.m16n8k16.row.col.f32.f16.f16.f32 "
        "{%0,%1,%2,%3}, {%4,%5,%6,%7}, {%8,%9}, {%0,%1,%2,%3};"
        : "+f"(d[0]), "+f"(d[1]), "+f"(d[2]), "+f"(d[3])
        : "r"(a[0]), "r"(a[1]), "r"(a[2]), "r"(a[3]), "r"(b0), "r"(b1));
}
__device__ __forceinline__ void ldsm4(uint32_t* r, uint32_t addr) {
    asm volatile("ldmatrix.sync.aligned.m8n8.x4.shared.b16 {%0,%1,%2,%3}, [%4];"
                 : "=r"(r[0]), "=r"(r[1]), "=r"(r[2]), "=r"(r[3]) : "r"(addr));
}
__device__ __forceinline__ void cp16(uint32_t s, const void* g, int sz) {
    asm volatile("cp.async.cg.shared.global [%0], [%1], 16, %2;"
                 :: "r"(s), "l"(g), "r"(sz) : "memory");
}
__device__ __forceinline__ void cpcommit() { asm volatile("cp.async.commit_group;" ::: "memory"); }
__device__ __forceinline__ void cpwait0()  { asm volatile("cp.async.wait_group 0;" ::: "memory"); }
__device__ __forceinline__ void cpwait1()  { asm volatile("cp.async.wait_group 1;" ::: "memory"); }
__device__ __forceinline__ void cpwait2()  { asm volatile("cp.async.wait_group 2;" ::: "memory"); }

__device__ __forceinline__ uint32_t pack_bf16(float a, float b) {
    union { bf16 v[2]; uint32_t u; } p;
    p.v[0] = __float2bfloat16(a);
    p.v[1] = __float2bfloat16(b);
    return p.u;
}
__device__ __forceinline__ uint32_t pack_f16(float a, float b) {
    union { f16 v[2]; uint32_t u; } p;
    p.v[0] = __float2half(a);
    p.v[1] = __float2half(b);
    return p.u;
}

// ================= bf16x3 tensor-core GEMM =================
// C[M,N] = A[M,K] @ B[N,K]^T (+bias), A/B bf16 hi/lo pairs.
// OUT: 0 = fp32, 1 = bf16 hi/lo, 3 = fp16 hi/lo.
constexpr int PADW_ = 12;
constexpr int TILE_W_ = 128 * PADW_;
constexpr int STG_W_ = 4 * TILE_W_;
constexpr int SMEM_GEMM_ = 3 * STG_W_ * 4;   // 73728 bytes
constexpr int STGF_W_ = 3 * TILE_W_;
constexpr int SMEM_GEMMF_ = 3 * STGF_W_ * 4; // 55296 bytes

template<bool CSKIP, bool BIAS, int OUT>
__global__ __launch_bounds__(256, 2)
void gemm_bf3(const bf16* __restrict__ Ah, const bf16* __restrict__ Al,
              int lda, long long sAo, long long sAi,
              const bf16* __restrict__ Bh, const bf16* __restrict__ Bl,
              int ldb, long long sBo, long long sBi,
              float* __restrict__ C, bf16* __restrict__ Ch, bf16* __restrict__ Cl,
              int ldc, long long sCo, long long sCi,
              int M, int N, int K, int inner,
              const float* __restrict__ bias)
{
    const int m0 = blockIdx.y * 128;
    const int n0 = blockIdx.x * 128;
    if (CSKIP && n0 >= m0 + 128) return;

    const int z = blockIdx.z;
    const int zo = z / inner, zi = z - zo * inner;
    const long long aoff = zo * sAo + zi * sAi;
    const long long boff = zo * sBo + zi * sBi;
    Ah += aoff; Al += aoff;
    Bh += boff; Bl += boff;
    const long long coff = zo * sCo + zi * sCi;

    extern __shared__ uint32_t sm[];
    const uint32_t smw = (uint32_t)__cvta_generic_to_shared(sm);

    const int tid = threadIdx.x;
    const int wid = tid >> 5, lid = tid & 31;
    const int wm = (wid >> 2) * 64;
    const int wn = (wid & 3) * 32;
    const int gr = lid >> 2;
    const int gc = lid & 3;

    const int lr8 = lid & 7;
    const int mat = lid >> 3;
    const int a_row = (mat & 1) * 8 + lr8;
    const int a_kof = (mat >> 1) * 4;
    const int b_row = (mat >> 1) * 8 + lr8;
    const int b_kof = (mat & 1) * 4;

    const int nkt = K >> 4;

    float acc[4][4][4];
#pragma unroll
    for (int i = 0; i < 4; i++)
#pragma unroll
        for (int j = 0; j < 4; j++)
#pragma unroll
            for (int q = 0; q < 4; q++) acc[i][j][q] = 0.f;

    const int lrow = tid >> 1;
    const int lseg = tid & 1;

    auto issue = [&](int kt) {
        const int s = kt % 3;
        uint32_t* st = sm + s * STG_W_;
        const int k0 = kt << 4;
        const uint32_t dw = (uint32_t)__cvta_generic_to_shared(st + lrow * PADW_ + lseg * 4);
        const int ar = m0 + lrow, br = n0 + lrow;
        const int asz = ar < M ? 16 : 0, bsz = br < N ? 16 : 0;
        const long long ai = (long long)ar * lda + k0 + lseg * 8;
        const long long bi = (long long)br * ldb + k0 + lseg * 8;
        cp16(dw,                   Ah + ai, asz);
        cp16(dw + TILE_W_ * 4,     Al + ai, asz);
        cp16(dw + 2 * TILE_W_ * 4, Bh + bi, bsz);
        cp16(dw + 3 * TILE_W_ * 4, Bl + bi, bsz);
        cpcommit();
    };

    const int pre = nkt < 2 ? nkt : 2;
    for (int i = 0; i < pre; i++) issue(i);

    for (int kt = 0; kt < nkt; kt++) {
        if (kt + 2 < nkt) { issue(kt + 2); cpwait2(); }
        else if (kt + 1 < nkt) cpwait1();
        else cpwait0();
        __syncthreads();

        const int s = kt % 3;
        const uint32_t stb = smw + s * STG_W_ * 4;

        uint32_t afh[4][4], afl[4][4];
#pragma unroll
        for (int i = 0; i < 4; i++) {
            const uint32_t aaddr = stb + (uint32_t)(((wm + i * 16 + a_row) * PADW_ + a_kof) * 4);
            ldsm4(afh[i], aaddr);
            ldsm4(afl[i], aaddr + TILE_W_ * 4);
        }
#pragma unroll
        for (int p = 0; p < 2; p++) {
            const uint32_t baddr = stb + 2 * TILE_W_ * 4 +
                                   (uint32_t)(((wn + p * 16 + b_row) * PADW_ + b_kof) * 4);
            uint32_t bfh[4], bfl[4];
            ldsm4(bfh, baddr);
            ldsm4(bfl, baddr + TILE_W_ * 4);
#pragma unroll
            for (int j2 = 0; j2 < 2; j2++) {
                const int j = p * 2 + j2;
                const uint32_t bh0 = bfh[j2 * 2], bh1 = bfh[j2 * 2 + 1];
                const uint32_t bl0 = bfl[j2 * 2], bl1 = bfl[j2 * 2 + 1];
#pragma unroll
                for (int i = 0; i < 4; i++) {
                    mma_bf16(acc[i][j], afh[i], bh0, bh1);
                    mma_bf16(acc[i][j], afh[i], bl0, bl1);
                    mma_bf16(acc[i][j], afl[i], bh0, bh1);
                }
            }
        }
        __syncthreads();
    }

    // epilogue
    f16* Fh = (f16*)Ch;
    f16* Fl = (f16*)Cl;
#pragma unroll
    for (int i = 0; i < 4; i++) {
        const int r0 = m0 + wm + i * 16 + gr;
        const int r1 = r0 + 8;
#pragma unroll
        for (int j = 0; j < 4; j++) {
            const int cc = n0 + wn + j * 8 + gc * 2;
            if (cc >= N) continue;
            float b0 = 0.f, b1 = 0.f;
            if (BIAS) { b0 = bias[cc]; b1 = bias[cc + 1]; }
            float v00 = acc[i][j][0] + b0, v01 = acc[i][j][1] + b1;
            float v10 = acc[i][j][2] + b0, v11 = acc[i][j][3] + b1;
            if (r0 < M) {
                const long long o = coff + (long long)r0 * ldc + cc;
                if (OUT == 0) *(float2*)(C + o) = make_float2(v00, v01);
                if (OUT == 1) {
                    float h0 = __bfloat162float(__float2bfloat16(v00));
                    float h1 = __bfloat162float(__float2bfloat16(v01));
                    *(uint32_t*)(Ch + o) = pack_bf16(v00, v01);
                    *(uint32_t*)(Cl + o) = pack_bf16(v00 - h0, v01 - h1);
                }
                if (OUT == 3) {
                    float h0 = __half2float(__float2half(v00));
                    float h1 = __half2float(__float2half(v01));
                    *(uint32_t*)(Fh + o) = pack_f16(v00, v01);
                    *(uint32_t*)(Fl + o) = pack_f16(v00 - h0, v01 - h1);
                }
            }
            if (r1 < M) {
                const long long o = coff + (long long)r1 * ldc + cc;
                if (OUT == 0) *(float2*)(C + o) = make_float2(v10, v11);
                if (OUT == 1) {
                    float h0 = __bfloat162float(__float2bfloat16(v10));
                    float h1 = __bfloat162float(__float2bfloat16(v11));
                    *(uint32_t*)(Ch + o) = pack_bf16(v10, v11);
                    *(uint32_t*)(Cl + o) = pack_bf16(v10 - h0, v11 - h1);
                }
                if (OUT == 3) {
                    float h0 = __half2float(__float2half(v10));
                    float h1 = __half2float(__float2half(v11));
                    *(uint32_t*)(Fh + o) = pack_f16(v10, v11);
                    *(uint32_t*)(Fl + o) = pack_f16(v10 - h0, v11 - h1);
                }
            }
        }
    }
}

// ================= fp16 two-term GEMM =================
// A single fp16, B fp16 hi/lo pair. CK: Kend = m0+128.
// OUT: 0 = fp32 (+bias), 2 = fp32 + bf16 hi/lo (+bias), 4 = fp16 single.
template<bool CK, bool BIAS, int OUT>
__global__ __launch_bounds__(256, 2)
void gemm_f16x2(const f16* __restrict__ A, int lda, long long sAo, long long sAi,
                const f16* __restrict__ Bh, const f16* __restrict__ Bl,
                int ldb, long long sBo, long long sBi,
                float* __restrict__ C, bf16* __restrict__ Ch, bf16* __restrict__ Cl,
                int ldc, long long sCo, long long sCi,
                int M, int N, int K, int inner,
                const float* __restrict__ bias)
{
    const int m0 = blockIdx.y * 128;
    const int n0 = blockIdx.x * 128;

    const int z = blockIdx.z;
    const int zo = z / inner, zi = z - zo * inner;
    A  += zo * sAo + zi * sAi;
    const long long boff = zo * sBo + zi * sBi;
    Bh += boff; Bl += boff;
    const long long coff = zo * sCo + zi * sCi;

    extern __shared__ uint32_t sm[];
    const uint32_t smw = (uint32_t)__cvta_generic_to_shared(sm);

    const int tid = threadIdx.x;
    const int wid = tid >> 5, lid = tid & 31;
    const int wm = (wid >> 2) * 64;
    const int wn = (wid & 3) * 32;
    const int gr = lid >> 2;
    const int gc = lid & 3;

    const int lr8 = lid & 7;
    const int mat = lid >> 3;
    const int a_row = (mat & 1) * 8 + lr8;
    const int a_kof = (mat >> 1) * 4;
    const int b_row = (mat >> 1) * 8 + lr8;
    const int b_kof = (mat & 1) * 4;

    int Kend = K;
    if (CK) { int ke = m0 + 128; Kend = ke < K ? ke : K; }
    const int nkt = Kend >> 4;

    float acc[4][4][4];
#pragma unroll
    for (int i = 0; i < 4; i++)
#pragma unroll
        for (int j = 0; j < 4; j++)
#pragma unroll
            for (int q = 0; q < 4; q++) acc[i][j][q] = 0.f;

    const int lrow = tid >> 1;
    const int lseg = tid & 1;

    auto issue = [&](int kt) {
        const int s = kt % 3;
        uint32_t* st = sm + s * STGF_W_;
        const int k0 = kt << 4;
        const uint32_t dw = (uint32_t)__cvta_generic_to_shared(st + lrow * PADW_ + lseg * 4);
        const int ar = m0 + lrow, br = n0 + lrow;
        const int asz = ar < M ? 16 : 0, bsz = br < N ? 16 : 0;
        const long long ai = (long long)ar * lda + k0 + lseg * 8;
        const long long bi = (long long)br * ldb + k0 + lseg * 8;
        cp16(dw,                   A + ai,  asz);
        cp16(dw + TILE_W_ * 4,     Bh + bi, bsz);
        cp16(dw + 2 * TILE_W_ * 4, Bl + bi, bsz);
        cpcommit();
    };

    const int pre = nkt < 2 ? nkt : 2;
    for (int i = 0; i < pre; i++) issue(i);

    for (int kt = 0; kt < nkt; kt++) {
        if (kt + 2 < nkt) { issue(kt + 2); cpwait2(); }
        else if (kt + 1 < nkt) cpwait1();
        else cpwait0();
        __syncthreads();

        const int s = kt % 3;
        const uint32_t stb = smw + s * STGF_W_ * 4;

        uint32_t af[4][4];
#pragma unroll
        for (int i = 0; i < 4; i++) {
            const uint32_t aaddr = stb + (uint32_t)(((wm + i * 16 + a_row) * PADW_ + a_kof) * 4);
            ldsm4(af[i], aaddr);
        }
#pragma unroll
        for (int p = 0; p < 2; p++) {
            const uint32_t baddr = stb + TILE_W_ * 4 +
                                   (uint32_t)(((wn + p * 16 + b_row) * PADW_ + b_kof) * 4);
            uint32_t bfh[4], bfl[4];
            ldsm4(bfh, baddr);
            ldsm4(bfl, baddr + TILE_W_ * 4);
#pragma unroll
            for (int j2 = 0; j2 < 2; j2++) {
                const int j = p * 2 + j2;
                const uint32_t bh0 = bfh[j2 * 2], bh1 = bfh[j2 * 2 + 1];
                const uint32_t bl0 = bfl[j2 * 2], bl1 = bfl[j2 * 2 + 1];
#pragma unroll
                for (int i = 0; i < 4; i++) {
                    mma_f16(acc[i][j], af[i], bh0, bh1);
                    mma_f16(acc[i][j], af[i], bl0, bl1);
                }
            }
        }
        __syncthreads();
    }

    f16* Fh = (f16*)Ch;
#pragma unroll
    for (int i = 0; i < 4; i++) {
        const int r0 = m0 + wm + i * 16 + gr;
        const int r1 = r0 + 8;
#pragma unroll
        for (int j = 0; j < 4; j++) {
            const int cc = n0 + wn + j * 8 + gc * 2;
            if (cc >= N) continue;
            float b0 = 0.f, b1 = 0.f;
            if (BIAS) { b0 = bias[cc]; b1 = bias[cc + 1]; }
            float v00 = acc[i][j][0] + b0, v01 = acc[i][j][1] + b1;
            float v10 = acc[i][j][2] + b0, v11 = acc[i][j][3] + b1;
            if (r0 < M) {
                const long long o = coff + (long long)r0 * ldc + cc;
                if (OUT == 0 || OUT == 2) *(float2*)(C + o) = make_float2(v00, v01);
                if (OUT == 2) {
                    float h0 = __bfloat162float(__float2bfloat16(v00));
                    float h1 = __bfloat162float(__float2bfloat16(v01));
                    *(uint32_t*)(Ch + o) = pack_bf16(v00, v01);
                    *(uint32_t*)(Cl + o) = pack_bf16(v00 - h0, v01 - h1);
                }
                if (OUT == 4) *(uint32_t*)(Fh + o) = pack_f16(v00, v01);
            }
            if (r1 < M) {
                const long long o = coff + (long long)r1 * ldc + cc;
                if (OUT == 0 || OUT == 2) *(float2*)(C + o) = make_float2(v10, v11);
                if (OUT == 2) {
                    float h0 = __bfloat162float(__float2bfloat16(v10));
                    float h1 = __bfloat162float(__float2bfloat16(v11));
                    *(uint32_t*)(Ch + o) = pack_bf16(v10, v11);
                    *(uint32_t*)(Cl + o) = pack_bf16(v10 - h0, v11 - h1);
                }
                if (OUT == 4) *(uint32_t*)(Fh + o) = pack_f16(v10, v11);
            }
        }
    }
}

// ---------------- fp32 -> bf16 hi/lo split ----------------
__global__ __launch_bounds__(256)
void cvt_kernel(const float* __restrict__ src, bf16* __restrict__ hi, bf16* __restrict__ lo,
                long long n4)
{
    long long i = (long long)blockIdx.x * blockDim.x + threadIdx.x;
    if (i >= n4) return;
    float4 v = ((const float4*)src)[i];
    union { bf16 b[4]; uint2 u; } ph, pl;
    float f[4] = { v.x, v.y, v.z, v.w };
#pragma unroll
    for (int q = 0; q < 4; q++) {
        bf16 h = __float2bfloat16(f[q]);
        ph.b[q] = h;
        pl.b[q] = __float2bfloat16(f[q] - __bfloat162float(h));
    }
    ((uint2*)hi)[i] = ph.u;
    ((uint2*)lo)[i] = pl.u;
}

// ---------------- fp32 -> fp16 hi/lo split ----------------
__global__ __launch_bounds__(256)
void cvt_f16_kernel(const float* __restrict__ src, f16* __restrict__ hi, f16* __restrict__ lo,
                    long long n4)
{
    long long i = (long long)blockIdx.x * blockDim.x + threadIdx.x;
    if (i >= n4) return;
    float4 v = ((const float4*)src)[i];
    union { f16 b[4]; uint2 u; } ph, pl;
    float f[4] = { v.x, v.y, v.z, v.w };
#pragma unroll
    for (int q = 0; q < 4; q++) {
        f16 h = __float2half(f[q]);
        ph.b[q] = h;
        pl.b[q] = __float2half(f[q] - __half2float(h));
    }
    ((uint2*)hi)[i] = ph.u;
    ((uint2*)lo)[i] = pl.u;
}

// ================= pointwise / softmax =================
// rmsnorm -> fp16 single
__global__ __launch_bounds__(256)
void rmsnorm_f16_kernel(const float* __restrict__ x, const float* __restrict__ w, int cols,
                        f16* __restrict__ outp)
{
    __shared__ float sh[256];
    const float* p = x + (long long)blockIdx.x * cols;
    f16* o = outp + (long long)blockIdx.x * cols;
    float s = 0.f;
    for (int c = threadIdx.x; c < cols; c += 256) { float v = p[c]; s += v * v; }
    sh[threadIdx.x] = s; __syncthreads();
    for (int off = 128; off > 0; off >>= 1) {
        if (threadIdx.x < off) sh[threadIdx.x] += sh[threadIdx.x + off];
        __syncthreads();
    }
    float rs = rsqrtf(sh[0] / (float)cols + EPSF);
    for (int c = threadIdx.x; c < cols; c += 256)
        o[c] = __float2half(w[c] * p[c] * rs);
}

__global__ void rope_table_kernel(float* __restrict__ rope)
{
    int idx = blockIdx.x * blockDim.x + threadIdx.x;
    if (idx >= S_ * 32) return;
    int pos = idx >> 5, j = idx & 31;
    double f = pow(10000.0, -(double)j / 32.0);
    double ang = (double)pos * f;
    rope[pos * 64 + j]      = (float)cos(ang);
    rope[pos * 64 + 32 + j] = (float)sin(ang);
}

// kv branch: rmsnorm -> kcat bf16 hi/lo; roped k_pe replicated into kcat192
__global__ __launch_bounds__(256)
void kvproc_kernel(const float* __restrict__ kvfull, const float* __restrict__ w,
                   const float* __restrict__ rope,
                   bf16* __restrict__ kh, bf16* __restrict__ kl,
                   bf16* __restrict__ k192h, bf16* __restrict__ k192l)
{
    __shared__ float sh[256];
    const int row = blockIdx.x;
    const float* in = kvfull + (long long)row * KC_;
    bf16* oh = kh + (long long)row * KC_;
    bf16* ol = kl + (long long)row * KC_;
    float s = 0.f;
    for (int c = threadIdx.x; c < KVL_; c += 256) { float v = in[c]; s += v * v; }
    sh[threadIdx.x] = s; __syncthreads();
    for (int o = 128; o > 0; o >>= 1) {
        if (threadIdx.x < o) sh[threadIdx.x] += sh[threadIdx.x + o];
        __syncthreads();
    }
    float rs = rsqrtf(sh[0] / (float)KVL_ + EPSF);
    for (int c = threadIdx.x; c < KVL_; c += 256) {
        float v = w[c] * in[c] * rs;
        bf16 h = __float2bfloat16(v);
        oh[c] = h;
        ol[c] = __float2bfloat16(v - __bfloat162float(h));
    }
    if (threadIdx.x < 32) {
        int j = threadIdx.x;
        int pos = row & (S_ - 1);
        float cs = rope[pos * 64 + j], sn = rope[pos * 64 + 32 + j];
        float x1 = in[KVL_ + j], x2 = in[KVL_ + 32 + j];
        float v1 = x1 * cs - x2 * sn;
        float v2 = x2 * cs + x1 * sn;
        bf16 h1 = __float2bfloat16(v1), h2 = __float2bfloat16(v2);
        bf16 l1 = __float2bfloat16(v1 - __bfloat162float(h1));
        bf16 l2 = __float2bfloat16(v2 - __bfloat162float(h2));
        const long long rb = (long long)row * QDIM_;
#pragma unroll
        for (int h = 0; h < NH_; h++) {
            const long long o = rb + h * QKH_ + NOPE_;
            k192h[o + j] = h1;       k192l[o + j] = l1;
            k192h[o + 32 + j] = h2;  k192l[o + 32 + j] = l2;
        }
    }
}

// q_pe RoPE: overwrite pe columns of qfull hi/lo split in place
__global__ void qpe_rope_kernel(const float* __restrict__ qfull,
                                const float* __restrict__ rope,
                                bf16* __restrict__ qh, bf16* __restrict__ ql)
{
    int idx = blockIdx.x * blockDim.x + threadIdx.x;
    if (idx >= M_ * NH_ * 32) return;
    int j   = idx & 31;
    int h   = (idx >> 5) & (NH_ - 1);
    int row = idx >> 9;
    int pos = row & (S_ - 1);
    float cs = rope[pos * 64 + j], sn = rope[pos * 64 + 32 + j];
    const long long o = (long long)row * QDIM_ + h * QKH_ + NOPE_;
    const float* q = qfull + o;
    float x1 = q[j], x2 = q[32 + j];
    float v1 = x1 * cs - x2 * sn;
    float v2 = x2 * cs + x1 * sn;
    bf16 h1 = __float2bfloat16(v1), h2 = __float2bfloat16(v2);
    qh[o + j] = h1;       ql[o + j] = __float2bfloat16(v1 - __bfloat162float(h1));
    qh[o + 32 + j] = h2;  ql[o + 32 + j] = __float2bfloat16(v2 - __bfloat162float(h2));
}

__global__ __launch_bounds__(256)
void softmax_kernel(const float* __restrict__ scores, const int* __restrict__ mask,
                    f16* __restrict__ probs)
{
    __shared__ float sh[256];
    const int s = blockIdx.x;
    const int z = blockIdx.y;
    const int b = z >> 4;
    const long long ro = ((long long)z * S_ + s) * S_;
    const float* row = scores + ro;
    f16* op = probs + ro;
    const int* mrow = mask + b * S_;
    const int n = s + 1;
    const int tid = threadIdx.x;
    const float scale = 0.07216878364870323f;   // 1/sqrt(192)

    float vals[8];
    float mx = -3.0e38f;
#pragma unroll
    for (int it = 0; it < 8; it++) {
        int t = tid + it * 256;
        float v = -3.0e38f;
        if (t < n) {
            v = row[t] * scale;
            if (mrow[t] == 0) v += MINV;
        }
        vals[it] = v;
        mx = fmaxf(mx, v);
    }
    sh[tid] = mx; __syncthreads();
    for (int o = 128; o > 0; o >>= 1) {
        if (tid < o) sh[tid] = fmaxf(sh[tid], sh[tid + o]);
        __syncthreads();
    }
    mx = sh[0]; __syncthreads();

    float sum = 0.f;
#pragma unroll
    for (int it = 0; it < 8; it++) {
        int t = tid + it * 256;
        if (t < n) { float e = expf(vals[it] - mx); vals[it] = e; sum += e; }
    }
    sh[tid] = sum; __syncthreads();
    for (int o = 128; o > 0; o >>= 1) {
        if (tid < o) sh[tid] += sh[tid + o];
        __syncthreads();
    }
    float inv = 1.f / sh[0];
#pragma unroll
    for (int it = 0; it < 8; it++) {
        int t = tid + it * 256;
        if (t < n) op[t] = __float2half(vals[it] * inv);
    }
    const f16 zero = __float2half(0.f);
    int pad = ((s >> 7) + 1) << 7;
    for (int t = n + tid; t < pad; t += 256) op[t] = zero;
}

// ================= host side =================
static void cvt(const float* src, bf16* hi, bf16* lo, long long n)
{
    long long n4 = n / 4;
    cvt_kernel<<<(unsigned)((n4 + 255) / 256), 256>>>(src, hi, lo, n4);
}
static void cvtf(const float* src, f16* hi, f16* lo, long long n)
{
    long long n4 = n / 4;
    cvt_f16_kernel<<<(unsigned)((n4 + 255) / 256), 256>>>(src, hi, lo, n4);
}

extern "C" void kernel_launch(void* const* d_in, const int* in_sizes, int n_in,
                              void* d_out, int out_size)
{
    (void)in_sizes; (void)n_in; (void)out_size;
    const float* x        = (const float*)d_in[0];
    const int*   mask     = (const int*)  d_in[1];
    const float* wq_a_w   = (const float*)d_in[2];
    const float* wq_a_b   = (const float*)d_in[3];
    const float* q_norm_w = (const float*)d_in[4];
    const float* wq_b_w   = (const float*)d_in[5];
    const float* wq_b_b   = (const float*)d_in[6];
    const float* wkv_a_w  = (const float*)d_in[7];
    const float* wkv_a_b  = (const float*)d_in[8];
    const float* kv_norm_w= (const float*)d_in[9];
    const float* wkv_b_w  = (const float*)d_in[10];
    const float* wo_w     = (const float*)d_in[11];
    const float* wo_b     = (const float*)d_in[12];
    float* out = (float*)d_out;

    float *qa, *qfull, *kvfull, *scores, *rope;
    cudaGetSymbolAddress((void**)&qa,     g_qa);
    cudaGetSymbolAddress((void**)&qfull,  g_qfull);
    cudaGetSymbolAddress((void**)&kvfull, g_kvfull);
    cudaGetSymbolAddress((void**)&scores, g_scores);
    cudaGetSymbolAddress((void**)&rope,   g_rope);

    bf16 *x_h,*x_l,*wqa_h,*wqa_l,*wkva_h,*wkva_l,*wkvb_h,*wkvb_l;
    bf16 *qfull_h,*qfull_l,*kcat_h,*kcat_l,*k192_h,*k192_l;
    f16 *qa_f,*wqb_fh,*wqb_fl,*wo_fh,*wo_fl,*oheads_f,*probs,*vT_h,*vT_l;
    cudaGetSymbolAddress((void**)&x_h, g_x_h);         cudaGetSymbolAddress((void**)&x_l, g_x_l);
    cudaGetSymbolAddress((void**)&wqa_h, g_wqa_h);     cudaGetSymbolAddress((void**)&wqa_l, g_wqa_l);
    cudaGetSymbolAddress((void**)&wkva_h, g_wkva_h);   cudaGetSymbolAddress((void**)&wkva_l, g_wkva_l);
    cudaGetSymbolAddress((void**)&wkvb_h, g_wkvb_h);   cudaGetSymbolAddress((void**)&wkvb_l, g_wkvb_l);
    cudaGetSymbolAddress((void**)&qfull_h, g_qfull_h); cudaGetSymbolAddress((void**)&qfull_l, g_qfull_l);
    cudaGetSymbolAddress((void**)&kcat_h, g_kcat_h);   cudaGetSymbolAddress((void**)&kcat_l, g_kcat_l);
    cudaGetSymbolAddress((void**)&k192_h, g_kcat192_h); cudaGetSymbolAddress((void**)&k192_l, g_kcat192_l);
    cudaGetSymbolAddress((void**)&qa_f, g_qa_f);
    cudaGetSymbolAddress((void**)&wqb_fh, g_wqb_fh);   cudaGetSymbolAddress((void**)&wqb_fl, g_wqb_fl);
    cudaGetSymbolAddress((void**)&wo_fh, g_wo_fh);     cudaGetSymbolAddress((void**)&wo_fl, g_wo_fl);
    cudaGetSymbolAddress((void**)&oheads_f, g_oheads_f);
    cudaGetSymbolAddress((void**)&probs, g_probs);
    cudaGetSymbolAddress((void**)&vT_h, g_vT_h);       cudaGetSymbolAddress((void**)&vT_l, g_vT_l);

    cudaFuncSetAttribute(gemm_bf3<false,true ,0>, cudaFuncAttributeMaxDynamicSharedMemorySize, SMEM_GEMM_);
    cudaFuncSetAttribute(gemm_bf3<false,false,1>, cudaFuncAttributeMaxDynamicSharedMemorySize, SMEM_GEMM_);
    cudaFuncSetAttribute(gemm_bf3<false,false,3>, cudaFuncAttributeMaxDynamicSharedMemorySize, SMEM_GEMM_);
    cudaFuncSetAttribute(gemm_bf3<true ,false,0>, cudaFuncAttributeMaxDynamicSharedMemorySize, SMEM_GEMM_);
    cudaFuncSetAttribute(gemm_f16x2<false,true ,2>, cudaFuncAttributeMaxDynamicSharedMemorySize, SMEM_GEMMF_);
    cudaFuncSetAttribute(gemm_f16x2<true ,false,4>, cudaFuncAttributeMaxDynamicSharedMemorySize, SMEM_GEMMF_);
    cudaFuncSetAttribute(gemm_f16x2<false,true ,0>, cudaFuncAttributeMaxDynamicSharedMemorySize, SMEM_GEMMF_);

    dim3 thr(256);

    rope_table_kernel<<<(S_ * 32 + 255) / 256, thr>>>(rope);
    cvt(x,       x_h,    x_l,    (long long)M_ * H_);
    cvt(wq_a_w,  wqa_h,  wqa_l,  (long long)QL_ * H_);
    cvt(wkv_a_w, wkva_h, wkva_l, (long long)KC_ * H_);
    cvt(wkv_b_w, wkvb_h, wkvb_l, (long long)NH_ * (NOPE_ + VD_) * KVL_);

    // 1) qa = x @ wq_a^T + b  (fp32, bf16x3)
    gemm_bf3<false,true,0><<<dim3(QL_/128, M_/128, 1), thr, SMEM_GEMM_>>>(
        x_h, x_l, H_, 0, 0, wqa_h, wqa_l, H_, 0, 0,
        qa, nullptr, nullptr, QL_, 0, 0, M_, QL_, H_, 1, wq_a_b);

    cvtf(wq_b_w, wqb_fh, wqb_fl, (long long)QDIM_ * QL_);
    cvtf(wo_w,   wo_fh,  wo_fl,  (long long)H_ * H_);

    // 2) rmsnorm -> qa fp16 single
    rmsnorm_f16_kernel<<<M_, thr>>>(qa, q_norm_w, QL_, qa_f);
    // 3) qfull = qa @ wq_b^T + b  (fp16 two-term; out fp32 + bf16 pairs)
    gemm_f16x2<false,true,2><<<dim3(QDIM_/128, M_/128, 1), thr, SMEM_GEMMF_>>>(
        qa_f, QL_, 0, 0, wqb_fh, wqb_fl, QL_, 0, 0,
        qfull, qfull_h, qfull_l, QDIM_, 0, 0, M_, QDIM_, QL_, 1, wq_b_b);
    // 4) kvfull = x @ wkv_a^T + b  (fp32, bf16x3)
    gemm_bf3<false,true,0><<<dim3((KC_ + 127)/128, M_/128, 1), thr, SMEM_GEMM_>>>(
        x_h, x_l, H_, 0, 0, wkva_h, wkva_l, H_, 0, 0,
        kvfull, nullptr, nullptr, KC_, 0, 0, M_, KC_, H_, 1, wkv_a_b);
    // 5) kcat hi/lo + roped k_pe replicated into kcat192
    kvproc_kernel<<<M_, thr>>>(kvfull, kv_norm_w, rope, kcat_h, kcat_l, k192_h, k192_l);
    // 6) k_proj: kcat192[:, h*192:+128] = kv_norm @ wkvb_k[h]^T  batched 16
    gemm_bf3<false,false,1><<<dim3(1, M_/128, NH_), thr, SMEM_GEMM_>>>(
        kcat_h, kcat_l, KC_, 0, 0,
        wkvb_h, wkvb_l, KVL_, 0, (long long)(NOPE_ + VD_) * KVL_,
        nullptr, k192_h, k192_l, QDIM_, 0, QKH_,
        M_, NOPE_, KVL_, NH_, nullptr);
    // 7) q_pe rope overwrite in qfull hi/lo
    qpe_rope_kernel<<<(M_ * NH_ * 32 + 255) / 256, thr>>>(qfull, rope, qfull_h, qfull_l);
    // 8) scores = q192 @ k192^T  batched (b,h), K=192, causal skip (fp32)
    gemm_bf3<true,false,0><<<dim3(S_/128, S_/128, B_ * NH_), thr, SMEM_GEMM_>>>(
        qfull_h, qfull_l, QDIM_, (long long)S_ * QDIM_, QKH_,
        k192_h,  k192_l,  QDIM_, (long long)S_ * QDIM_, QKH_,
        scores, nullptr, nullptr, S_, (long long)NH_ * S_ * S_, (long long)S_ * S_,
        S_, S_, QKH_, NH_, nullptr);
    // 9) v_proj (transposed): vT[h][d][r] = wkvb_v[h] @ kv_norm^T  (fp16 pairs out)
    gemm_bf3<false,false,3><<<dim3(M_/128, 1, NH_), thr, SMEM_GEMM_>>>(
        wkvb_h + (long long)NOPE_ * KVL_, wkvb_l + (long long)NOPE_ * KVL_,
        KVL_, 0, (long long)(NOPE_ + VD_) * KVL_,
        kcat_h, kcat_l, KC_, 0, 0,
        nullptr, (bf16*)vT_h, (bf16*)vT_l, M_, 0, (long long)VD_ * M_,
        VD_, M_, KVL_, NH_, nullptr);
    // 10) softmax -> fp16 probs
    softmax_kernel<<<dim3(S_, B_ * NH_), thr>>>(scores, mask, probs);
    // 11) oheads(fp16 single) = probs @ vT^T  batched (b,h), causal K bound
    gemm_f16x2<true,false,4><<<dim3(1, S_/128, B_ * NH_), thr, SMEM_GEMMF_>>>(
        probs, S_, (long long)NH_ * S_ * S_, (long long)S_ * S_,
        vT_h, vT_l, M_, 2048, (long long)VD_ * M_,
        nullptr, (bf16*)oheads_f, nullptr, H_, (long long)S_ * H_, VD_,
        S_, VD_, S_, NH_, nullptr);
    // 12) out = oheads @ wo^T + b  (fp16 two-term, fp32 out)
    gemm_f16x2<false,true,0><<<dim3(H_/128, M_/128, 1), thr, SMEM_GEMMF_>>>(
        oheads_f, H_, 0, 0, wo_fh, wo_fl, H_, 0, 0,
        out, nullptr, nullptr, H_, 0, 0, M_, H_, H_, 1, wo_b);
}

// round 16
// speedup vs baseline: 9.6428x; 1.1057x over previous
#include <cuda_runtime.h>
#include <cuda_bf16.h>
#include <cuda_fp16.h>
#include <math.h>
#include <stdint.h>

// ---------------- problem constants ----------------
constexpr int B_    = 2;
constexpr int S_    = 2048;
constexpr int H_    = 2048;
constexpr int NH_   = 16;
constexpr int QL_   = 1536;
constexpr int KVL_  = 512;
constexpr int NOPE_ = 128;
constexpr int ROPE_ = 64;
constexpr int VD_   = 128;
constexpr int QKH_  = 192;
constexpr int M_    = B_ * S_;      // 4096
constexpr int QDIM_ = NH_ * QKH_;   // 3072
constexpr int KC_   = KVL_ + ROPE_; // 576
constexpr float EPSF = 1e-6f;
constexpr float MINV = -1e15f;

typedef __nv_bfloat16 bf16;
typedef __half f16;

// ---------------- fp32 scratch ----------------
__device__ float g_qa    [M_ * QL_];
__device__ float g_qfull [M_ * QDIM_];
__device__ float g_kvfull[M_ * KC_];
__device__ float g_rope  [S_ * ROPE_];

// ---------------- bf16 hi/lo scratch ----------------
__device__ bf16 g_wkvb_h[NH_ * (NOPE_ + VD_) * KVL_], g_wkvb_l[NH_ * (NOPE_ + VD_) * KVL_];
__device__ bf16 g_kcat_h[M_ * KC_],        g_kcat_l[M_ * KC_];
// fp16 scratch
__device__ f16 g_x_f[M_ * H_];                                        // x single
__device__ f16 g_wqa_fh[QL_ * H_],         g_wqa_fl[QL_ * H_];
__device__ f16 g_wkva_fh[KC_ * H_],        g_wkva_fl[KC_ * H_];
__device__ f16 g_wqb_fh[QDIM_ * QL_],      g_wqb_fl[QDIM_ * QL_];
__device__ f16 g_wo_fh[H_ * H_],           g_wo_fl[H_ * H_];
__device__ f16 g_qa_f[M_ * QL_];                                      // rmsnorm out (single)
__device__ f16 g_qfull_f[M_ * QDIM_];                                 // q192 (single)
__device__ f16 g_k192_fh[M_ * QDIM_],      g_k192_fl[M_ * QDIM_];     // [r][h*192+d]
__device__ f16 g_scores_f[(size_t)B_ * NH_ * S_ * S_];
__device__ f16 g_oheads_f[M_ * H_];                                   // attn out (single)
__device__ f16 g_probs[(size_t)B_ * NH_ * S_ * S_];
__device__ f16 g_vT_h[NH_ * VD_ * M_],     g_vT_l[NH_ * VD_ * M_];    // [h][d][b*S+t]

// ---------------- PTX helpers ----------------
__device__ __forceinline__ void mma_bf16(float* d, const uint32_t* a, uint32_t b0, uint32_t b1) {
    asm volatile(
        "mma.sync.aligned.m16n8k16.row.col.f32.bf16.bf16.f32 "
        "{%0,%1,%2,%3}, {%4,%5,%6,%7}, {%8,%9}, {%0,%1,%2,%3};"
        : "+f"(d[0]), "+f"(d[1]), "+f"(d[2]), "+f"(d[3])
        : "r"(a[0]), "r"(a[1]), "r"(a[2]), "r"(a[3]), "r"(b0), "r"(b1));
}
__device__ __forceinline__ void mma_f16(float* d, const uint32_t* a, uint32_t b0, uint32_t b1) {
    asm volatile(
        "mma.sync.aligned.m16n8k16.row.col.f32.f16.f16.f32 "
        "{%0,%1,%2,%3}, {%4,%5,%6,%7}, {%8,%9}, {%0,%1,%2,%3};"
        : "+f"(d[0]), "+f"(d[1]), "+f"(d[2]), "+f"(d[3])
        : "r"(a[0]), "r"(a[1]), "r"(a[2]), "r"(a[3]), "r"(b0), "r"(b1));
}
__device__ __forceinline__ void ldsm4(uint32_t* r, uint32_t addr) {
    asm volatile("ldmatrix.sync.aligned.m8n8.x4.shared.b16 {%0,%1,%2,%3}, [%4];"
                 : "=r"(r[0]), "=r"(r[1]), "=r"(r[2]), "=r"(r[3]) : "r"(addr));
}
__device__ __forceinline__ void cp16(uint32_t s, const void* g, int sz) {
    asm volatile("cp.async.cg.shared.global [%0], [%1], 16, %2;"
                 :: "r"(s), "l"(g), "r"(sz) : "memory");
}
__device__ __forceinline__ void cpcommit() { asm volatile("cp.async.commit_group;" ::: "memory"); }
__device__ __forceinline__ void cpwait0()  { asm volatile("cp.async.wait_group 0;" ::: "memory"); }
__device__ __forceinline__ void cpwait1()  { asm volatile("cp.async.wait_group 1;" ::: "memory"); }
__device__ __forceinline__ void cpwait2()  { asm volatile("cp.async.wait_group 2;" ::: "memory"); }

__device__ __forceinline__ uint32_t pack_bf16(float a, float b) {
    union { bf16 v[2]; uint32_t u; } p;
    p.v[0] = __float2bfloat16(a);
    p.v[1] = __float2bfloat16(b);
    return p.u;
}
__device__ __forceinline__ uint32_t pack_f16(float a, float b) {
    union { f16 v[2]; uint32_t u; } p;
    p.v[0] = __float2half(a);
    p.v[1] = __float2half(b);
    return p.u;
}

// ================= smem geometry =================
constexpr int PADW_ = 12;
constexpr int TILE_W_ = 128 * PADW_;
constexpr int STG_W_ = 4 * TILE_W_;
constexpr int SMEM_GEMM_ = 3 * STG_W_ * 4;   // 73728 bytes
constexpr int STGF_W_ = 3 * TILE_W_;
constexpr int SMEM_GEMMF_ = 3 * STGF_W_ * 4; // 55296 bytes

// ================= bf16x3 tensor-core GEMM =================
// C[M,N] = A[M,K] @ B[N,K]^T, A/B bf16 hi/lo pairs. OUT: 3 = fp16 hi/lo.
template<int OUT>
__global__ __launch_bounds__(256, 2)
void gemm_bf3(const bf16* __restrict__ Ah, const bf16* __restrict__ Al,
              int lda, long long sAo, long long sAi,
              const bf16* __restrict__ Bh, const bf16* __restrict__ Bl,
              int ldb, long long sBo, long long sBi,
              f16* __restrict__ Fh, f16* __restrict__ Fl,
              int ldc, long long sCo, long long sCi,
              int M, int N, int K, int inner)
{
    const int m0 = blockIdx.y * 128;
    const int n0 = blockIdx.x * 128;

    const int z = blockIdx.z;
    const int zo = z / inner, zi = z - zo * inner;
    const long long aoff = zo * sAo + zi * sAi;
    const long long boff = zo * sBo + zi * sBi;
    Ah += aoff; Al += aoff;
    Bh += boff; Bl += boff;
    const long long coff = zo * sCo + zi * sCi;

    extern __shared__ uint32_t sm[];
    const uint32_t smw = (uint32_t)__cvta_generic_to_shared(sm);

    const int tid = threadIdx.x;
    const int wid = tid >> 5, lid = tid & 31;
    const int wm = (wid >> 2) * 64;
    const int wn = (wid & 3) * 32;
    const int gr = lid >> 2;
    const int gc = lid & 3;

    const int lr8 = lid & 7;
    const int mat = lid >> 3;
    const int a_row = (mat & 1) * 8 + lr8;
    const int a_kof = (mat >> 1) * 4;
    const int b_row = (mat >> 1) * 8 + lr8;
    const int b_kof = (mat & 1) * 4;

    const int nkt = K >> 4;

    float acc[4][4][4];
#pragma unroll
    for (int i = 0; i < 4; i++)
#pragma unroll
        for (int j = 0; j < 4; j++)
#pragma unroll
            for (int q = 0; q < 4; q++) acc[i][j][q] = 0.f;

    const int lrow = tid >> 1;
    const int lseg = tid & 1;

    auto issue = [&](int kt) {
        const int s = kt % 3;
        uint32_t* st = sm + s * STG_W_;
        const int k0 = kt << 4;
        const uint32_t dw = (uint32_t)__cvta_generic_to_shared(st + lrow * PADW_ + lseg * 4);
        const int ar = m0 + lrow, br = n0 + lrow;
        const int asz = ar < M ? 16 : 0, bsz = br < N ? 16 : 0;
        const long long ai = (long long)ar * lda + k0 + lseg * 8;
        const long long bi = (long long)br * ldb + k0 + lseg * 8;
        cp16(dw,                   Ah + ai, asz);
        cp16(dw + TILE_W_ * 4,     Al + ai, asz);
        cp16(dw + 2 * TILE_W_ * 4, Bh + bi, bsz);
        cp16(dw + 3 * TILE_W_ * 4, Bl + bi, bsz);
        cpcommit();
    };

    const int pre = nkt < 2 ? nkt : 2;
    for (int i = 0; i < pre; i++) issue(i);

    for (int kt = 0; kt < nkt; kt++) {
        if (kt + 2 < nkt) { issue(kt + 2); cpwait2(); }
        else if (kt + 1 < nkt) cpwait1();
        else cpwait0();
        __syncthreads();

        const int s = kt % 3;
        const uint32_t stb = smw + s * STG_W_ * 4;

        uint32_t afh[4][4], afl[4][4];
#pragma unroll
        for (int i = 0; i < 4; i++) {
            const uint32_t aaddr = stb + (uint32_t)(((wm + i * 16 + a_row) * PADW_ + a_kof) * 4);
            ldsm4(afh[i], aaddr);
            ldsm4(afl[i], aaddr + TILE_W_ * 4);
        }
#pragma unroll
        for (int p = 0; p < 2; p++) {
            const uint32_t baddr = stb + 2 * TILE_W_ * 4 +
                                   (uint32_t)(((wn + p * 16 + b_row) * PADW_ + b_kof) * 4);
            uint32_t bfh[4], bfl[4];
            ldsm4(bfh, baddr);
            ldsm4(bfl, baddr + TILE_W_ * 4);
#pragma unroll
            for (int j2 = 0; j2 < 2; j2++) {
                const int j = p * 2 + j2;
                const uint32_t bh0 = bfh[j2 * 2], bh1 = bfh[j2 * 2 + 1];
                const uint32_t bl0 = bfl[j2 * 2], bl1 = bfl[j2 * 2 + 1];
#pragma unroll
                for (int i = 0; i < 4; i++) {
                    mma_bf16(acc[i][j], afh[i], bh0, bh1);
                    mma_bf16(acc[i][j], afh[i], bl0, bl1);
                    mma_bf16(acc[i][j], afl[i], bh0, bh1);
                }
            }
        }
        __syncthreads();
    }

    // epilogue (fp16 hi/lo)
#pragma unroll
    for (int i = 0; i < 4; i++) {
        const int r0 = m0 + wm + i * 16 + gr;
        const int r1 = r0 + 8;
#pragma unroll
        for (int j = 0; j < 4; j++) {
            const int cc = n0 + wn + j * 8 + gc * 2;
            if (cc >= N) continue;
            float v00 = acc[i][j][0], v01 = acc[i][j][1];
            float v10 = acc[i][j][2], v11 = acc[i][j][3];
            if (r0 < M) {
                const long long o = coff + (long long)r0 * ldc + cc;
                float h0 = __half2float(__float2half(v00));
                float h1 = __half2float(__float2half(v01));
                *(uint32_t*)(Fh + o) = pack_f16(v00, v01);
                *(uint32_t*)(Fl + o) = pack_f16(v00 - h0, v01 - h1);
            }
            if (r1 < M) {
                const long long o = coff + (long long)r1 * ldc + cc;
                float h0 = __half2float(__float2half(v10));
                float h1 = __half2float(__float2half(v11));
                *(uint32_t*)(Fh + o) = pack_f16(v10, v11);
                *(uint32_t*)(Fl + o) = pack_f16(v10 - h0, v11 - h1);
            }
        }
    }
}

// ================= fp16 two-term GEMM =================
// A single fp16, B fp16 hi/lo pair. CSKIP: skip tiles above diagonal.
// CK: Kend = m0+128.
// OUT: 0 = fp32 (+bias), 4 = fp16 single, 5 = fp32 + fp16 single (+bias).
template<bool CSKIP, bool CK, bool BIAS, int OUT>
__global__ __launch_bounds__(256, 2)
void gemm_f16x2(const f16* __restrict__ A, int lda, long long sAo, long long sAi,
                const f16* __restrict__ Bh, const f16* __restrict__ Bl,
                int ldb, long long sBo, long long sBi,
                float* __restrict__ C, f16* __restrict__ Fh,
                int ldc, long long sCo, long long sCi,
                int M, int N, int K, int inner,
                const float* __restrict__ bias)
{
    const int m0 = blockIdx.y * 128;
    const int n0 = blockIdx.x * 128;
    if (CSKIP && n0 >= m0 + 128) return;

    const int z = blockIdx.z;
    const int zo = z / inner, zi = z - zo * inner;
    A  += zo * sAo + zi * sAi;
    const long long boff = zo * sBo + zi * sBi;
    Bh += boff; Bl += boff;
    const long long coff = zo * sCo + zi * sCi;

    extern __shared__ uint32_t sm[];
    const uint32_t smw = (uint32_t)__cvta_generic_to_shared(sm);

    const int tid = threadIdx.x;
    const int wid = tid >> 5, lid = tid & 31;
    const int wm = (wid >> 2) * 64;
    const int wn = (wid & 3) * 32;
    const int gr = lid >> 2;
    const int gc = lid & 3;

    const int lr8 = lid & 7;
    const int mat = lid >> 3;
    const int a_row = (mat & 1) * 8 + lr8;
    const int a_kof = (mat >> 1) * 4;
    const int b_row = (mat >> 1) * 8 + lr8;
    const int b_kof = (mat & 1) * 4;

    int Kend = K;
    if (CK) { int ke = m0 + 128; Kend = ke < K ? ke : K; }
    const int nkt = Kend >> 4;

    float acc[4][4][4];
#pragma unroll
    for (int i = 0; i < 4; i++)
#pragma unroll
        for (int j = 0; j < 4; j++)
#pragma unroll
            for (int q = 0; q < 4; q++) acc[i][j][q] = 0.f;

    const int lrow = tid >> 1;
    const int lseg = tid & 1;

    auto issue = [&](int kt) {
        const int s = kt % 3;
        uint32_t* st = sm + s * STGF_W_;
        const int k0 = kt << 4;
        const uint32_t dw = (uint32_t)__cvta_generic_to_shared(st + lrow * PADW_ + lseg * 4);
        const int ar = m0 + lrow, br = n0 + lrow;
        const int asz = ar < M ? 16 : 0, bsz = br < N ? 16 : 0;
        const long long ai = (long long)ar * lda + k0 + lseg * 8;
        const long long bi = (long long)br * ldb + k0 + lseg * 8;
        cp16(dw,                   A + ai,  asz);
        cp16(dw + TILE_W_ * 4,     Bh + bi, bsz);
        cp16(dw + 2 * TILE_W_ * 4, Bl + bi, bsz);
        cpcommit();
    };

    const int pre = nkt < 2 ? nkt : 2;
    for (int i = 0; i < pre; i++) issue(i);

    for (int kt = 0; kt < nkt; kt++) {
        if (kt + 2 < nkt) { issue(kt + 2); cpwait2(); }
        else if (kt + 1 < nkt) cpwait1();
        else cpwait0();
        __syncthreads();

        const int s = kt % 3;
        const uint32_t stb = smw + s * STGF_W_ * 4;

        uint32_t af[4][4];
#pragma unroll
        for (int i = 0; i < 4; i++) {
            const uint32_t aaddr = stb + (uint32_t)(((wm + i * 16 + a_row) * PADW_ + a_kof) * 4);
            ldsm4(af[i], aaddr);
        }
#pragma unroll
        for (int p = 0; p < 2; p++) {
            const uint32_t baddr = stb + TILE_W_ * 4 +
                                   (uint32_t)(((wn + p * 16 + b_row) * PADW_ + b_kof) * 4);
            uint32_t bfh[4], bfl[4];
            ldsm4(bfh, baddr);
            ldsm4(bfl, baddr + TILE_W_ * 4);
#pragma unroll
            for (int j2 = 0; j2 < 2; j2++) {
                const int j = p * 2 + j2;
                const uint32_t bh0 = bfh[j2 * 2], bh1 = bfh[j2 * 2 + 1];
                const uint32_t bl0 = bfl[j2 * 2], bl1 = bfl[j2 * 2 + 1];
#pragma unroll
                for (int i = 0; i < 4; i++) {
                    mma_f16(acc[i][j], af[i], bh0, bh1);
                    mma_f16(acc[i][j], af[i], bl0, bl1);
                }
            }
        }
        __syncthreads();
    }

#pragma unroll
    for (int i = 0; i < 4; i++) {
        const int r0 = m0 + wm + i * 16 + gr;
        const int r1 = r0 + 8;
#pragma unroll
        for (int j = 0; j < 4; j++) {
            const int cc = n0 + wn + j * 8 + gc * 2;
            if (cc >= N) continue;
            float b0 = 0.f, b1 = 0.f;
            if (BIAS) { b0 = bias[cc]; b1 = bias[cc + 1]; }
            float v00 = acc[i][j][0] + b0, v01 = acc[i][j][1] + b1;
            float v10 = acc[i][j][2] + b0, v11 = acc[i][j][3] + b1;
            if (r0 < M) {
                const long long o = coff + (long long)r0 * ldc + cc;
                if (OUT == 0 || OUT == 5) *(float2*)(C + o) = make_float2(v00, v01);
                if (OUT == 4 || OUT == 5) *(uint32_t*)(Fh + o) = pack_f16(v00, v01);
            }
            if (r1 < M) {
                const long long o = coff + (long long)r1 * ldc + cc;
                if (OUT == 0 || OUT == 5) *(float2*)(C + o) = make_float2(v10, v11);
                if (OUT == 4 || OUT == 5) *(uint32_t*)(Fh + o) = pack_f16(v10, v11);
            }
        }
    }
}

// ---------------- conversion kernels ----------------
__global__ __launch_bounds__(256)
void cvt_bf16_kernel(const float* __restrict__ src, bf16* __restrict__ hi, bf16* __restrict__ lo,
                     long long n4)
{
    long long i = (long long)blockIdx.x * blockDim.x + threadIdx.x;
    if (i >= n4) return;
    float4 v = ((const float4*)src)[i];
    union { bf16 b[4]; uint2 u; } ph, pl;
    float f[4] = { v.x, v.y, v.z, v.w };
#pragma unroll
    for (int q = 0; q < 4; q++) {
        bf16 h = __float2bfloat16(f[q]);
        ph.b[q] = h;
        pl.b[q] = __float2bfloat16(f[q] - __bfloat162float(h));
    }
    ((uint2*)hi)[i] = ph.u;
    ((uint2*)lo)[i] = pl.u;
}

__global__ __launch_bounds__(256)
void cvt_f16_kernel(const float* __restrict__ src, f16* __restrict__ hi, f16* __restrict__ lo,
                    long long n4)
{
    long long i = (long long)blockIdx.x * blockDim.x + threadIdx.x;
    if (i >= n4) return;
    float4 v = ((const float4*)src)[i];
    union { f16 b[4]; uint2 u; } ph, pl;
    float f[4] = { v.x, v.y, v.z, v.w };
#pragma unroll
    for (int q = 0; q < 4; q++) {
        f16 h = __float2half(f[q]);
        ph.b[q] = h;
        pl.b[q] = __float2half(f[q] - __half2float(h));
    }
    ((uint2*)hi)[i] = ph.u;
    ((uint2*)lo)[i] = pl.u;
}

__global__ __launch_bounds__(256)
void cvt_f16s_kernel(const float* __restrict__ src, f16* __restrict__ dst, long long n4)
{
    long long i = (long long)blockIdx.x * blockDim.x + threadIdx.x;
    if (i >= n4) return;
    float4 v = ((const float4*)src)[i];
    union { f16 b[4]; uint2 u; } p;
    p.b[0] = __float2half(v.x);
    p.b[1] = __float2half(v.y);
    p.b[2] = __float2half(v.z);
    p.b[3] = __float2half(v.w);
    ((uint2*)dst)[i] = p.u;
}

// ================= pointwise / softmax =================
__global__ __launch_bounds__(256)
void rmsnorm_f16_kernel(const float* __restrict__ x, const float* __restrict__ w, int cols,
                        f16* __restrict__ outp)
{
    __shared__ float sh[256];
    const float* p = x + (long long)blockIdx.x * cols;
    f16* o = outp + (long long)blockIdx.x * cols;
    float s = 0.f;
    for (int c = threadIdx.x; c < cols; c += 256) { float v = p[c]; s += v * v; }
    sh[threadIdx.x] = s; __syncthreads();
    for (int off = 128; off > 0; off >>= 1) {
        if (threadIdx.x < off) sh[threadIdx.x] += sh[threadIdx.x + off];
        __syncthreads();
    }
    float rs = rsqrtf(sh[0] / (float)cols + EPSF);
    for (int c = threadIdx.x; c < cols; c += 256)
        o[c] = __float2half(w[c] * p[c] * rs);
}

__global__ void rope_table_kernel(float* __restrict__ rope)
{
    int idx = blockIdx.x * blockDim.x + threadIdx.x;
    if (idx >= S_ * 32) return;
    int pos = idx >> 5, j = idx & 31;
    double f = pow(10000.0, -(double)j / 32.0);
    double ang = (double)pos * f;
    rope[pos * 64 + j]      = (float)cos(ang);
    rope[pos * 64 + 32 + j] = (float)sin(ang);
}

// kv branch: rmsnorm -> kcat bf16 hi/lo; roped k_pe replicated (fp16 hi/lo) into k192
__global__ __launch_bounds__(256)
void kvproc_kernel(const float* __restrict__ kvfull, const float* __restrict__ w,
                   const float* __restrict__ rope,
                   bf16* __restrict__ kh, bf16* __restrict__ kl,
                   f16* __restrict__ k192h, f16* __restrict__ k192l)
{
    __shared__ float sh[256];
    const int row = blockIdx.x;
    const float* in = kvfull + (long long)row * KC_;
    bf16* oh = kh + (long long)row * KC_;
    bf16* ol = kl + (long long)row * KC_;
    float s = 0.f;
    for (int c = threadIdx.x; c < KVL_; c += 256) { float v = in[c]; s += v * v; }
    sh[threadIdx.x] = s; __syncthreads();
    for (int o = 128; o > 0; o >>= 1) {
        if (threadIdx.x < o) sh[threadIdx.x] += sh[threadIdx.x + o];
        __syncthreads();
    }
    float rs = rsqrtf(sh[0] / (float)KVL_ + EPSF);
    for (int c = threadIdx.x; c < KVL_; c += 256) {
        float v = w[c] * in[c] * rs;
        bf16 h = __float2bfloat16(v);
        oh[c] = h;
        ol[c] = __float2bfloat16(v - __bfloat162float(h));
    }
    if (threadIdx.x < 32) {
        int j = threadIdx.x;
        int pos = row & (S_ - 1);
        float cs = rope[pos * 64 + j], sn = rope[pos * 64 + 32 + j];
        float x1 = in[KVL_ + j], x2 = in[KVL_ + 32 + j];
        float v1 = x1 * cs - x2 * sn;
        float v2 = x2 * cs + x1 * sn;
        f16 h1 = __float2half(v1), h2 = __float2half(v2);
        f16 l1 = __float2half(v1 - __half2float(h1));
        f16 l2 = __float2half(v2 - __half2float(h2));
        const long long rb = (long long)row * QDIM_;
#pragma unroll
        for (int h = 0; h < NH_; h++) {
            const long long o = rb + h * QKH_ + NOPE_;
            k192h[o + j] = h1;       k192l[o + j] = l1;
            k192h[o + 32 + j] = h2;  k192l[o + 32 + j] = l2;
        }
    }
}

// q_pe RoPE: write fp16 single into qfull_f pe columns
__global__ void qpe_rope_kernel(const float* __restrict__ qfull,
                                const float* __restrict__ rope,
                                f16* __restrict__ qf)
{
    int idx = blockIdx.x * blockDim.x + threadIdx.x;
    if (idx >= M_ * NH_ * 32) return;
    int j   = idx & 31;
    int h   = (idx >> 5) & (NH_ - 1);
    int row = idx >> 9;
    int pos = row & (S_ - 1);
    float cs = rope[pos * 64 + j], sn = rope[pos * 64 + 32 + j];
    const long long o = (long long)row * QDIM_ + h * QKH_ + NOPE_;
    const float* q = qfull + o;
    float x1 = q[j], x2 = q[32 + j];
    qf[o + j]      = __float2half(x1 * cs - x2 * sn);
    qf[o + 32 + j] = __float2half(x2 * cs + x1 * sn);
}

// softmax: fp16 scores -> fp16 probs (zero-padded to 128 boundary)
__global__ __launch_bounds__(256)
void softmax_kernel(const f16* __restrict__ scores, const int* __restrict__ mask,
                    f16* __restrict__ probs)
{
    __shared__ float sh[256];
    const int s = blockIdx.x;
    const int z = blockIdx.y;
    const int b = z >> 4;
    const long long ro = ((long long)z * S_ + s) * S_;
    const f16* row = scores + ro;
    f16* op = probs + ro;
    const int* mrow = mask + b * S_;
    const int n = s + 1;
    const int tid = threadIdx.x;
    const float scale = 0.07216878364870323f;   // 1/sqrt(192)

    float vals[8];
    float mx = -3.0e38f;
#pragma unroll
    for (int it = 0; it < 8; it++) {
        int t = tid + it * 256;
        float v = -3.0e38f;
        if (t < n) {
            v = __half2float(row[t]) * scale;
            if (mrow[t] == 0) v += MINV;
        }
        vals[it] = v;
        mx = fmaxf(mx, v);
    }
    sh[tid] = mx; __syncthreads();
    for (int o = 128; o > 0; o >>= 1) {
        if (tid < o) sh[tid] = fmaxf(sh[tid], sh[tid + o]);
        __syncthreads();
    }
    mx = sh[0]; __syncthreads();

    float sum = 0.f;
#pragma unroll
    for (int it = 0; it < 8; it++) {
        int t = tid + it * 256;
        if (t < n) { float e = expf(vals[it] - mx); vals[it] = e; sum += e; }
    }
    sh[tid] = sum; __syncthreads();
    for (int o = 128; o > 0; o >>= 1) {
        if (tid < o) sh[tid] += sh[tid + o];
        __syncthreads();
    }
    float inv = 1.f / sh[0];
#pragma unroll
    for (int it = 0; it < 8; it++) {
        int t = tid + it * 256;
        if (t < n) op[t] = __float2half(vals[it] * inv);
    }
    const f16 zero = __float2half(0.f);
    int pad = ((s >> 7) + 1) << 7;
    for (int t = n + tid; t < pad; t += 256) op[t] = zero;
}

// ================= host side =================
static void cvtb(const float* src, bf16* hi, bf16* lo, long long n)
{
    long long n4 = n / 4;
    cvt_bf16_kernel<<<(unsigned)((n4 + 255) / 256), 256>>>(src, hi, lo, n4);
}
static void cvtf(const float* src, f16* hi, f16* lo, long long n)
{
    long long n4 = n / 4;
    cvt_f16_kernel<<<(unsigned)((n4 + 255) / 256), 256>>>(src, hi, lo, n4);
}
static void cvtfs(const float* src, f16* dst, long long n)
{
    long long n4 = n / 4;
    cvt_f16s_kernel<<<(unsigned)((n4 + 255) / 256), 256>>>(src, dst, n4);
}

extern "C" void kernel_launch(void* const* d_in, const int* in_sizes, int n_in,
                              void* d_out, int out_size)
{
    (void)in_sizes; (void)n_in; (void)out_size;
    const float* x        = (const float*)d_in[0];
    const int*   mask     = (const int*)  d_in[1];
    const float* wq_a_w   = (const float*)d_in[2];
    const float* wq_a_b   = (const float*)d_in[3];
    const float* q_norm_w = (const float*)d_in[4];
    const float* wq_b_w   = (const float*)d_in[5];
    const float* wq_b_b   = (const float*)d_in[6];
    const float* wkv_a_w  = (const float*)d_in[7];
    const float* wkv_a_b  = (const float*)d_in[8];
    const float* kv_norm_w= (const float*)d_in[9];
    const float* wkv_b_w  = (const float*)d_in[10];
    const float* wo_w     = (const float*)d_in[11];
    const float* wo_b     = (const float*)d_in[12];
    float* out = (float*)d_out;

    float *qa, *qfull, *kvfull, *rope;
    cudaGetSymbolAddress((void**)&qa,     g_qa);
    cudaGetSymbolAddress((void**)&qfull,  g_qfull);
    cudaGetSymbolAddress((void**)&kvfull, g_kvfull);
    cudaGetSymbolAddress((void**)&rope,   g_rope);

    bf16 *wkvb_h,*wkvb_l,*kcat_h,*kcat_l;
    f16 *x_f,*wqa_fh,*wqa_fl,*wkva_fh,*wkva_fl,*wqb_fh,*wqb_fl,*wo_fh,*wo_fl;
    f16 *qa_f,*qfull_f,*k192_fh,*k192_fl,*scores_f,*oheads_f,*probs,*vT_h,*vT_l;
    cudaGetSymbolAddress((void**)&wkvb_h, g_wkvb_h);   cudaGetSymbolAddress((void**)&wkvb_l, g_wkvb_l);
    cudaGetSymbolAddress((void**)&kcat_h, g_kcat_h);   cudaGetSymbolAddress((void**)&kcat_l, g_kcat_l);
    cudaGetSymbolAddress((void**)&x_f, g_x_f);
    cudaGetSymbolAddress((void**)&wqa_fh, g_wqa_fh);   cudaGetSymbolAddress((void**)&wqa_fl, g_wqa_fl);
    cudaGetSymbolAddress((void**)&wkva_fh, g_wkva_fh); cudaGetSymbolAddress((void**)&wkva_fl, g_wkva_fl);
    cudaGetSymbolAddress((void**)&wqb_fh, g_wqb_fh);   cudaGetSymbolAddress((void**)&wqb_fl, g_wqb_fl);
    cudaGetSymbolAddress((void**)&wo_fh, g_wo_fh);     cudaGetSymbolAddress((void**)&wo_fl, g_wo_fl);
    cudaGetSymbolAddress((void**)&qa_f, g_qa_f);
    cudaGetSymbolAddress((void**)&qfull_f, g_qfull_f);
    cudaGetSymbolAddress((void**)&k192_fh, g_k192_fh); cudaGetSymbolAddress((void**)&k192_fl, g_k192_fl);
    cudaGetSymbolAddress((void**)&scores_f, g_scores_f);
    cudaGetSymbolAddress((void**)&oheads_f, g_oheads_f);
    cudaGetSymbolAddress((void**)&probs, g_probs);
    cudaGetSymbolAddress((void**)&vT_h, g_vT_h);       cudaGetSymbolAddress((void**)&vT_l, g_vT_l);

    cudaFuncSetAttribute(gemm_bf3<3>, cudaFuncAttributeMaxDynamicSharedMemorySize, SMEM_GEMM_);
    cudaFuncSetAttribute((const void*)gemm_f16x2<false,false,true ,0>, cudaFuncAttributeMaxDynamicSharedMemorySize, SMEM_GEMMF_);
    cudaFuncSetAttribute((const void*)gemm_f16x2<false,false,true ,5>, cudaFuncAttributeMaxDynamicSharedMemorySize, SMEM_GEMMF_);
    cudaFuncSetAttribute((const void*)gemm_f16x2<true ,false,false,4>, cudaFuncAttributeMaxDynamicSharedMemorySize, SMEM_GEMMF_);
    cudaFuncSetAttribute((const void*)gemm_f16x2<false,true ,false,4>, cudaFuncAttributeMaxDynamicSharedMemorySize, SMEM_GEMMF_);

    dim3 thr(256);

    rope_table_kernel<<<(S_ * 32 + 255) / 256, thr>>>(rope);
    cvtfs(x, x_f, (long long)M_ * H_);
    cvtf(wq_a_w,  wqa_fh,  wqa_fl,  (long long)QL_ * H_);
    cvtf(wkv_a_w, wkva_fh, wkva_fl, (long long)KC_ * H_);
    cvtb(wkv_b_w, wkvb_h,  wkvb_l,  (long long)NH_ * (NOPE_ + VD_) * KVL_);

    // 1) qa = x @ wq_a^T + b  (fp16 x2, fp32 out)
    gemm_f16x2<false,false,true,0><<<dim3(QL_/128, M_/128, 1), thr, SMEM_GEMMF_>>>(
        x_f, H_, 0, 0, wqa_fh, wqa_fl, H_, 0, 0,
        qa, nullptr, QL_, 0, 0, M_, QL_, H_, 1, wq_a_b);

    cvtf(wq_b_w, wqb_fh, wqb_fl, (long long)QDIM_ * QL_);
    cvtf(wo_w,   wo_fh,  wo_fl,  (long long)H_ * H_);

    // 2) rmsnorm -> qa fp16 single
    rmsnorm_f16_kernel<<<M_, thr>>>(qa, q_norm_w, QL_, qa_f);
    // 3) qfull = qa @ wq_b^T + b  (fp16 x2; out fp32 + fp16 single)
    gemm_f16x2<false,false,true,5><<<dim3(QDIM_/128, M_/128, 1), thr, SMEM_GEMMF_>>>(
        qa_f, QL_, 0, 0, wqb_fh, wqb_fl, QL_, 0, 0,
        qfull, qfull_f, QDIM_, 0, 0, M_, QDIM_, QL_, 1, wq_b_b);
    // 4) kvfull = x @ wkv_a^T + b  (fp16 x2, fp32 out)
    gemm_f16x2<false,false,true,0><<<dim3((KC_ + 127)/128, M_/128, 1), thr, SMEM_GEMMF_>>>(
        x_f, H_, 0, 0, wkva_fh, wkva_fl, H_, 0, 0,
        kvfull, nullptr, KC_, 0, 0, M_, KC_, H_, 1, wkv_a_b);
    // 5) kcat bf16 hi/lo + roped k_pe (fp16 hi/lo) into k192
    kvproc_kernel<<<M_, thr>>>(kvfull, kv_norm_w, rope, kcat_h, kcat_l, k192_fh, k192_fl);
    // 6) k_proj: k192[:, h*192:+128] = kv_norm @ wkvb_k[h]^T  (bf16x3, fp16 hi/lo out)
    gemm_bf3<3><<<dim3(1, M_/128, NH_), thr, SMEM_GEMM_>>>(
        kcat_h, kcat_l, KC_, 0, 0,
        wkvb_h, wkvb_l, KVL_, 0, (long long)(NOPE_ + VD_) * KVL_,
        k192_fh, k192_fl, QDIM_, 0, QKH_,
        M_, NOPE_, KVL_, NH_);
    // 7) q_pe rope -> qfull_f pe columns (fp16 single)
    qpe_rope_kernel<<<(M_ * NH_ * 32 + 255) / 256, thr>>>(qfull, rope, qfull_f);
    // 8) scores(fp16) = q192 @ k192^T  batched (b,h), K=192, causal skip (fp16 x2)
    gemm_f16x2<true,false,false,4><<<dim3(S_/128, S_/128, B_ * NH_), thr, SMEM_GEMMF_>>>(
        qfull_f, QDIM_, (long long)S_ * QDIM_, QKH_,
        k192_fh, k192_fl, QDIM_, (long long)S_ * QDIM_, QKH_,
        nullptr, scores_f, S_, (long long)NH_ * S_ * S_, (long long)S_ * S_,
        S_, S_, QKH_, NH_, nullptr);
    // 9) v_proj (transposed): vT[h][d][r] = wkvb_v[h] @ kv_norm^T  (bf16x3, fp16 hi/lo out)
    gemm_bf3<3><<<dim3(M_/128, 1, NH_), thr, SMEM_GEMM_>>>(
        wkvb_h + (long long)NOPE_ * KVL_, wkvb_l + (long long)NOPE_ * KVL_,
        KVL_, 0, (long long)(NOPE_ + VD_) * KVL_,
        kcat_h, kcat_l, KC_, 0, 0,
        vT_h, vT_l, M_, 0, (long long)VD_ * M_,
        VD_, M_, KVL_, NH_);
    // 10) softmax (fp16 in) -> fp16 probs
    softmax_kernel<<<dim3(S_, B_ * NH_), thr>>>(scores_f, mask, probs);
    // 11) oheads(fp16 single) = probs @ vT^T  batched (b,h), causal K bound
    gemm_f16x2<false,true,false,4><<<dim3(1, S_/128, B_ * NH_), thr, SMEM_GEMMF_>>>(
        probs, S_, (long long)NH_ * S_ * S_, (long long)S_ * S_,
        vT_h, vT_l, M_, 2048, (long long)VD_ * M_,
        nullptr, oheads_f, H_, (long long)S_ * H_, VD_,
        S_, VD_, S_, NH_, nullptr);
    // 12) out = oheads @ wo^T + b  (fp16 x2, fp32 out)
    gemm_f16x2<false,false,true,0><<<dim3(H_/128, M_/128, 1), thr, SMEM_GEMMF_>>>(
        oheads_f, H_, 0, 0, wo_fh, wo_fl, H_, 0, 0,
        out, nullptr, H_, 0, 0, M_, H_, H_, 1, wo_b);
}